// round 9
// baseline (speedup 1.0000x reference)
#include <cuda_runtime.h>
#include <cuda_bf16.h>
#include <math.h>
#include <cstdint>

#define B_   4
#define N_   4096
#define M_   8192
#define C_   256
#define K_   8
#define FF_  1024
#define NQ_  (B_ * N_)
#define NM_  (B_ * M_)
#define NCELL_ (B_ * 125)
#define CAP_ 192
#define QCAP_ 128
#define MAXC_ (27 * CAP_)   /* 5184 */

// ================= scratch ======================================================
__device__ float          g_Xq   [NQ_ * C_];
__device__ __nv_bfloat16  g_Xq_b [NQ_ * C_];
__device__ __nv_bfloat16  g_Xkv_b[NM_ * C_];
__device__ __nv_bfloat16  g_QKVq [NQ_ * 3 * C_];
__device__ __nv_bfloat16  g_KVkv [NM_ * 2 * C_];
__device__ __nv_bfloat16  g_O_b  [NQ_ * C_];
__device__ __nv_bfloat16  g_T_b  [NQ_ * C_];
__device__ float          g_Y    [NQ_ * C_];
__device__ __nv_bfloat16  g_Y_b  [NQ_ * C_];
__device__ __nv_bfloat16  g_Hid_b[NQ_ * FF_];
__device__ int            g_nidx [NQ_ * K_];
__device__ int            g_cnt  [NCELL_];
__device__ int            g_qcnt [NCELL_];
__device__ int            g_qids [NCELL_ * QCAP_];
__device__ float4         g_pts  [NCELL_ * CAP_];
__device__ int            g_pidx [NCELL_ * CAP_];
__device__ __nv_bfloat16  g_WTqkv[3 * C_ * C_];
__device__ __nv_bfloat16  g_WTkv [2 * C_ * C_];
__device__ __nv_bfloat16  g_WTo  [C_ * C_];
__device__ __nv_bfloat16  g_WT1  [FF_ * C_];
__device__ __nv_bfloat16  g_WT2  [C_ * FF_];
__device__ float          g_bqkv [3 * C_];
__device__ float          g_bkv  [2 * C_];

__device__ __forceinline__ uint32_t smem_u32(const void* p) {
    uint32_t a;
    asm("{ .reg .u64 t; cvta.to.shared.u64 t, %1; cvt.u32.u64 %0, t; }" : "=r"(a) : "l"(p));
    return a;
}

// ================= fused weight prep + cell zeroing =============================
__global__ void prep_weights(const float* __restrict__ Wq, const float* __restrict__ Wk,
                             const float* __restrict__ Wv, const float* __restrict__ Wo,
                             const float* __restrict__ W1, const float* __restrict__ W2,
                             const float* __restrict__ bq, const float* __restrict__ bk,
                             const float* __restrict__ bv) {
    int idx = blockIdx.x * 256 + threadIdx.x;
    const int S = C_ * C_;
    const int E0 = 4 * S + 2 * C_ * FF_;
    if (idx < S) {
        int k = idx >> 8, n = idx & 255;
        g_WTqkv[(size_t)n * C_ + k] = __float2bfloat16(Wq[idx]);
    } else if (idx < 2 * S) {
        int j = idx - S; int k = j >> 8, n = j & 255;
        __nv_bfloat16 v = __float2bfloat16(Wk[j]);
        g_WTqkv[(size_t)(C_ + n) * C_ + k] = v;
        g_WTkv [(size_t)n * C_ + k] = v;
    } else if (idx < 3 * S) {
        int j = idx - 2 * S; int k = j >> 8, n = j & 255;
        __nv_bfloat16 v = __float2bfloat16(Wv[j]);
        g_WTqkv[(size_t)(2 * C_ + n) * C_ + k] = v;
        g_WTkv [(size_t)(C_ + n) * C_ + k] = v;
    } else if (idx < 4 * S) {
        int j = idx - 3 * S; int k = j >> 8, n = j & 255;
        g_WTo[(size_t)n * C_ + k] = __float2bfloat16(Wo[j]);
    } else if (idx < 4 * S + C_ * FF_) {
        int j = idx - 4 * S; int k = j >> 10, n = j & 1023;
        g_WT1[(size_t)n * C_ + k] = __float2bfloat16(W1[j]);
    } else if (idx < E0) {
        int j = idx - 4 * S - C_ * FF_; int k = j >> 8, n = j & 255;
        g_WT2[(size_t)n * FF_ + k] = __float2bfloat16(W2[j]);
    } else if (idx < E0 + 768) {
        int j = idx - E0;
        g_bqkv[j] = (j < 256) ? bq[j] : (j < 512 ? bk[j - 256] : bv[j - 512]);
    } else if (idx < E0 + 768 + 512) {
        int j = idx - E0 - 768;
        g_bkv[j] = (j < 256) ? bk[j] : bv[j - 256];
    } else if (idx < E0 + 768 + 512 + NCELL_) {
        g_cnt[idx - E0 - 768 - 512] = 0;
    } else if (idx < E0 + 768 + 512 + 2 * NCELL_) {
        g_qcnt[idx - E0 - 768 - 512 - NCELL_] = 0;
    }
}
#define PREP_ITEMS (4 * C_ * C_ + 2 * C_ * FF_ + 768 + 512 + 2 * NCELL_)

// ================= fused pos-encoding ===========================================
__global__ void posenc_kernel(const float* __restrict__ q_xyz,
                              const float* __restrict__ q_feat,
                              const float* __restrict__ kv_xyz,
                              const float* __restrict__ kv_feat,
                              const float* __restrict__ Wpos,
                              const float* __restrict__ bpos) {
    int row = blockIdx.x;
    int c   = threadIdx.x;
    const float* xyz; const float* feat;
    if (row < NQ_) { xyz = q_xyz + row * 3; feat = q_feat + (size_t)row * C_; }
    else { int r = row - NQ_; xyz = kv_xyz + r * 3; feat = kv_feat + (size_t)r * C_; }
    float x = xyz[0], y = xyz[1], z = xyz[2];
    float v = feat[c] + x * Wpos[c] + y * Wpos[C_ + c] + z * Wpos[2 * C_ + c] + bpos[c];
    if (row < NQ_) {
        g_Xq[(size_t)row * C_ + c] = v;
        g_Xq_b[(size_t)row * C_ + c] = __float2bfloat16(v);
    } else {
        g_Xkv_b[(size_t)(row - NQ_) * C_ + c] = __float2bfloat16(v);
    }
}

// ================= HMMA GEMM (R7 config: 128x128 tile, 64x32 warp, 3-stage) =====
// MODE 0: fp32 out.  MODE 1: relu+bf16 out.  MODE 2: bf16 out.
#define SSTR 40
#define STG_BYTES (128 * SSTR * 2)
#define GEMM_SMEM (3 * STG_BYTES * 2)

__device__ __forceinline__ void ldm_x4(uint32_t* r, uint32_t addr) {
    asm volatile("ldmatrix.sync.aligned.m8n8.x4.shared.b16 {%0,%1,%2,%3}, [%4];"
                 : "=r"(r[0]), "=r"(r[1]), "=r"(r[2]), "=r"(r[3]) : "r"(addr));
}
__device__ __forceinline__ void mma_bf16(float* d, const uint32_t* a, const uint32_t* b) {
    asm volatile(
        "mma.sync.aligned.m16n8k16.row.col.f32.bf16.bf16.f32 "
        "{%0,%1,%2,%3}, {%4,%5,%6,%7}, {%8,%9}, {%0,%1,%2,%3};"
        : "+f"(d[0]), "+f"(d[1]), "+f"(d[2]), "+f"(d[3])
        : "r"(a[0]), "r"(a[1]), "r"(a[2]), "r"(a[3]), "r"(b[0]), "r"(b[1]));
}
__device__ __forceinline__ void cp16(uint32_t saddr, const void* gaddr) {
    asm volatile("cp.async.cg.shared.global [%0], [%1], 16;" :: "r"(saddr), "l"(gaddr));
}

template <int MODE>
__global__ __launch_bounds__(256, 2)
void gemm_hmma(const __nv_bfloat16* __restrict__ A,
               const __nv_bfloat16* __restrict__ BT,
               const float* __restrict__ bias,
               void* __restrict__ Out, int K, int N) {
    extern __shared__ char dsm[];
    int tid  = threadIdx.x;
    int wid  = tid >> 5, lane = tid & 31;
    int row0 = blockIdx.y * 128;
    int col0 = blockIdx.x * 128;
    int wm   = (wid & 1) * 64;
    int wn   = (wid >> 1) * 32;

    uint32_t aA = smem_u32(dsm);
    uint32_t aB = aA + 3 * STG_BYTES;

    int r0i = tid >> 2, s0 = (tid & 3) * 8;
    int r1i = (tid + 256) >> 2, s1 = ((tid + 256) & 3) * 8;

    auto issue = [&](int st, int kc0) {
        uint32_t oA = aA + st * STG_BYTES, oB = aB + st * STG_BYTES;
        cp16(oA + (r0i * SSTR + s0) * 2, A  + (size_t)(row0 + r0i) * K + kc0 + s0);
        cp16(oA + (r1i * SSTR + s1) * 2, A  + (size_t)(row0 + r1i) * K + kc0 + s1);
        cp16(oB + (r0i * SSTR + s0) * 2, BT + (size_t)(col0 + r0i) * K + kc0 + s0);
        cp16(oB + (r1i * SSTR + s1) * 2, BT + (size_t)(col0 + r1i) * K + kc0 + s1);
        asm volatile("cp.async.commit_group;" ::: "memory");
    };

    float acc[4][4][4] = {};
    int nk = K >> 5;

    issue(0, 0);
    issue(1, 32);

    for (int i = 0; i < nk; i++) {
        if (i < nk - 1) asm volatile("cp.async.wait_group 1;" ::: "memory");
        else            asm volatile("cp.async.wait_group 0;" ::: "memory");
        __syncthreads();

        if (i + 2 < nk) issue((i + 2) % 3, (i + 2) << 5);

        uint32_t bA = aA + (i % 3) * STG_BYTES;
        uint32_t bB = aB + (i % 3) * STG_BYTES;
#pragma unroll
        for (int ks = 0; ks < 2; ks++) {
            uint32_t afr[4][4];
#pragma unroll
            for (int mt = 0; mt < 4; mt++) {
                uint32_t addr = bA + ((wm + mt * 16 + (lane & 15)) * SSTR
                                      + ks * 16 + ((lane >> 4) << 3)) * 2;
                ldm_x4(afr[mt], addr);
            }
            uint32_t bfr[2][4];
#pragma unroll
            for (int np = 0; np < 2; np++) {
                uint32_t row = wn + np * 16 + ((lane >> 4) << 3) + (lane & 7);
                uint32_t kc  = ks * 16 + ((lane >> 3) & 1) * 8;
                ldm_x4(bfr[np], bB + (row * SSTR + kc) * 2);
            }
#pragma unroll
            for (int mt = 0; mt < 4; mt++)
#pragma unroll
                for (int nt = 0; nt < 4; nt++)
                    mma_bf16(acc[mt][nt], afr[mt], &bfr[nt >> 1][(nt & 1) * 2]);
        }
    }

    int g  = lane >> 2;
    int t2 = (lane & 3) * 2;
#pragma unroll
    for (int mt = 0; mt < 4; mt++) {
#pragma unroll
        for (int nt = 0; nt < 4; nt++) {
            int row = row0 + wm + mt * 16 + g;
            int col = col0 + wn + nt * 8 + t2;
            float2 b2 = *(const float2*)&bias[col];
            float v0 = acc[mt][nt][0] + b2.x, v1 = acc[mt][nt][1] + b2.y;
            float v2 = acc[mt][nt][2] + b2.x, v3 = acc[mt][nt][3] + b2.y;
            if (MODE == 0) {
                float* op = (float*)Out;
                *(float2*)&op[(size_t)row * N + col]       = make_float2(v0, v1);
                *(float2*)&op[(size_t)(row + 8) * N + col] = make_float2(v2, v3);
            } else {
                if (MODE == 1) {
                    v0 = fmaxf(v0, 0.f); v1 = fmaxf(v1, 0.f);
                    v2 = fmaxf(v2, 0.f); v3 = fmaxf(v3, 0.f);
                }
                __nv_bfloat16* op = (__nv_bfloat16*)Out;
                *(__nv_bfloat162*)&op[(size_t)row * N + col]       = __floats2bfloat162_rn(v0, v1);
                *(__nv_bfloat162*)&op[(size_t)(row + 8) * N + col] = __floats2bfloat162_rn(v2, v3);
            }
        }
    }
}

// ================= binning: kv points AND queries ===============================
__device__ __forceinline__ int cell_of(float x, float y, float z) {
    int cx = min((int)(x * 5.f), 4);
    int cy = min((int)(y * 5.f), 4);
    int cz = min((int)(z * 5.f), 4);
    return (cx * 5 + cy) * 5 + cz;
}

__global__ void scatter_all(const float* __restrict__ kv_xyz,
                            const unsigned char* __restrict__ kv_pad,
                            const float* __restrict__ q_xyz) {
    int i = blockIdx.x * 256 + threadIdx.x;
    if (i < NM_) {
        if (kv_pad[i]) return;
        int b = i >> 13;
        float x = kv_xyz[i * 3], y = kv_xyz[i * 3 + 1], z = kv_xyz[i * 3 + 2];
        int cid = b * 125 + cell_of(x, y, z);
        int pos = atomicAdd(&g_cnt[cid], 1);
        if (pos < CAP_) {
            g_pts[cid * CAP_ + pos] = make_float4(x, y, z, x * x + y * y + z * z);
            g_pidx[cid * CAP_ + pos] = i & 8191;
        }
    } else {
        int qi = i - NM_;
        if (qi >= NQ_) return;
        int b = qi >> 12;
        float x = q_xyz[qi * 3], y = q_xyz[qi * 3 + 1], z = q_xyz[qi * 3 + 2];
        int cid = b * 125 + cell_of(x, y, z);
        int pos = atomicAdd(&g_qcnt[cid], 1);
        if (pos < QCAP_) g_qids[cid * QCAP_ + pos] = qi;
    }
}

// ================= cell-grouped kNN: 1 CTA per cell, candidates in SMEM =========
#define KNN_SMEM (MAXC_ * 20 + 256)

__global__ __launch_bounds__(256)
void knn_cell_kernel(const float* __restrict__ q_xyz, int* __restrict__ nidx) {
    const float INF = __int_as_float(0x7f800000);
    int cid = blockIdx.x;
    int nq = min(g_qcnt[cid], QCAP_);
    if (nq == 0) return;
    int b = cid / 125;
    int cc = cid % 125;
    int cx = cc / 25, cy = (cc / 5) % 5, cz = cc % 5;

    extern __shared__ char sm[];
    float4* spts = (float4*)sm;
    int*    sidx = (int*)(sm + MAXC_ * 16);
    __shared__ int s_cells[27], s_offs[28];
    __shared__ int s_nc;

    int tid = threadIdx.x, warp = tid >> 5, lane = tid & 31;

    if (tid == 0) {
        int nc = 0, tot = 0;
        for (int dx = -1; dx <= 1; dx++) {
            int x = cx + dx; if (x < 0 || x > 4) continue;
            for (int dy = -1; dy <= 1; dy++) {
                int y = cy + dy; if (y < 0 || y > 4) continue;
                for (int dz = -1; dz <= 1; dz++) {
                    int z = cz + dz; if (z < 0 || z > 4) continue;
                    int nid = b * 125 + (x * 5 + y) * 5 + z;
                    s_cells[nc] = nid;
                    s_offs[nc] = tot;
                    tot += min(g_cnt[nid], CAP_);
                    nc++;
                }
            }
        }
        s_nc = nc;
        s_offs[nc] = tot;
    }
    __syncthreads();
    int nc = s_nc, tot = s_offs[nc];

    for (int j = 0; j < nc; j++) {
        int nid = s_cells[j], off = s_offs[j], n = s_offs[j + 1] - off;
        for (int t = tid; t < n; t += 256) {
            spts[off + t] = g_pts[nid * CAP_ + t];
            sidx[off + t] = g_pidx[nid * CAP_ + t];
        }
    }
    __syncthreads();

    for (int qj = warp; qj < nq; qj += 8) {
        int qi = g_qids[cid * QCAP_ + qj];
        float qx = q_xyz[qi * 3], qy = q_xyz[qi * 3 + 1], qz = q_xyz[qi * 3 + 2];
        float qn = qx * qx + qy * qy + qz * qz;

        float d8[8]; int i8[8];
#pragma unroll
        for (int i = 0; i < 8; i++) { d8[i] = INF; i8[i] = -1; }
        float worst = INF;

        for (int t = lane; t < tot; t += 32) {
            float4 p = spts[t];
            float d2 = qn + p.w - 2.f * (qx * p.x + qy * p.y + qz * p.z);
            if (d2 <= 0.04f && d2 < worst) {
                int ii = sidx[t];
                int pp = 7;
                while (pp > 0 && d8[pp - 1] > d2) {
                    d8[pp] = d8[pp - 1]; i8[pp] = i8[pp - 1]; pp--;
                }
                d8[pp] = d2; i8[pp] = ii;
                worst = d8[7];
            }
        }

        int p = 0;
        for (int r = 0; r < 8; r++) {
            float dv = (p < 8) ? d8[p] : INF;
            int   iv = (p < 8) ? i8[p] : 0;
            unsigned db = __float_as_uint(fmaxf(dv, 0.f));
            unsigned long long key = ((unsigned long long)db << 32)
                                   | ((unsigned)(iv & 0x1FFF) << 5) | (unsigned)lane;
#pragma unroll
            for (int o = 16; o; o >>= 1) {
                unsigned long long other = __shfl_xor_sync(0xffffffffu, key, o);
                key = (other < key) ? other : key;
            }
            bool valid = ((unsigned)(key >> 32)) < 0x7f800000u;
            if (valid && lane == (int)(key & 31u)) p++;
            if (lane == 0) nidx[qi * 8 + r] = valid ? (int)((key >> 5) & 0x1FFF) : -1;
        }
    }
}

// ================= gather attention =============================================
__device__ __forceinline__ void ld8bf(const __nv_bfloat16* p, float* f) {
    uint4 u = *(const uint4*)p;
    const __nv_bfloat162* h = (const __nv_bfloat162*)&u;
#pragma unroll
    for (int i = 0; i < 4; i++) {
        float2 t = __bfloat1622float2(h[i]);
        f[2 * i] = t.x; f[2 * i + 1] = t.y;
    }
}

__global__ void attn_kernel(const __nv_bfloat16* __restrict__ QKV,
                            const __nv_bfloat16* __restrict__ KV,
                            const int* __restrict__ nidx,
                            __nv_bfloat16* __restrict__ O) {
    const float INF = __int_as_float(0x7f800000);
    int warp = threadIdx.x >> 5, lane = threadIdx.x & 31;
    int q = blockIdx.x * 8 + warp;
    int b = q >> 12;
    const int off8 = lane * 8;
    const __nv_bfloat16* qkv = QKV + (size_t)q * 768;

    float qr[8];
    ld8bf(qkv + off8, qr);

    int rid[8]; int nt = 1;
#pragma unroll
    for (int j = 0; j < 8; j++) {
        rid[j] = nidx[q * 8 + j];
        if (rid[j] >= 0) nt++;
    }
    float sc[9];
#pragma unroll
    for (int j = 0; j < 9; j++) {
        if (j == 0 || j < nt) {
            const __nv_bfloat16* kr = (j == 0)
                ? qkv + 256 + off8
                : KV + ((size_t)b * M_ + rid[j - 1]) * 512 + off8;
            float kf[8];
            ld8bf(kr, kf);
            float s = qr[0] * kf[0] + qr[1] * kf[1] + qr[2] * kf[2] + qr[3] * kf[3]
                    + qr[4] * kf[4] + qr[5] * kf[5] + qr[6] * kf[6] + qr[7] * kf[7];
            s += __shfl_xor_sync(0xffffffffu, s, 1);
            s += __shfl_xor_sync(0xffffffffu, s, 2);
            sc[j] = s * 0.17677669529663687f;
        } else sc[j] = -INF;
    }
    float m = sc[0];
#pragma unroll
    for (int j = 1; j < 9; j++) m = fmaxf(m, sc[j]);
    float w[9], ssum = 0.f;
#pragma unroll
    for (int j = 0; j < 9; j++) {
        w[j] = (j == 0 || j < nt) ? expf(sc[j] - m) : 0.f;
        ssum += w[j];
    }
    float inv = 1.f / ssum;

    float o[8] = {0, 0, 0, 0, 0, 0, 0, 0};
#pragma unroll
    for (int j = 0; j < 9; j++) {
        if (j == 0 || j < nt) {
            const __nv_bfloat16* vr = (j == 0)
                ? qkv + 512 + off8
                : KV + ((size_t)b * M_ + rid[j - 1]) * 512 + 256 + off8;
            float vf[8];
            ld8bf(vr, vf);
            float a = w[j] * inv;
#pragma unroll
            for (int d = 0; d < 8; d++) o[d] += a * vf[d];
        }
    }
    __nv_bfloat162 pk[4];
#pragma unroll
    for (int t = 0; t < 4; t++) pk[t] = __floats2bfloat162_rn(o[2 * t], o[2 * t + 1]);
    *(uint4*)&O[(size_t)q * C_ + off8] = *(uint4*)pk;
}

// ================= residual + LayerNorm (Bv in bf16) ============================
__global__ void ln_res_kernel(const float* __restrict__ A,
                              const __nv_bfloat16* __restrict__ Bv,
                              const float* __restrict__ g,
                              const float* __restrict__ be,
                              const float* __restrict__ addq,
                              float* __restrict__ out,
                              __nv_bfloat16* __restrict__ outb) {
    int warp = threadIdx.x >> 5, lane = threadIdx.x & 31;
    int row = blockIdx.x * 8 + warp;
    size_t off = (size_t)row * C_ + lane * 8;

    float v[8], bvf[8];
    float4 a0 = *(const float4*)&A[off],  a1 = *(const float4*)&A[off + 4];
    ld8bf(&Bv[off], bvf);
    v[0] = a0.x + bvf[0]; v[1] = a0.y + bvf[1]; v[2] = a0.z + bvf[2]; v[3] = a0.w + bvf[3];
    v[4] = a1.x + bvf[4]; v[5] = a1.y + bvf[5]; v[6] = a1.z + bvf[6]; v[7] = a1.w + bvf[7];

    float s = 0.f;
#pragma unroll
    for (int d = 0; d < 8; d++) s += v[d];
#pragma unroll
    for (int o = 16; o; o >>= 1) s += __shfl_xor_sync(0xffffffffu, s, o);
    float mu = s * (1.f / 256.f);
    float s2 = 0.f;
#pragma unroll
    for (int d = 0; d < 8; d++) { float t = v[d] - mu; s2 += t * t; }
#pragma unroll
    for (int o = 16; o; o >>= 1) s2 += __shfl_xor_sync(0xffffffffu, s2, o);
    float is = rsqrtf(s2 * (1.f / 256.f) + 1e-5f);

    float r[8];
#pragma unroll
    for (int d = 0; d < 8; d++) {
        r[d] = (v[d] - mu) * is * g[lane * 8 + d] + be[lane * 8 + d];
        if (addq) r[d] += addq[off + d];
    }
    if (out) {
        *(float4*)&out[off]     = make_float4(r[0], r[1], r[2], r[3]);
        *(float4*)&out[off + 4] = make_float4(r[4], r[5], r[6], r[7]);
    }
    if (outb) {
        __nv_bfloat162 pk[4];
#pragma unroll
        for (int t = 0; t < 4; t++) pk[t] = __floats2bfloat162_rn(r[2 * t], r[2 * t + 1]);
        *(uint4*)&outb[off] = *(uint4*)pk;
    }
}

// ================= launch =======================================================
extern "C" void kernel_launch(void* const* d_in, const int* in_sizes, int n_in,
                              void* d_out, int out_size) {
    (void)in_sizes; (void)n_in; (void)out_size;
    const float* q_xyz   = (const float*)d_in[0];
    const float* q_feat  = (const float*)d_in[1];
    const float* kv_xyz  = (const float*)d_in[2];
    const float* kv_feat = (const float*)d_in[3];
    const unsigned char* kv_pad = (const unsigned char*)d_in[4];
    const float* Wpos  = (const float*)d_in[5];
    const float* bpos  = (const float*)d_in[6];
    const float* Wq    = (const float*)d_in[7];
    const float* bq    = (const float*)d_in[8];
    const float* Wk    = (const float*)d_in[9];
    const float* bk    = (const float*)d_in[10];
    const float* Wv    = (const float*)d_in[11];
    const float* bv    = (const float*)d_in[12];
    const float* Wo    = (const float*)d_in[13];
    const float* bo    = (const float*)d_in[14];
    const float* ln1_g = (const float*)d_in[15];
    const float* ln1_b = (const float*)d_in[16];
    const float* W1    = (const float*)d_in[17];
    const float* b1    = (const float*)d_in[18];
    const float* W2    = (const float*)d_in[19];
    const float* b2    = (const float*)d_in[20];
    const float* ln2_g = (const float*)d_in[21];
    const float* ln2_b = (const float*)d_in[22];
    float* out = (float*)d_out;

    float *Xq, *Y, *bqkv, *bkv;
    __nv_bfloat16 *Xqb, *Xkvb, *QKVq, *KVkv, *Ob, *Tb, *Yb, *Hidb, *WTqkv, *WTkv, *WTo, *WT1, *WT2;
    int* nidx;
    cudaGetSymbolAddress((void**)&Xq,    g_Xq);
    cudaGetSymbolAddress((void**)&Xqb,   g_Xq_b);
    cudaGetSymbolAddress((void**)&Xkvb,  g_Xkv_b);
    cudaGetSymbolAddress((void**)&QKVq,  g_QKVq);
    cudaGetSymbolAddress((void**)&KVkv,  g_KVkv);
    cudaGetSymbolAddress((void**)&Ob,    g_O_b);
    cudaGetSymbolAddress((void**)&Tb,    g_T_b);
    cudaGetSymbolAddress((void**)&Y,     g_Y);
    cudaGetSymbolAddress((void**)&Yb,    g_Y_b);
    cudaGetSymbolAddress((void**)&Hidb,  g_Hid_b);
    cudaGetSymbolAddress((void**)&nidx,  g_nidx);
    cudaGetSymbolAddress((void**)&WTqkv, g_WTqkv);
    cudaGetSymbolAddress((void**)&WTkv,  g_WTkv);
    cudaGetSymbolAddress((void**)&WTo,   g_WTo);
    cudaGetSymbolAddress((void**)&WT1,   g_WT1);
    cudaGetSymbolAddress((void**)&WT2,   g_WT2);
    cudaGetSymbolAddress((void**)&bqkv,  g_bqkv);
    cudaGetSymbolAddress((void**)&bkv,   g_bkv);

    cudaFuncSetAttribute(gemm_hmma<0>, cudaFuncAttributeMaxDynamicSharedMemorySize, GEMM_SMEM);
    cudaFuncSetAttribute(gemm_hmma<1>, cudaFuncAttributeMaxDynamicSharedMemorySize, GEMM_SMEM);
    cudaFuncSetAttribute(gemm_hmma<2>, cudaFuncAttributeMaxDynamicSharedMemorySize, GEMM_SMEM);
    cudaFuncSetAttribute(knn_cell_kernel, cudaFuncAttributeMaxDynamicSharedMemorySize, KNN_SMEM);

    // 0: weight prep + cell zeroing
    prep_weights<<<(PREP_ITEMS + 255) / 256, 256>>>(Wq, Wk, Wv, Wo, W1, W2, bq, bk, bv);
    // 1: bin kv points + queries
    scatter_all<<<(NM_ + NQ_ + 255) / 256, 256>>>(kv_xyz, kv_pad, q_xyz);
    // 2: fused pos-encoding
    posenc_kernel<<<NQ_ + NM_, 256>>>(q_xyz, q_feat, kv_xyz, kv_feat, Wpos, bpos);
    // 3: cell-grouped kNN  <-- profiled slot
    knn_cell_kernel<<<NCELL_, 256, KNN_SMEM>>>(q_xyz, nidx);
    // 4: fused QKV projection
    dim3 gqkv(768 / 128, NQ_ / 128);
    gemm_hmma<2><<<gqkv, 256, GEMM_SMEM>>>(Xqb, WTqkv, bqkv, QKVq, C_, 768);
    // 5: fused KV projection
    dim3 gkv(512 / 128, NM_ / 128);
    gemm_hmma<2><<<gkv, 256, GEMM_SMEM>>>(Xkvb, WTkv, bkv, KVkv, C_, 512);
    // 6: gather attention
    attn_kernel<<<NQ_ / 8, 256>>>(QKVq, KVkv, nidx, Ob);
    // 7-8: output projection (bf16 out) + LN1
    dim3 go(C_ / 128, NQ_ / 128);
    gemm_hmma<2><<<go, 256, GEMM_SMEM>>>(Ob, WTo, bo, Tb, C_, C_);
    ln_res_kernel<<<NQ_ / 8, 256>>>(Xq, Tb, ln1_g, ln1_b, nullptr, Y, Yb);
    // 9-10: FFN
    dim3 gf1(FF_ / 128, NQ_ / 128);
    gemm_hmma<1><<<gf1, 256, GEMM_SMEM>>>(Yb, WT1, b1, Hidb, C_, FF_);
    gemm_hmma<2><<<go, 256, GEMM_SMEM>>>(Hidb, WT2, b2, Tb, FF_, C_);
    // 11: LN2 + residual + q_feat -> d_out
    ln_res_kernel<<<NQ_ / 8, 256>>>(Y, Tb, ln2_g, ln2_b, q_feat, out, nullptr);
}

// round 10
// speedup vs baseline: 1.2111x; 1.2111x over previous
#include <cuda_runtime.h>
#include <cuda_bf16.h>
#include <math.h>
#include <cstdint>

#define B_   4
#define N_   4096
#define M_   8192
#define C_   256
#define K_   8
#define FF_  1024
#define NQ_  (B_ * N_)
#define NM_  (B_ * M_)
#define NCELL_ (B_ * 125)
#define CAP_ 192
#define QCAP_ 128
#define MAXC_ (27 * CAP_)   /* 5184 */

// ================= scratch ======================================================
__device__ float          g_Xq   [NQ_ * C_];
__device__ __nv_bfloat16  g_Xq_b [NQ_ * C_];
__device__ __nv_bfloat16  g_Xkv_b[NM_ * C_];
__device__ __nv_bfloat16  g_QKVq [NQ_ * 3 * C_];
__device__ __nv_bfloat16  g_KVkv [NM_ * 2 * C_];
__device__ __nv_bfloat16  g_O_b  [NQ_ * C_];
__device__ __nv_bfloat16  g_T_b  [NQ_ * C_];
__device__ float          g_Y    [NQ_ * C_];
__device__ __nv_bfloat16  g_Y_b  [NQ_ * C_];
__device__ __nv_bfloat16  g_Hid_b[NQ_ * FF_];
__device__ int            g_nidx [NQ_ * K_];
__device__ int            g_cnt  [NCELL_];
__device__ int            g_qcnt [NCELL_];
__device__ int            g_qids [NCELL_ * QCAP_];
__device__ float4         g_pts  [NCELL_ * CAP_];
__device__ int            g_pidx [NCELL_ * CAP_];
__device__ __nv_bfloat16  g_WTqkv[3 * C_ * C_];
__device__ __nv_bfloat16  g_WTkv [2 * C_ * C_];
__device__ __nv_bfloat16  g_WTo  [C_ * C_];
__device__ __nv_bfloat16  g_WT1  [FF_ * C_];
__device__ __nv_bfloat16  g_WT2  [C_ * FF_];
__device__ float          g_bqkv [3 * C_];
__device__ float          g_bkv  [2 * C_];

__device__ __forceinline__ uint32_t smem_u32(const void* p) {
    uint32_t a;
    asm("{ .reg .u64 t; cvta.to.shared.u64 t, %1; cvt.u32.u64 %0, t; }" : "=r"(a) : "l"(p));
    return a;
}

// ================= fused weight prep + cell zeroing =============================
__global__ void prep_weights(const float* __restrict__ Wq, const float* __restrict__ Wk,
                             const float* __restrict__ Wv, const float* __restrict__ Wo,
                             const float* __restrict__ W1, const float* __restrict__ W2,
                             const float* __restrict__ bq, const float* __restrict__ bk,
                             const float* __restrict__ bv) {
    int idx = blockIdx.x * 256 + threadIdx.x;
    const int S = C_ * C_;
    const int E0 = 4 * S + 2 * C_ * FF_;
    if (idx < S) {
        int k = idx >> 8, n = idx & 255;
        g_WTqkv[(size_t)n * C_ + k] = __float2bfloat16(Wq[idx]);
    } else if (idx < 2 * S) {
        int j = idx - S; int k = j >> 8, n = j & 255;
        __nv_bfloat16 v = __float2bfloat16(Wk[j]);
        g_WTqkv[(size_t)(C_ + n) * C_ + k] = v;
        g_WTkv [(size_t)n * C_ + k] = v;
    } else if (idx < 3 * S) {
        int j = idx - 2 * S; int k = j >> 8, n = j & 255;
        __nv_bfloat16 v = __float2bfloat16(Wv[j]);
        g_WTqkv[(size_t)(2 * C_ + n) * C_ + k] = v;
        g_WTkv [(size_t)(C_ + n) * C_ + k] = v;
    } else if (idx < 4 * S) {
        int j = idx - 3 * S; int k = j >> 8, n = j & 255;
        g_WTo[(size_t)n * C_ + k] = __float2bfloat16(Wo[j]);
    } else if (idx < 4 * S + C_ * FF_) {
        int j = idx - 4 * S; int k = j >> 10, n = j & 1023;
        g_WT1[(size_t)n * C_ + k] = __float2bfloat16(W1[j]);
    } else if (idx < E0) {
        int j = idx - 4 * S - C_ * FF_; int k = j >> 8, n = j & 255;
        g_WT2[(size_t)n * FF_ + k] = __float2bfloat16(W2[j]);
    } else if (idx < E0 + 768) {
        int j = idx - E0;
        g_bqkv[j] = (j < 256) ? bq[j] : (j < 512 ? bk[j - 256] : bv[j - 512]);
    } else if (idx < E0 + 768 + 512) {
        int j = idx - E0 - 768;
        g_bkv[j] = (j < 256) ? bk[j] : bv[j - 256];
    } else if (idx < E0 + 768 + 512 + NCELL_) {
        g_cnt[idx - E0 - 768 - 512] = 0;
    } else if (idx < E0 + 768 + 512 + 2 * NCELL_) {
        g_qcnt[idx - E0 - 768 - 512 - NCELL_] = 0;
    }
}
#define PREP_ITEMS (4 * C_ * C_ + 2 * C_ * FF_ + 768 + 512 + 2 * NCELL_)

// ================= fused pos-encoding ===========================================
__global__ void posenc_kernel(const float* __restrict__ q_xyz,
                              const float* __restrict__ q_feat,
                              const float* __restrict__ kv_xyz,
                              const float* __restrict__ kv_feat,
                              const float* __restrict__ Wpos,
                              const float* __restrict__ bpos) {
    int row = blockIdx.x;
    int c   = threadIdx.x;
    const float* xyz; const float* feat;
    if (row < NQ_) { xyz = q_xyz + row * 3; feat = q_feat + (size_t)row * C_; }
    else { int r = row - NQ_; xyz = kv_xyz + r * 3; feat = kv_feat + (size_t)r * C_; }
    float x = xyz[0], y = xyz[1], z = xyz[2];
    float v = feat[c] + x * Wpos[c] + y * Wpos[C_ + c] + z * Wpos[2 * C_ + c] + bpos[c];
    if (row < NQ_) {
        g_Xq[(size_t)row * C_ + c] = v;
        g_Xq_b[(size_t)row * C_ + c] = __float2bfloat16(v);
    } else {
        g_Xkv_b[(size_t)(row - NQ_) * C_ + c] = __float2bfloat16(v);
    }
}

// ================= HMMA GEMM (R7 config: 128x128 tile, 64x32 warp, 3-stage) =====
// MODE 0: fp32 out.  MODE 1: relu+bf16 out.  MODE 2: bf16 out.
#define SSTR 40
#define STG_BYTES (128 * SSTR * 2)
#define GEMM_SMEM (3 * STG_BYTES * 2)

__device__ __forceinline__ void ldm_x4(uint32_t* r, uint32_t addr) {
    asm volatile("ldmatrix.sync.aligned.m8n8.x4.shared.b16 {%0,%1,%2,%3}, [%4];"
                 : "=r"(r[0]), "=r"(r[1]), "=r"(r[2]), "=r"(r[3]) : "r"(addr));
}
__device__ __forceinline__ void mma_bf16(float* d, const uint32_t* a, const uint32_t* b) {
    asm volatile(
        "mma.sync.aligned.m16n8k16.row.col.f32.bf16.bf16.f32 "
        "{%0,%1,%2,%3}, {%4,%5,%6,%7}, {%8,%9}, {%0,%1,%2,%3};"
        : "+f"(d[0]), "+f"(d[1]), "+f"(d[2]), "+f"(d[3])
        : "r"(a[0]), "r"(a[1]), "r"(a[2]), "r"(a[3]), "r"(b[0]), "r"(b[1]));
}
__device__ __forceinline__ void cp16(uint32_t saddr, const void* gaddr) {
    asm volatile("cp.async.cg.shared.global [%0], [%1], 16;" :: "r"(saddr), "l"(gaddr));
}

template <int MODE>
__global__ __launch_bounds__(256, 2)
void gemm_hmma(const __nv_bfloat16* __restrict__ A,
               const __nv_bfloat16* __restrict__ BT,
               const float* __restrict__ bias,
               void* __restrict__ Out, int K, int N) {
    extern __shared__ char dsm[];
    int tid  = threadIdx.x;
    int wid  = tid >> 5, lane = tid & 31;
    int row0 = blockIdx.y * 128;
    int col0 = blockIdx.x * 128;
    int wm   = (wid & 1) * 64;
    int wn   = (wid >> 1) * 32;

    uint32_t aA = smem_u32(dsm);
    uint32_t aB = aA + 3 * STG_BYTES;

    int r0i = tid >> 2, s0 = (tid & 3) * 8;
    int r1i = (tid + 256) >> 2, s1 = ((tid + 256) & 3) * 8;

    auto issue = [&](int st, int kc0) {
        uint32_t oA = aA + st * STG_BYTES, oB = aB + st * STG_BYTES;
        cp16(oA + (r0i * SSTR + s0) * 2, A  + (size_t)(row0 + r0i) * K + kc0 + s0);
        cp16(oA + (r1i * SSTR + s1) * 2, A  + (size_t)(row0 + r1i) * K + kc0 + s1);
        cp16(oB + (r0i * SSTR + s0) * 2, BT + (size_t)(col0 + r0i) * K + kc0 + s0);
        cp16(oB + (r1i * SSTR + s1) * 2, BT + (size_t)(col0 + r1i) * K + kc0 + s1);
        asm volatile("cp.async.commit_group;" ::: "memory");
    };

    float acc[4][4][4] = {};
    int nk = K >> 5;

    issue(0, 0);
    issue(1, 32);

    for (int i = 0; i < nk; i++) {
        if (i < nk - 1) asm volatile("cp.async.wait_group 1;" ::: "memory");
        else            asm volatile("cp.async.wait_group 0;" ::: "memory");
        __syncthreads();

        if (i + 2 < nk) issue((i + 2) % 3, (i + 2) << 5);

        uint32_t bA = aA + (i % 3) * STG_BYTES;
        uint32_t bB = aB + (i % 3) * STG_BYTES;
#pragma unroll
        for (int ks = 0; ks < 2; ks++) {
            uint32_t afr[4][4];
#pragma unroll
            for (int mt = 0; mt < 4; mt++) {
                uint32_t addr = bA + ((wm + mt * 16 + (lane & 15)) * SSTR
                                      + ks * 16 + ((lane >> 4) << 3)) * 2;
                ldm_x4(afr[mt], addr);
            }
            uint32_t bfr[2][4];
#pragma unroll
            for (int np = 0; np < 2; np++) {
                uint32_t row = wn + np * 16 + ((lane >> 4) << 3) + (lane & 7);
                uint32_t kc  = ks * 16 + ((lane >> 3) & 1) * 8;
                ldm_x4(bfr[np], bB + (row * SSTR + kc) * 2);
            }
#pragma unroll
            for (int mt = 0; mt < 4; mt++)
#pragma unroll
                for (int nt = 0; nt < 4; nt++)
                    mma_bf16(acc[mt][nt], afr[mt], &bfr[nt >> 1][(nt & 1) * 2]);
        }
    }

    int g  = lane >> 2;
    int t2 = (lane & 3) * 2;
#pragma unroll
    for (int mt = 0; mt < 4; mt++) {
#pragma unroll
        for (int nt = 0; nt < 4; nt++) {
            int row = row0 + wm + mt * 16 + g;
            int col = col0 + wn + nt * 8 + t2;
            float2 b2 = *(const float2*)&bias[col];
            float v0 = acc[mt][nt][0] + b2.x, v1 = acc[mt][nt][1] + b2.y;
            float v2 = acc[mt][nt][2] + b2.x, v3 = acc[mt][nt][3] + b2.y;
            if (MODE == 0) {
                float* op = (float*)Out;
                *(float2*)&op[(size_t)row * N + col]       = make_float2(v0, v1);
                *(float2*)&op[(size_t)(row + 8) * N + col] = make_float2(v2, v3);
            } else {
                if (MODE == 1) {
                    v0 = fmaxf(v0, 0.f); v1 = fmaxf(v1, 0.f);
                    v2 = fmaxf(v2, 0.f); v3 = fmaxf(v3, 0.f);
                }
                __nv_bfloat16* op = (__nv_bfloat16*)Out;
                *(__nv_bfloat162*)&op[(size_t)row * N + col]       = __floats2bfloat162_rn(v0, v1);
                *(__nv_bfloat162*)&op[(size_t)(row + 8) * N + col] = __floats2bfloat162_rn(v2, v3);
            }
        }
    }
}

// ================= binning: kv points AND queries ===============================
__device__ __forceinline__ int cell_of(float x, float y, float z) {
    int cx = min((int)(x * 5.f), 4);
    int cy = min((int)(y * 5.f), 4);
    int cz = min((int)(z * 5.f), 4);
    return (cx * 5 + cy) * 5 + cz;
}

__global__ void scatter_all(const float* __restrict__ kv_xyz,
                            const unsigned char* __restrict__ kv_pad,
                            const float* __restrict__ q_xyz) {
    int i = blockIdx.x * 256 + threadIdx.x;
    if (i < NM_) {
        if (kv_pad[i]) return;
        int b = i >> 13;
        float x = kv_xyz[i * 3], y = kv_xyz[i * 3 + 1], z = kv_xyz[i * 3 + 2];
        int cid = b * 125 + cell_of(x, y, z);
        int pos = atomicAdd(&g_cnt[cid], 1);
        if (pos < CAP_) {
            g_pts[cid * CAP_ + pos] = make_float4(x, y, z, x * x + y * y + z * z);
            g_pidx[cid * CAP_ + pos] = i & 8191;
        }
    } else {
        int qi = i - NM_;
        if (qi >= NQ_) return;
        int b = qi >> 12;
        float x = q_xyz[qi * 3], y = q_xyz[qi * 3 + 1], z = q_xyz[qi * 3 + 2];
        int cid = b * 125 + cell_of(x, y, z);
        int pos = atomicAdd(&g_qcnt[cid], 1);
        if (pos < QCAP_) g_qids[cid * QCAP_ + pos] = qi;
    }
}

// ================= cell-grouped kNN: 1 CTA (1024 thr, 32 warps) per cell ========
#define KNN_SMEM (MAXC_ * 20 + 256)

__global__ __launch_bounds__(1024)
void knn_cell_kernel(const float* __restrict__ q_xyz, int* __restrict__ nidx) {
    const float INF = __int_as_float(0x7f800000);
    int cid = blockIdx.x;
    int nq = min(g_qcnt[cid], QCAP_);
    if (nq == 0) return;
    int b = cid / 125;
    int cc = cid % 125;
    int cx = cc / 25, cy = (cc / 5) % 5, cz = cc % 5;

    extern __shared__ char sm[];
    float4* spts = (float4*)sm;
    int*    sidx = (int*)(sm + MAXC_ * 16);
    __shared__ int s_cells[27], s_offs[28];
    __shared__ int s_nc;

    int tid = threadIdx.x, warp = tid >> 5, lane = tid & 31;

    if (tid == 0) {
        int nc = 0, tot = 0;
        for (int dx = -1; dx <= 1; dx++) {
            int x = cx + dx; if (x < 0 || x > 4) continue;
            for (int dy = -1; dy <= 1; dy++) {
                int y = cy + dy; if (y < 0 || y > 4) continue;
                for (int dz = -1; dz <= 1; dz++) {
                    int z = cz + dz; if (z < 0 || z > 4) continue;
                    int nid = b * 125 + (x * 5 + y) * 5 + z;
                    s_cells[nc] = nid;
                    s_offs[nc] = tot;
                    tot += min(g_cnt[nid], CAP_);
                    nc++;
                }
            }
        }
        s_nc = nc;
        s_offs[nc] = tot;
    }
    __syncthreads();
    int nc = s_nc, tot = s_offs[nc];

    for (int j = 0; j < nc; j++) {
        int nid = s_cells[j], off = s_offs[j], n = s_offs[j + 1] - off;
        for (int t = tid; t < n; t += 1024) {
            spts[off + t] = g_pts[nid * CAP_ + t];
            sidx[off + t] = g_pidx[nid * CAP_ + t];
        }
    }
    __syncthreads();

    // warp-per-query over SMEM candidates
    for (int qj = warp; qj < nq; qj += 32) {
        int qi = g_qids[cid * QCAP_ + qj];
        float qx = q_xyz[qi * 3], qy = q_xyz[qi * 3 + 1], qz = q_xyz[qi * 3 + 2];
        float qn = qx * qx + qy * qy + qz * qz;

        float d8[8]; int i8[8];
#pragma unroll
        for (int i = 0; i < 8; i++) { d8[i] = INF; i8[i] = -1; }
        float worst = INF;

        for (int t = lane; t < tot; t += 32) {
            float4 p = spts[t];
            float d2 = qn + p.w - 2.f * (qx * p.x + qy * p.y + qz * p.z);
            if (d2 <= 0.04f && d2 < worst) {
                int ii = sidx[t];
                int pp = 7;
                while (pp > 0 && d8[pp - 1] > d2) {
                    d8[pp] = d8[pp - 1]; i8[pp] = i8[pp - 1]; pp--;
                }
                d8[pp] = d2; i8[pp] = ii;
                worst = d8[7];
            }
        }

        int p = 0;
        for (int r = 0; r < 8; r++) {
            float dv = (p < 8) ? d8[p] : INF;
            int   iv = (p < 8) ? i8[p] : 0;
            unsigned db = __float_as_uint(fmaxf(dv, 0.f));
            unsigned long long key = ((unsigned long long)db << 32)
                                   | ((unsigned)(iv & 0x1FFF) << 5) | (unsigned)lane;
#pragma unroll
            for (int o = 16; o; o >>= 1) {
                unsigned long long other = __shfl_xor_sync(0xffffffffu, key, o);
                key = (other < key) ? other : key;
            }
            bool valid = ((unsigned)(key >> 32)) < 0x7f800000u;
            if (valid && lane == (int)(key & 31u)) p++;
            if (lane == 0) nidx[qi * 8 + r] = valid ? (int)((key >> 5) & 0x1FFF) : -1;
        }
    }
}

// ================= gather attention =============================================
__device__ __forceinline__ void ld8bf(const __nv_bfloat16* p, float* f) {
    uint4 u = *(const uint4*)p;
    const __nv_bfloat162* h = (const __nv_bfloat162*)&u;
#pragma unroll
    for (int i = 0; i < 4; i++) {
        float2 t = __bfloat1622float2(h[i]);
        f[2 * i] = t.x; f[2 * i + 1] = t.y;
    }
}

__global__ void attn_kernel(const __nv_bfloat16* __restrict__ QKV,
                            const __nv_bfloat16* __restrict__ KV,
                            const int* __restrict__ nidx,
                            __nv_bfloat16* __restrict__ O) {
    const float INF = __int_as_float(0x7f800000);
    int warp = threadIdx.x >> 5, lane = threadIdx.x & 31;
    int q = blockIdx.x * 8 + warp;
    int b = q >> 12;
    const int off8 = lane * 8;
    const __nv_bfloat16* qkv = QKV + (size_t)q * 768;

    float qr[8];
    ld8bf(qkv + off8, qr);

    int rid[8]; int nt = 1;
#pragma unroll
    for (int j = 0; j < 8; j++) {
        rid[j] = nidx[q * 8 + j];
        if (rid[j] >= 0) nt++;
    }
    float sc[9];
#pragma unroll
    for (int j = 0; j < 9; j++) {
        if (j == 0 || j < nt) {
            const __nv_bfloat16* kr = (j == 0)
                ? qkv + 256 + off8
                : KV + ((size_t)b * M_ + rid[j - 1]) * 512 + off8;
            float kf[8];
            ld8bf(kr, kf);
            float s = qr[0] * kf[0] + qr[1] * kf[1] + qr[2] * kf[2] + qr[3] * kf[3]
                    + qr[4] * kf[4] + qr[5] * kf[5] + qr[6] * kf[6] + qr[7] * kf[7];
            s += __shfl_xor_sync(0xffffffffu, s, 1);
            s += __shfl_xor_sync(0xffffffffu, s, 2);
            sc[j] = s * 0.17677669529663687f;
        } else sc[j] = -INF;
    }
    float m = sc[0];
#pragma unroll
    for (int j = 1; j < 9; j++) m = fmaxf(m, sc[j]);
    float w[9], ssum = 0.f;
#pragma unroll
    for (int j = 0; j < 9; j++) {
        w[j] = (j == 0 || j < nt) ? expf(sc[j] - m) : 0.f;
        ssum += w[j];
    }
    float inv = 1.f / ssum;

    float o[8] = {0, 0, 0, 0, 0, 0, 0, 0};
#pragma unroll
    for (int j = 0; j < 9; j++) {
        if (j == 0 || j < nt) {
            const __nv_bfloat16* vr = (j == 0)
                ? qkv + 512 + off8
                : KV + ((size_t)b * M_ + rid[j - 1]) * 512 + 256 + off8;
            float vf[8];
            ld8bf(vr, vf);
            float a = w[j] * inv;
#pragma unroll
            for (int d = 0; d < 8; d++) o[d] += a * vf[d];
        }
    }
    __nv_bfloat162 pk[4];
#pragma unroll
    for (int t = 0; t < 4; t++) pk[t] = __floats2bfloat162_rn(o[2 * t], o[2 * t + 1]);
    *(uint4*)&O[(size_t)q * C_ + off8] = *(uint4*)pk;
}

// ================= residual + LayerNorm (Bv in bf16) ============================
__global__ void ln_res_kernel(const float* __restrict__ A,
                              const __nv_bfloat16* __restrict__ Bv,
                              const float* __restrict__ g,
                              const float* __restrict__ be,
                              const float* __restrict__ addq,
                              float* __restrict__ out,
                              __nv_bfloat16* __restrict__ outb) {
    int warp = threadIdx.x >> 5, lane = threadIdx.x & 31;
    int row = blockIdx.x * 8 + warp;
    size_t off = (size_t)row * C_ + lane * 8;

    float v[8], bvf[8];
    float4 a0 = *(const float4*)&A[off],  a1 = *(const float4*)&A[off + 4];
    ld8bf(&Bv[off], bvf);
    v[0] = a0.x + bvf[0]; v[1] = a0.y + bvf[1]; v[2] = a0.z + bvf[2]; v[3] = a0.w + bvf[3];
    v[4] = a1.x + bvf[4]; v[5] = a1.y + bvf[5]; v[6] = a1.z + bvf[6]; v[7] = a1.w + bvf[7];

    float s = 0.f;
#pragma unroll
    for (int d = 0; d < 8; d++) s += v[d];
#pragma unroll
    for (int o = 16; o; o >>= 1) s += __shfl_xor_sync(0xffffffffu, s, o);
    float mu = s * (1.f / 256.f);
    float s2 = 0.f;
#pragma unroll
    for (int d = 0; d < 8; d++) { float t = v[d] - mu; s2 += t * t; }
#pragma unroll
    for (int o = 16; o; o >>= 1) s2 += __shfl_xor_sync(0xffffffffu, s2, o);
    float is = rsqrtf(s2 * (1.f / 256.f) + 1e-5f);

    float r[8];
#pragma unroll
    for (int d = 0; d < 8; d++) {
        r[d] = (v[d] - mu) * is * g[lane * 8 + d] + be[lane * 8 + d];
        if (addq) r[d] += addq[off + d];
    }
    if (out) {
        *(float4*)&out[off]     = make_float4(r[0], r[1], r[2], r[3]);
        *(float4*)&out[off + 4] = make_float4(r[4], r[5], r[6], r[7]);
    }
    if (outb) {
        __nv_bfloat162 pk[4];
#pragma unroll
        for (int t = 0; t < 4; t++) pk[t] = __floats2bfloat162_rn(r[2 * t], r[2 * t + 1]);
        *(uint4*)&outb[off] = *(uint4*)pk;
    }
}

// ================= launch =======================================================
extern "C" void kernel_launch(void* const* d_in, const int* in_sizes, int n_in,
                              void* d_out, int out_size) {
    (void)in_sizes; (void)n_in; (void)out_size;
    const float* q_xyz   = (const float*)d_in[0];
    const float* q_feat  = (const float*)d_in[1];
    const float* kv_xyz  = (const float*)d_in[2];
    const float* kv_feat = (const float*)d_in[3];
    const unsigned char* kv_pad = (const unsigned char*)d_in[4];
    const float* Wpos  = (const float*)d_in[5];
    const float* bpos  = (const float*)d_in[6];
    const float* Wq    = (const float*)d_in[7];
    const float* bq    = (const float*)d_in[8];
    const float* Wk    = (const float*)d_in[9];
    const float* bk    = (const float*)d_in[10];
    const float* Wv    = (const float*)d_in[11];
    const float* bv    = (const float*)d_in[12];
    const float* Wo    = (const float*)d_in[13];
    const float* bo    = (const float*)d_in[14];
    const float* ln1_g = (const float*)d_in[15];
    const float* ln1_b = (const float*)d_in[16];
    const float* W1    = (const float*)d_in[17];
    const float* b1    = (const float*)d_in[18];
    const float* W2    = (const float*)d_in[19];
    const float* b2    = (const float*)d_in[20];
    const float* ln2_g = (const float*)d_in[21];
    const float* ln2_b = (const float*)d_in[22];
    float* out = (float*)d_out;

    float *Xq, *Y, *bqkv, *bkv;
    __nv_bfloat16 *Xqb, *Xkvb, *QKVq, *KVkv, *Ob, *Tb, *Yb, *Hidb, *WTqkv, *WTkv, *WTo, *WT1, *WT2;
    int* nidx;
    cudaGetSymbolAddress((void**)&Xq,    g_Xq);
    cudaGetSymbolAddress((void**)&Xqb,   g_Xq_b);
    cudaGetSymbolAddress((void**)&Xkvb,  g_Xkv_b);
    cudaGetSymbolAddress((void**)&QKVq,  g_QKVq);
    cudaGetSymbolAddress((void**)&KVkv,  g_KVkv);
    cudaGetSymbolAddress((void**)&Ob,    g_O_b);
    cudaGetSymbolAddress((void**)&Tb,    g_T_b);
    cudaGetSymbolAddress((void**)&Y,     g_Y);
    cudaGetSymbolAddress((void**)&Yb,    g_Y_b);
    cudaGetSymbolAddress((void**)&Hidb,  g_Hid_b);
    cudaGetSymbolAddress((void**)&nidx,  g_nidx);
    cudaGetSymbolAddress((void**)&WTqkv, g_WTqkv);
    cudaGetSymbolAddress((void**)&WTkv,  g_WTkv);
    cudaGetSymbolAddress((void**)&WTo,   g_WTo);
    cudaGetSymbolAddress((void**)&WT1,   g_WT1);
    cudaGetSymbolAddress((void**)&WT2,   g_WT2);
    cudaGetSymbolAddress((void**)&bqkv,  g_bqkv);
    cudaGetSymbolAddress((void**)&bkv,   g_bkv);

    cudaFuncSetAttribute(gemm_hmma<0>, cudaFuncAttributeMaxDynamicSharedMemorySize, GEMM_SMEM);
    cudaFuncSetAttribute(gemm_hmma<1>, cudaFuncAttributeMaxDynamicSharedMemorySize, GEMM_SMEM);
    cudaFuncSetAttribute(gemm_hmma<2>, cudaFuncAttributeMaxDynamicSharedMemorySize, GEMM_SMEM);
    cudaFuncSetAttribute(knn_cell_kernel, cudaFuncAttributeMaxDynamicSharedMemorySize, KNN_SMEM);

    // 0: weight prep + cell zeroing
    prep_weights<<<(PREP_ITEMS + 255) / 256, 256>>>(Wq, Wk, Wv, Wo, W1, W2, bq, bk, bv);
    // 1: bin kv points + queries
    scatter_all<<<(NM_ + NQ_ + 255) / 256, 256>>>(kv_xyz, kv_pad, q_xyz);
    // 2: fused pos-encoding
    posenc_kernel<<<NQ_ + NM_, 256>>>(q_xyz, q_feat, kv_xyz, kv_feat, Wpos, bpos);
    // 3: cell-grouped kNN (1024 threads)  <-- profiled slot
    knn_cell_kernel<<<NCELL_, 1024, KNN_SMEM>>>(q_xyz, nidx);
    // 4: fused QKV projection
    dim3 gqkv(768 / 128, NQ_ / 128);
    gemm_hmma<2><<<gqkv, 256, GEMM_SMEM>>>(Xqb, WTqkv, bqkv, QKVq, C_, 768);
    // 5: fused KV projection
    dim3 gkv(512 / 128, NM_ / 128);
    gemm_hmma<2><<<gkv, 256, GEMM_SMEM>>>(Xkvb, WTkv, bkv, KVkv, C_, 512);
    // 6: gather attention
    attn_kernel<<<NQ_ / 8, 256>>>(QKVq, KVkv, nidx, Ob);
    // 7-8: output projection (bf16 out) + LN1
    dim3 go(C_ / 128, NQ_ / 128);
    gemm_hmma<2><<<go, 256, GEMM_SMEM>>>(Ob, WTo, bo, Tb, C_, C_);
    ln_res_kernel<<<NQ_ / 8, 256>>>(Xq, Tb, ln1_g, ln1_b, nullptr, Y, Yb);
    // 9-10: FFN
    dim3 gf1(FF_ / 128, NQ_ / 128);
    gemm_hmma<1><<<gf1, 256, GEMM_SMEM>>>(Yb, WT1, b1, Hidb, C_, FF_);
    gemm_hmma<2><<<go, 256, GEMM_SMEM>>>(Hidb, WT2, b2, Tb, FF_, C_);
    // 11: LN2 + residual + q_feat -> d_out
    ln_res_kernel<<<NQ_ / 8, 256>>>(Y, Tb, ln2_g, ln2_b, q_feat, out, nullptr);
}

// round 11
// speedup vs baseline: 1.7540x; 1.4483x over previous
#include <cuda_runtime.h>
#include <cuda_bf16.h>
#include <math.h>
#include <cstdint>

#define B_   4
#define N_   4096
#define M_   8192
#define C_   256
#define K_   8
#define FF_  1024
#define NQ_  (B_ * N_)
#define NM_  (B_ * M_)
#define NCELL_ (B_ * 125)
#define CAP_ 192
#define QCAP_ 128
#define SCAP_ 2400   /* smem candidate cap: mean 1769, sigma 42 -> 15 sigma margin */

// ================= scratch ======================================================
__device__ float          g_Xq   [NQ_ * C_];
__device__ __nv_bfloat16  g_Xq_b [NQ_ * C_];
__device__ __nv_bfloat16  g_Xkv_b[NM_ * C_];
__device__ __nv_bfloat16  g_QKVq [NQ_ * 3 * C_];
__device__ __nv_bfloat16  g_KVkv [NM_ * 2 * C_];
__device__ __nv_bfloat16  g_O_b  [NQ_ * C_];
__device__ __nv_bfloat16  g_T_b  [NQ_ * C_];
__device__ float          g_Y    [NQ_ * C_];
__device__ __nv_bfloat16  g_Y_b  [NQ_ * C_];
__device__ __nv_bfloat16  g_Hid_b[NQ_ * FF_];
__device__ int            g_nidx [NQ_ * K_];
__device__ int            g_cnt  [NCELL_];
__device__ int            g_qcnt [NCELL_];
__device__ int            g_qids [NCELL_ * QCAP_];
__device__ float4         g_pts  [NCELL_ * CAP_];
__device__ int            g_pidx [NCELL_ * CAP_];
__device__ __nv_bfloat16  g_WTqkv[3 * C_ * C_];
__device__ __nv_bfloat16  g_WTkv [2 * C_ * C_];
__device__ __nv_bfloat16  g_WTo  [C_ * C_];
__device__ __nv_bfloat16  g_WT1  [FF_ * C_];
__device__ __nv_bfloat16  g_WT2  [C_ * FF_];
__device__ float          g_bqkv [3 * C_];
__device__ float          g_bkv  [2 * C_];

__device__ __forceinline__ uint32_t smem_u32(const void* p) {
    uint32_t a;
    asm("{ .reg .u64 t; cvta.to.shared.u64 t, %1; cvt.u32.u64 %0, t; }" : "=r"(a) : "l"(p));
    return a;
}

// ================= fused weight prep + cell zeroing =============================
__global__ void prep_weights(const float* __restrict__ Wq, const float* __restrict__ Wk,
                             const float* __restrict__ Wv, const float* __restrict__ Wo,
                             const float* __restrict__ W1, const float* __restrict__ W2,
                             const float* __restrict__ bq, const float* __restrict__ bk,
                             const float* __restrict__ bv) {
    int idx = blockIdx.x * 256 + threadIdx.x;
    const int S = C_ * C_;
    const int E0 = 4 * S + 2 * C_ * FF_;
    if (idx < S) {
        int k = idx >> 8, n = idx & 255;
        g_WTqkv[(size_t)n * C_ + k] = __float2bfloat16(Wq[idx]);
    } else if (idx < 2 * S) {
        int j = idx - S; int k = j >> 8, n = j & 255;
        __nv_bfloat16 v = __float2bfloat16(Wk[j]);
        g_WTqkv[(size_t)(C_ + n) * C_ + k] = v;
        g_WTkv [(size_t)n * C_ + k] = v;
    } else if (idx < 3 * S) {
        int j = idx - 2 * S; int k = j >> 8, n = j & 255;
        __nv_bfloat16 v = __float2bfloat16(Wv[j]);
        g_WTqkv[(size_t)(2 * C_ + n) * C_ + k] = v;
        g_WTkv [(size_t)(C_ + n) * C_ + k] = v;
    } else if (idx < 4 * S) {
        int j = idx - 3 * S; int k = j >> 8, n = j & 255;
        g_WTo[(size_t)n * C_ + k] = __float2bfloat16(Wo[j]);
    } else if (idx < 4 * S + C_ * FF_) {
        int j = idx - 4 * S; int k = j >> 10, n = j & 1023;
        g_WT1[(size_t)n * C_ + k] = __float2bfloat16(W1[j]);
    } else if (idx < E0) {
        int j = idx - 4 * S - C_ * FF_; int k = j >> 8, n = j & 255;
        g_WT2[(size_t)n * FF_ + k] = __float2bfloat16(W2[j]);
    } else if (idx < E0 + 768) {
        int j = idx - E0;
        g_bqkv[j] = (j < 256) ? bq[j] : (j < 512 ? bk[j - 256] : bv[j - 512]);
    } else if (idx < E0 + 768 + 512) {
        int j = idx - E0 - 768;
        g_bkv[j] = (j < 256) ? bk[j] : bv[j - 256];
    } else if (idx < E0 + 768 + 512 + NCELL_) {
        g_cnt[idx - E0 - 768 - 512] = 0;
    } else if (idx < E0 + 768 + 512 + 2 * NCELL_) {
        g_qcnt[idx - E0 - 768 - 512 - NCELL_] = 0;
    }
}
#define PREP_ITEMS (4 * C_ * C_ + 2 * C_ * FF_ + 768 + 512 + 2 * NCELL_)

// ================= fused pos-encoding ===========================================
__global__ void posenc_kernel(const float* __restrict__ q_xyz,
                              const float* __restrict__ q_feat,
                              const float* __restrict__ kv_xyz,
                              const float* __restrict__ kv_feat,
                              const float* __restrict__ Wpos,
                              const float* __restrict__ bpos) {
    int row = blockIdx.x;
    int c   = threadIdx.x;
    const float* xyz; const float* feat;
    if (row < NQ_) { xyz = q_xyz + row * 3; feat = q_feat + (size_t)row * C_; }
    else { int r = row - NQ_; xyz = kv_xyz + r * 3; feat = kv_feat + (size_t)r * C_; }
    float x = xyz[0], y = xyz[1], z = xyz[2];
    float v = feat[c] + x * Wpos[c] + y * Wpos[C_ + c] + z * Wpos[2 * C_ + c] + bpos[c];
    if (row < NQ_) {
        g_Xq[(size_t)row * C_ + c] = v;
        g_Xq_b[(size_t)row * C_ + c] = __float2bfloat16(v);
    } else {
        g_Xkv_b[(size_t)(row - NQ_) * C_ + c] = __float2bfloat16(v);
    }
}

// ================= HMMA GEMM (R7 config: 128x128 tile, 64x32 warp, 3-stage) =====
#define SSTR 40
#define STG_BYTES (128 * SSTR * 2)
#define GEMM_SMEM (3 * STG_BYTES * 2)

__device__ __forceinline__ void ldm_x4(uint32_t* r, uint32_t addr) {
    asm volatile("ldmatrix.sync.aligned.m8n8.x4.shared.b16 {%0,%1,%2,%3}, [%4];"
                 : "=r"(r[0]), "=r"(r[1]), "=r"(r[2]), "=r"(r[3]) : "r"(addr));
}
__device__ __forceinline__ void mma_bf16(float* d, const uint32_t* a, const uint32_t* b) {
    asm volatile(
        "mma.sync.aligned.m16n8k16.row.col.f32.bf16.bf16.f32 "
        "{%0,%1,%2,%3}, {%4,%5,%6,%7}, {%8,%9}, {%0,%1,%2,%3};"
        : "+f"(d[0]), "+f"(d[1]), "+f"(d[2]), "+f"(d[3])
        : "r"(a[0]), "r"(a[1]), "r"(a[2]), "r"(a[3]), "r"(b[0]), "r"(b[1]));
}
__device__ __forceinline__ void cp16(uint32_t saddr, const void* gaddr) {
    asm volatile("cp.async.cg.shared.global [%0], [%1], 16;" :: "r"(saddr), "l"(gaddr));
}

template <int MODE>
__global__ __launch_bounds__(256, 2)
void gemm_hmma(const __nv_bfloat16* __restrict__ A,
               const __nv_bfloat16* __restrict__ BT,
               const float* __restrict__ bias,
               void* __restrict__ Out, int K, int N) {
    extern __shared__ char dsm[];
    int tid  = threadIdx.x;
    int wid  = tid >> 5, lane = tid & 31;
    int row0 = blockIdx.y * 128;
    int col0 = blockIdx.x * 128;
    int wm   = (wid & 1) * 64;
    int wn   = (wid >> 1) * 32;

    uint32_t aA = smem_u32(dsm);
    uint32_t aB = aA + 3 * STG_BYTES;

    int r0i = tid >> 2, s0 = (tid & 3) * 8;
    int r1i = (tid + 256) >> 2, s1 = ((tid + 256) & 3) * 8;

    auto issue = [&](int st, int kc0) {
        uint32_t oA = aA + st * STG_BYTES, oB = aB + st * STG_BYTES;
        cp16(oA + (r0i * SSTR + s0) * 2, A  + (size_t)(row0 + r0i) * K + kc0 + s0);
        cp16(oA + (r1i * SSTR + s1) * 2, A  + (size_t)(row0 + r1i) * K + kc0 + s1);
        cp16(oB + (r0i * SSTR + s0) * 2, BT + (size_t)(col0 + r0i) * K + kc0 + s0);
        cp16(oB + (r1i * SSTR + s1) * 2, BT + (size_t)(col0 + r1i) * K + kc0 + s1);
        asm volatile("cp.async.commit_group;" ::: "memory");
    };

    float acc[4][4][4] = {};
    int nk = K >> 5;

    issue(0, 0);
    issue(1, 32);

    for (int i = 0; i < nk; i++) {
        if (i < nk - 1) asm volatile("cp.async.wait_group 1;" ::: "memory");
        else            asm volatile("cp.async.wait_group 0;" ::: "memory");
        __syncthreads();

        if (i + 2 < nk) issue((i + 2) % 3, (i + 2) << 5);

        uint32_t bA = aA + (i % 3) * STG_BYTES;
        uint32_t bB = aB + (i % 3) * STG_BYTES;
#pragma unroll
        for (int ks = 0; ks < 2; ks++) {
            uint32_t afr[4][4];
#pragma unroll
            for (int mt = 0; mt < 4; mt++) {
                uint32_t addr = bA + ((wm + mt * 16 + (lane & 15)) * SSTR
                                      + ks * 16 + ((lane >> 4) << 3)) * 2;
                ldm_x4(afr[mt], addr);
            }
            uint32_t bfr[2][4];
#pragma unroll
            for (int np = 0; np < 2; np++) {
                uint32_t row = wn + np * 16 + ((lane >> 4) << 3) + (lane & 7);
                uint32_t kc  = ks * 16 + ((lane >> 3) & 1) * 8;
                ldm_x4(bfr[np], bB + (row * SSTR + kc) * 2);
            }
#pragma unroll
            for (int mt = 0; mt < 4; mt++)
#pragma unroll
                for (int nt = 0; nt < 4; nt++)
                    mma_bf16(acc[mt][nt], afr[mt], &bfr[nt >> 1][(nt & 1) * 2]);
        }
    }

    int g  = lane >> 2;
    int t2 = (lane & 3) * 2;
#pragma unroll
    for (int mt = 0; mt < 4; mt++) {
#pragma unroll
        for (int nt = 0; nt < 4; nt++) {
            int row = row0 + wm + mt * 16 + g;
            int col = col0 + wn + nt * 8 + t2;
            float2 b2 = *(const float2*)&bias[col];
            float v0 = acc[mt][nt][0] + b2.x, v1 = acc[mt][nt][1] + b2.y;
            float v2 = acc[mt][nt][2] + b2.x, v3 = acc[mt][nt][3] + b2.y;
            if (MODE == 0) {
                float* op = (float*)Out;
                *(float2*)&op[(size_t)row * N + col]       = make_float2(v0, v1);
                *(float2*)&op[(size_t)(row + 8) * N + col] = make_float2(v2, v3);
            } else {
                if (MODE == 1) {
                    v0 = fmaxf(v0, 0.f); v1 = fmaxf(v1, 0.f);
                    v2 = fmaxf(v2, 0.f); v3 = fmaxf(v3, 0.f);
                }
                __nv_bfloat16* op = (__nv_bfloat16*)Out;
                *(__nv_bfloat162*)&op[(size_t)row * N + col]       = __floats2bfloat162_rn(v0, v1);
                *(__nv_bfloat162*)&op[(size_t)(row + 8) * N + col] = __floats2bfloat162_rn(v2, v3);
            }
        }
    }
}

// ================= binning: kv points AND queries ===============================
__device__ __forceinline__ int cell_of(float x, float y, float z) {
    int cx = min((int)(x * 5.f), 4);
    int cy = min((int)(y * 5.f), 4);
    int cz = min((int)(z * 5.f), 4);
    return (cx * 5 + cy) * 5 + cz;
}

__global__ void scatter_all(const float* __restrict__ kv_xyz,
                            const unsigned char* __restrict__ kv_pad,
                            const float* __restrict__ q_xyz) {
    int i = blockIdx.x * 256 + threadIdx.x;
    if (i < NM_) {
        if (kv_pad[i]) return;
        int b = i >> 13;
        float x = kv_xyz[i * 3], y = kv_xyz[i * 3 + 1], z = kv_xyz[i * 3 + 2];
        int cid = b * 125 + cell_of(x, y, z);
        int pos = atomicAdd(&g_cnt[cid], 1);
        if (pos < CAP_) {
            g_pts[cid * CAP_ + pos] = make_float4(x, y, z, x * x + y * y + z * z);
            g_pidx[cid * CAP_ + pos] = i & 8191;
        }
    } else {
        int qi = i - NM_;
        if (qi >= NQ_) return;
        int b = qi >> 12;
        float x = q_xyz[qi * 3], y = q_xyz[qi * 3 + 1], z = q_xyz[qi * 3 + 2];
        int cid = b * 125 + cell_of(x, y, z);
        int pos = atomicAdd(&g_qcnt[cid], 1);
        if (pos < QCAP_) g_qids[cid * QCAP_ + pos] = qi;
    }
}

// ================= cell-grouped kNN: register-resident top-8 ====================
#define KNN_SMEM (SCAP_ * 20)

__global__ __launch_bounds__(512, 3)
void knn_cell_kernel(const float* __restrict__ q_xyz, int* __restrict__ nidx) {
    const float INF = __int_as_float(0x7f800000);
    int cid = blockIdx.x;
    int nq = min(g_qcnt[cid], QCAP_);
    if (nq == 0) return;
    int b = cid / 125;
    int cc = cid % 125;
    int cx = cc / 25, cy = (cc / 5) % 5, cz = cc % 5;

    extern __shared__ char sm[];
    float4* spts = (float4*)sm;
    int*    sidx = (int*)(sm + SCAP_ * 16);
    __shared__ int s_cells[27], s_offs[28];
    __shared__ int s_nc;

    int tid = threadIdx.x, warp = tid >> 5, lane = tid & 31;

    if (tid == 0) {
        int nc = 0, tot = 0;
        for (int dx = -1; dx <= 1; dx++) {
            int x = cx + dx; if (x < 0 || x > 4) continue;
            for (int dy = -1; dy <= 1; dy++) {
                int y = cy + dy; if (y < 0 || y > 4) continue;
                for (int dz = -1; dz <= 1; dz++) {
                    int z = cz + dz; if (z < 0 || z > 4) continue;
                    int nid = b * 125 + (x * 5 + y) * 5 + z;
                    int c = min(g_cnt[nid], CAP_);
                    if (tot + c > SCAP_) c = SCAP_ - tot;  // 15-sigma headroom; never hit
                    s_cells[nc] = nid;
                    s_offs[nc] = tot;
                    tot += c;
                    nc++;
                }
            }
        }
        s_nc = nc;
        s_offs[nc] = tot;
    }
    __syncthreads();
    int nc = s_nc, tot = s_offs[nc];

    for (int j = 0; j < nc; j++) {
        int nid = s_cells[j], off = s_offs[j], n = s_offs[j + 1] - off;
        for (int t = tid; t < n; t += 512) {
            spts[off + t] = g_pts[nid * CAP_ + t];
            sidx[off + t] = g_pidx[nid * CAP_ + t];
        }
    }
    __syncthreads();

    // warp-per-query over SMEM candidates; top-8 lists fully register-resident
    for (int qj = warp; qj < nq; qj += 16) {
        int qi = g_qids[cid * QCAP_ + qj];
        float qx = q_xyz[qi * 3], qy = q_xyz[qi * 3 + 1], qz = q_xyz[qi * 3 + 2];
        float qn = qx * qx + qy * qy + qz * qz;

        float d8[8]; int i8[8];
#pragma unroll
        for (int i = 0; i < 8; i++) { d8[i] = INF; i8[i] = -1; }

        for (int t = lane; t < tot; t += 32) {
            float4 p = spts[t];
            float d2 = qn + p.w - 2.f * (qx * p.x + qy * p.y + qz * p.z);
            if (d2 <= 0.04f && d2 < d8[7]) {
                float dv = d2; int iv = sidx[t];
#pragma unroll
                for (int k = 0; k < 8; k++) {       // static-index bubble insert
                    if (dv < d8[k]) {
                        float td = d8[k]; d8[k] = dv; dv = td;
                        int   ti = i8[k]; i8[k] = iv; iv = ti;
                    }
                }
            }
        }

        // merge: always consume d8[0]; winner shifts its list (static indices)
        for (int r = 0; r < 8; r++) {
            unsigned db = __float_as_uint(fmaxf(d8[0], 0.f));
            unsigned long long key = ((unsigned long long)db << 32)
                                   | ((unsigned)(i8[0] & 0x1FFF) << 5) | (unsigned)lane;
#pragma unroll
            for (int o = 16; o; o >>= 1) {
                unsigned long long other = __shfl_xor_sync(0xffffffffu, key, o);
                key = (other < key) ? other : key;
            }
            bool valid = ((unsigned)(key >> 32)) < 0x7f800000u;
            if (valid && lane == (int)(key & 31u)) {
#pragma unroll
                for (int k = 0; k < 7; k++) { d8[k] = d8[k + 1]; i8[k] = i8[k + 1]; }
                d8[7] = INF; i8[7] = -1;
            }
            if (lane == 0) nidx[qi * 8 + r] = valid ? (int)((key >> 5) & 0x1FFF) : -1;
        }
    }
}

// ================= gather attention =============================================
__device__ __forceinline__ void ld8bf(const __nv_bfloat16* p, float* f) {
    uint4 u = *(const uint4*)p;
    const __nv_bfloat162* h = (const __nv_bfloat162*)&u;
#pragma unroll
    for (int i = 0; i < 4; i++) {
        float2 t = __bfloat1622float2(h[i]);
        f[2 * i] = t.x; f[2 * i + 1] = t.y;
    }
}

__global__ void attn_kernel(const __nv_bfloat16* __restrict__ QKV,
                            const __nv_bfloat16* __restrict__ KV,
                            const int* __restrict__ nidx,
                            __nv_bfloat16* __restrict__ O) {
    const float INF = __int_as_float(0x7f800000);
    int warp = threadIdx.x >> 5, lane = threadIdx.x & 31;
    int q = blockIdx.x * 8 + warp;
    int b = q >> 12;
    const int off8 = lane * 8;
    const __nv_bfloat16* qkv = QKV + (size_t)q * 768;

    float qr[8];
    ld8bf(qkv + off8, qr);

    int rid[8]; int nt = 1;
#pragma unroll
    for (int j = 0; j < 8; j++) {
        rid[j] = nidx[q * 8 + j];
        if (rid[j] >= 0) nt++;
    }
    float sc[9];
#pragma unroll
    for (int j = 0; j < 9; j++) {
        if (j == 0 || j < nt) {
            const __nv_bfloat16* kr = (j == 0)
                ? qkv + 256 + off8
                : KV + ((size_t)b * M_ + rid[j - 1]) * 512 + off8;
            float kf[8];
            ld8bf(kr, kf);
            float s = qr[0] * kf[0] + qr[1] * kf[1] + qr[2] * kf[2] + qr[3] * kf[3]
                    + qr[4] * kf[4] + qr[5] * kf[5] + qr[6] * kf[6] + qr[7] * kf[7];
            s += __shfl_xor_sync(0xffffffffu, s, 1);
            s += __shfl_xor_sync(0xffffffffu, s, 2);
            sc[j] = s * 0.17677669529663687f;
        } else sc[j] = -INF;
    }
    float m = sc[0];
#pragma unroll
    for (int j = 1; j < 9; j++) m = fmaxf(m, sc[j]);
    float w[9], ssum = 0.f;
#pragma unroll
    for (int j = 0; j < 9; j++) {
        w[j] = (j == 0 || j < nt) ? expf(sc[j] - m) : 0.f;
        ssum += w[j];
    }
    float inv = 1.f / ssum;

    float o[8] = {0, 0, 0, 0, 0, 0, 0, 0};
#pragma unroll
    for (int j = 0; j < 9; j++) {
        if (j == 0 || j < nt) {
            const __nv_bfloat16* vr = (j == 0)
                ? qkv + 512 + off8
                : KV + ((size_t)b * M_ + rid[j - 1]) * 512 + 256 + off8;
            float vf[8];
            ld8bf(vr, vf);
            float a = w[j] * inv;
#pragma unroll
            for (int d = 0; d < 8; d++) o[d] += a * vf[d];
        }
    }
    __nv_bfloat162 pk[4];
#pragma unroll
    for (int t = 0; t < 4; t++) pk[t] = __floats2bfloat162_rn(o[2 * t], o[2 * t + 1]);
    *(uint4*)&O[(size_t)q * C_ + off8] = *(uint4*)pk;
}

// ================= residual + LayerNorm (Bv in bf16) ============================
__global__ void ln_res_kernel(const float* __restrict__ A,
                              const __nv_bfloat16* __restrict__ Bv,
                              const float* __restrict__ g,
                              const float* __restrict__ be,
                              const float* __restrict__ addq,
                              float* __restrict__ out,
                              __nv_bfloat16* __restrict__ outb) {
    int warp = threadIdx.x >> 5, lane = threadIdx.x & 31;
    int row = blockIdx.x * 8 + warp;
    size_t off = (size_t)row * C_ + lane * 8;

    float v[8], bvf[8];
    float4 a0 = *(const float4*)&A[off],  a1 = *(const float4*)&A[off + 4];
    ld8bf(&Bv[off], bvf);
    v[0] = a0.x + bvf[0]; v[1] = a0.y + bvf[1]; v[2] = a0.z + bvf[2]; v[3] = a0.w + bvf[3];
    v[4] = a1.x + bvf[4]; v[5] = a1.y + bvf[5]; v[6] = a1.z + bvf[6]; v[7] = a1.w + bvf[7];

    float s = 0.f;
#pragma unroll
    for (int d = 0; d < 8; d++) s += v[d];
#pragma unroll
    for (int o = 16; o; o >>= 1) s += __shfl_xor_sync(0xffffffffu, s, o);
    float mu = s * (1.f / 256.f);
    float s2 = 0.f;
#pragma unroll
    for (int d = 0; d < 8; d++) { float t = v[d] - mu; s2 += t * t; }
#pragma unroll
    for (int o = 16; o; o >>= 1) s2 += __shfl_xor_sync(0xffffffffu, s2, o);
    float is = rsqrtf(s2 * (1.f / 256.f) + 1e-5f);

    float r[8];
#pragma unroll
    for (int d = 0; d < 8; d++) {
        r[d] = (v[d] - mu) * is * g[lane * 8 + d] + be[lane * 8 + d];
        if (addq) r[d] += addq[off + d];
    }
    if (out) {
        *(float4*)&out[off]     = make_float4(r[0], r[1], r[2], r[3]);
        *(float4*)&out[off + 4] = make_float4(r[4], r[5], r[6], r[7]);
    }
    if (outb) {
        __nv_bfloat162 pk[4];
#pragma unroll
        for (int t = 0; t < 4; t++) pk[t] = __floats2bfloat162_rn(r[2 * t], r[2 * t + 1]);
        *(uint4*)&outb[off] = *(uint4*)pk;
    }
}

// ================= launch =======================================================
extern "C" void kernel_launch(void* const* d_in, const int* in_sizes, int n_in,
                              void* d_out, int out_size) {
    (void)in_sizes; (void)n_in; (void)out_size;
    const float* q_xyz   = (const float*)d_in[0];
    const float* q_feat  = (const float*)d_in[1];
    const float* kv_xyz  = (const float*)d_in[2];
    const float* kv_feat = (const float*)d_in[3];
    const unsigned char* kv_pad = (const unsigned char*)d_in[4];
    const float* Wpos  = (const float*)d_in[5];
    const float* bpos  = (const float*)d_in[6];
    const float* Wq    = (const float*)d_in[7];
    const float* bq    = (const float*)d_in[8];
    const float* Wk    = (const float*)d_in[9];
    const float* bk    = (const float*)d_in[10];
    const float* Wv    = (const float*)d_in[11];
    const float* bv    = (const float*)d_in[12];
    const float* Wo    = (const float*)d_in[13];
    const float* bo    = (const float*)d_in[14];
    const float* ln1_g = (const float*)d_in[15];
    const float* ln1_b = (const float*)d_in[16];
    const float* W1    = (const float*)d_in[17];
    const float* b1    = (const float*)d_in[18];
    const float* W2    = (const float*)d_in[19];
    const float* b2    = (const float*)d_in[20];
    const float* ln2_g = (const float*)d_in[21];
    const float* ln2_b = (const float*)d_in[22];
    float* out = (float*)d_out;

    float *Xq, *Y, *bqkv, *bkv;
    __nv_bfloat16 *Xqb, *Xkvb, *QKVq, *KVkv, *Ob, *Tb, *Yb, *Hidb, *WTqkv, *WTkv, *WTo, *WT1, *WT2;
    int* nidx;
    cudaGetSymbolAddress((void**)&Xq,    g_Xq);
    cudaGetSymbolAddress((void**)&Xqb,   g_Xq_b);
    cudaGetSymbolAddress((void**)&Xkvb,  g_Xkv_b);
    cudaGetSymbolAddress((void**)&QKVq,  g_QKVq);
    cudaGetSymbolAddress((void**)&KVkv,  g_KVkv);
    cudaGetSymbolAddress((void**)&Ob,    g_O_b);
    cudaGetSymbolAddress((void**)&Tb,    g_T_b);
    cudaGetSymbolAddress((void**)&Y,     g_Y);
    cudaGetSymbolAddress((void**)&Yb,    g_Y_b);
    cudaGetSymbolAddress((void**)&Hidb,  g_Hid_b);
    cudaGetSymbolAddress((void**)&nidx,  g_nidx);
    cudaGetSymbolAddress((void**)&WTqkv, g_WTqkv);
    cudaGetSymbolAddress((void**)&WTkv,  g_WTkv);
    cudaGetSymbolAddress((void**)&WTo,   g_WTo);
    cudaGetSymbolAddress((void**)&WT1,   g_WT1);
    cudaGetSymbolAddress((void**)&WT2,   g_WT2);
    cudaGetSymbolAddress((void**)&bqkv,  g_bqkv);
    cudaGetSymbolAddress((void**)&bkv,   g_bkv);

    cudaFuncSetAttribute(gemm_hmma<0>, cudaFuncAttributeMaxDynamicSharedMemorySize, GEMM_SMEM);
    cudaFuncSetAttribute(gemm_hmma<1>, cudaFuncAttributeMaxDynamicSharedMemorySize, GEMM_SMEM);
    cudaFuncSetAttribute(gemm_hmma<2>, cudaFuncAttributeMaxDynamicSharedMemorySize, GEMM_SMEM);
    cudaFuncSetAttribute(knn_cell_kernel, cudaFuncAttributeMaxDynamicSharedMemorySize, KNN_SMEM);

    // 0: weight prep + cell zeroing
    prep_weights<<<(PREP_ITEMS + 255) / 256, 256>>>(Wq, Wk, Wv, Wo, W1, W2, bq, bk, bv);
    // 1: bin kv points + queries
    scatter_all<<<(NM_ + NQ_ + 255) / 256, 256>>>(kv_xyz, kv_pad, q_xyz);
    // 2: fused pos-encoding
    posenc_kernel<<<NQ_ + NM_, 256>>>(q_xyz, q_feat, kv_xyz, kv_feat, Wpos, bpos);
    // 3: cell-grouped kNN (register top-8)  <-- profiled slot
    knn_cell_kernel<<<NCELL_, 512, KNN_SMEM>>>(q_xyz, nidx);
    // 4: fused QKV projection
    dim3 gqkv(768 / 128, NQ_ / 128);
    gemm_hmma<2><<<gqkv, 256, GEMM_SMEM>>>(Xqb, WTqkv, bqkv, QKVq, C_, 768);
    // 5: fused KV projection
    dim3 gkv(512 / 128, NM_ / 128);
    gemm_hmma<2><<<gkv, 256, GEMM_SMEM>>>(Xkvb, WTkv, bkv, KVkv, C_, 512);
    // 6: gather attention
    attn_kernel<<<NQ_ / 8, 256>>>(QKVq, KVkv, nidx, Ob);
    // 7-8: output projection (bf16 out) + LN1
    dim3 go(C_ / 128, NQ_ / 128);
    gemm_hmma<2><<<go, 256, GEMM_SMEM>>>(Ob, WTo, bo, Tb, C_, C_);
    ln_res_kernel<<<NQ_ / 8, 256>>>(Xq, Tb, ln1_g, ln1_b, nullptr, Y, Yb);
    // 9-10: FFN
    dim3 gf1(FF_ / 128, NQ_ / 128);
    gemm_hmma<1><<<gf1, 256, GEMM_SMEM>>>(Yb, WT1, b1, Hidb, C_, FF_);
    gemm_hmma<2><<<go, 256, GEMM_SMEM>>>(Hidb, WT2, b2, Tb, FF_, C_);
    // 11: LN2 + residual + q_feat -> d_out
    ln_res_kernel<<<NQ_ / 8, 256>>>(Y, Tb, ln2_g, ln2_b, q_feat, out, nullptr);
}

// round 12
// speedup vs baseline: 1.9691x; 1.1226x over previous
#include <cuda_runtime.h>
#include <cuda_bf16.h>
#include <math.h>
#include <cstdint>

#define B_   4
#define N_   4096
#define M_   8192
#define C_   256
#define K_   8
#define FF_  1024
#define NQ_  (B_ * N_)
#define NM_  (B_ * M_)
#define NCELL_ (B_ * 125)
#define CAP_ 192
#define QCAP_ 128
#define SCAP_ 2400

// ================= scratch ======================================================
__device__ float          g_Xq   [NQ_ * C_];
__device__ __nv_bfloat16  g_Xq_b [NQ_ * C_];
__device__ __nv_bfloat16  g_Xkv_b[NM_ * C_];
__device__ __nv_bfloat16  g_QKVq [NQ_ * 3 * C_];
__device__ __nv_bfloat16  g_KVkv [NM_ * 2 * C_];
__device__ __nv_bfloat16  g_O_b  [NQ_ * C_];
__device__ __nv_bfloat16  g_T_b  [NQ_ * C_];
__device__ float          g_Y    [NQ_ * C_];
__device__ __nv_bfloat16  g_Y_b  [NQ_ * C_];
__device__ __nv_bfloat16  g_Hid_b[NQ_ * FF_];
__device__ int            g_nidx [NQ_ * K_];
__device__ int            g_cnt  [NCELL_];
__device__ int            g_qcnt [NCELL_];
__device__ int            g_qids [NCELL_ * QCAP_];
__device__ float4         g_pts  [NCELL_ * CAP_];
__device__ int            g_pidx [NCELL_ * CAP_];
__device__ __nv_bfloat16  g_WTqkv[3 * C_ * C_];
__device__ __nv_bfloat16  g_WTkv [2 * C_ * C_];
__device__ __nv_bfloat16  g_WTo  [C_ * C_];
__device__ __nv_bfloat16  g_WT1  [FF_ * C_];
__device__ __nv_bfloat16  g_WT2  [C_ * FF_];
__device__ float          g_bqkv [3 * C_];
__device__ float          g_bkv  [2 * C_];

__device__ __forceinline__ uint32_t smem_u32(const void* p) {
    uint32_t a;
    asm("{ .reg .u64 t; cvta.to.shared.u64 t, %1; cvt.u32.u64 %0, t; }" : "=r"(a) : "l"(p));
    return a;
}

// ================= fused weight prep + cell zeroing =============================
__global__ void prep_weights(const float* __restrict__ Wq, const float* __restrict__ Wk,
                             const float* __restrict__ Wv, const float* __restrict__ Wo,
                             const float* __restrict__ W1, const float* __restrict__ W2,
                             const float* __restrict__ bq, const float* __restrict__ bk,
                             const float* __restrict__ bv) {
    int idx = blockIdx.x * 256 + threadIdx.x;
    const int S = C_ * C_;
    const int E0 = 4 * S + 2 * C_ * FF_;
    if (idx < S) {
        int k = idx >> 8, n = idx & 255;
        g_WTqkv[(size_t)n * C_ + k] = __float2bfloat16(Wq[idx]);
    } else if (idx < 2 * S) {
        int j = idx - S; int k = j >> 8, n = j & 255;
        __nv_bfloat16 v = __float2bfloat16(Wk[j]);
        g_WTqkv[(size_t)(C_ + n) * C_ + k] = v;
        g_WTkv [(size_t)n * C_ + k] = v;
    } else if (idx < 3 * S) {
        int j = idx - 2 * S; int k = j >> 8, n = j & 255;
        __nv_bfloat16 v = __float2bfloat16(Wv[j]);
        g_WTqkv[(size_t)(2 * C_ + n) * C_ + k] = v;
        g_WTkv [(size_t)(C_ + n) * C_ + k] = v;
    } else if (idx < 4 * S) {
        int j = idx - 3 * S; int k = j >> 8, n = j & 255;
        g_WTo[(size_t)n * C_ + k] = __float2bfloat16(Wo[j]);
    } else if (idx < 4 * S + C_ * FF_) {
        int j = idx - 4 * S; int k = j >> 10, n = j & 1023;
        g_WT1[(size_t)n * C_ + k] = __float2bfloat16(W1[j]);
    } else if (idx < E0) {
        int j = idx - 4 * S - C_ * FF_; int k = j >> 8, n = j & 255;
        g_WT2[(size_t)n * FF_ + k] = __float2bfloat16(W2[j]);
    } else if (idx < E0 + 768) {
        int j = idx - E0;
        g_bqkv[j] = (j < 256) ? bq[j] : (j < 512 ? bk[j - 256] : bv[j - 512]);
    } else if (idx < E0 + 768 + 512) {
        int j = idx - E0 - 768;
        g_bkv[j] = (j < 256) ? bk[j] : bv[j - 256];
    } else if (idx < E0 + 768 + 512 + NCELL_) {
        g_cnt[idx - E0 - 768 - 512] = 0;
    } else if (idx < E0 + 768 + 512 + 2 * NCELL_) {
        g_qcnt[idx - E0 - 768 - 512 - NCELL_] = 0;
    }
}
#define PREP_ITEMS (4 * C_ * C_ + 2 * C_ * FF_ + 768 + 512 + 2 * NCELL_)

// ================= fused pos-encoding (4 rows per CTA) ==========================
__global__ void posenc_kernel(const float* __restrict__ q_xyz,
                              const float* __restrict__ q_feat,
                              const float* __restrict__ kv_xyz,
                              const float* __restrict__ kv_feat,
                              const float* __restrict__ Wpos,
                              const float* __restrict__ bpos) {
    int base = blockIdx.x * 4;
    int c    = threadIdx.x;
    float w0 = Wpos[c], w1 = Wpos[C_ + c], w2 = Wpos[2 * C_ + c], bp = bpos[c];
#pragma unroll
    for (int r = 0; r < 4; r++) {
        int row = base + r;
        const float* xyz; const float* feat;
        if (row < NQ_) { xyz = q_xyz + row * 3; feat = q_feat + (size_t)row * C_; }
        else { int rr = row - NQ_; xyz = kv_xyz + rr * 3; feat = kv_feat + (size_t)rr * C_; }
        float v = feat[c] + xyz[0] * w0 + xyz[1] * w1 + xyz[2] * w2 + bp;
        if (row < NQ_) {
            g_Xq[(size_t)row * C_ + c] = v;
            g_Xq_b[(size_t)row * C_ + c] = __float2bfloat16(v);
        } else {
            g_Xkv_b[(size_t)(row - NQ_) * C_ + c] = __float2bfloat16(v);
        }
    }
}

// ================= HMMA GEMM: 128x128 tile, 64x32 warp, BK=64, XOR swizzle ======
// MODE 0: fp32 out.  MODE 1: relu+bf16 out.  MODE 2: bf16 out.
#define STG_BYTES (128 * 128)            /* 16384 B per operand per stage */
#define GEMM_SMEM (3 * STG_BYTES * 2)    /* 98304 B */

__device__ __forceinline__ void ldm_x4(uint32_t* r, uint32_t addr) {
    asm volatile("ldmatrix.sync.aligned.m8n8.x4.shared.b16 {%0,%1,%2,%3}, [%4];"
                 : "=r"(r[0]), "=r"(r[1]), "=r"(r[2]), "=r"(r[3]) : "r"(addr));
}
__device__ __forceinline__ void mma_bf16(float* d, const uint32_t* a, const uint32_t* b) {
    asm volatile(
        "mma.sync.aligned.m16n8k16.row.col.f32.bf16.bf16.f32 "
        "{%0,%1,%2,%3}, {%4,%5,%6,%7}, {%8,%9}, {%0,%1,%2,%3};"
        : "+f"(d[0]), "+f"(d[1]), "+f"(d[2]), "+f"(d[3])
        : "r"(a[0]), "r"(a[1]), "r"(a[2]), "r"(a[3]), "r"(b[0]), "r"(b[1]));
}
__device__ __forceinline__ void cp16(uint32_t saddr, const void* gaddr) {
    asm volatile("cp.async.cg.shared.global [%0], [%1], 16;" :: "r"(saddr), "l"(gaddr));
}

template <int MODE>
__global__ __launch_bounds__(256, 2)
void gemm_hmma(const __nv_bfloat16* __restrict__ A,
               const __nv_bfloat16* __restrict__ BT,
               const float* __restrict__ bias,
               void* __restrict__ Out, int K, int N) {
    extern __shared__ char dsm[];
    int tid  = threadIdx.x;
    int wid  = tid >> 5, lane = tid & 31;
    int row0 = blockIdx.y * 128;
    int col0 = blockIdx.x * 128;
    int wm   = (wid & 1) * 64;
    int wn   = (wid >> 1) * 32;

    uint32_t aA = smem_u32(dsm);
    uint32_t aB = aA + 3 * STG_BYTES;

    // per-stage: 128 rows x 64 bf16 = 128 rows x 8 chunks(16B); chunk ^= row&7
    auto issue = [&](int st, int kc0) {
        uint32_t oA = aA + st * STG_BYTES, oB = aB + st * STG_BYTES;
#pragma unroll
        for (int j = 0; j < 4; j++) {
            int idx = tid + j * 256;            // 0..1023
            int row = idx >> 3, s = idx & 7;
            uint32_t soff = row * 128 + ((s ^ (row & 7)) << 4);
            cp16(oA + soff, A  + (size_t)(row0 + row) * K + kc0 + s * 8);
            cp16(oB + soff, BT + (size_t)(col0 + row) * K + kc0 + s * 8);
        }
        asm volatile("cp.async.commit_group;" ::: "memory");
    };

    float acc[4][4][4] = {};
    int nk = K >> 6;

    issue(0, 0);
    issue(1, 64);

    for (int i = 0; i < nk; i++) {
        if (i < nk - 1) asm volatile("cp.async.wait_group 1;" ::: "memory");
        else            asm volatile("cp.async.wait_group 0;" ::: "memory");
        __syncthreads();

        if (i + 2 < nk) issue((i + 2) % 3, (i + 2) << 6);

        uint32_t bAs = aA + (i % 3) * STG_BYTES;
        uint32_t bBs = aB + (i % 3) * STG_BYTES;
#pragma unroll
        for (int ks = 0; ks < 4; ks++) {
            uint32_t afr[4][4];
#pragma unroll
            for (int mt = 0; mt < 4; mt++) {
                uint32_t row = wm + mt * 16 + (lane & 15);
                uint32_t ch  = (uint32_t)(ks * 2) + (lane >> 4);
                ldm_x4(afr[mt], bAs + row * 128 + ((ch ^ (row & 7)) << 4));
            }
            uint32_t bfr[2][4];
#pragma unroll
            for (int np = 0; np < 2; np++) {
                uint32_t row = wn + np * 16 + ((lane >> 4) << 3) + (lane & 7);
                uint32_t ch  = (uint32_t)(ks * 2) + ((lane >> 3) & 1);
                ldm_x4(bfr[np], bBs + row * 128 + ((ch ^ (row & 7)) << 4));
            }
#pragma unroll
            for (int mt = 0; mt < 4; mt++)
#pragma unroll
                for (int nt = 0; nt < 4; nt++)
                    mma_bf16(acc[mt][nt], afr[mt], &bfr[nt >> 1][(nt & 1) * 2]);
        }
    }

    int g  = lane >> 2;
    int t2 = (lane & 3) * 2;
#pragma unroll
    for (int mt = 0; mt < 4; mt++) {
#pragma unroll
        for (int nt = 0; nt < 4; nt++) {
            int row = row0 + wm + mt * 16 + g;
            int col = col0 + wn + nt * 8 + t2;
            float2 b2 = *(const float2*)&bias[col];
            float v0 = acc[mt][nt][0] + b2.x, v1 = acc[mt][nt][1] + b2.y;
            float v2 = acc[mt][nt][2] + b2.x, v3 = acc[mt][nt][3] + b2.y;
            if (MODE == 0) {
                float* op = (float*)Out;
                *(float2*)&op[(size_t)row * N + col]       = make_float2(v0, v1);
                *(float2*)&op[(size_t)(row + 8) * N + col] = make_float2(v2, v3);
            } else {
                if (MODE == 1) {
                    v0 = fmaxf(v0, 0.f); v1 = fmaxf(v1, 0.f);
                    v2 = fmaxf(v2, 0.f); v3 = fmaxf(v3, 0.f);
                }
                __nv_bfloat16* op = (__nv_bfloat16*)Out;
                *(__nv_bfloat162*)&op[(size_t)row * N + col]       = __floats2bfloat162_rn(v0, v1);
                *(__nv_bfloat162*)&op[(size_t)(row + 8) * N + col] = __floats2bfloat162_rn(v2, v3);
            }
        }
    }
}

// ================= binning: kv points AND queries ===============================
__device__ __forceinline__ int cell_of(float x, float y, float z) {
    int cx = min((int)(x * 5.f), 4);
    int cy = min((int)(y * 5.f), 4);
    int cz = min((int)(z * 5.f), 4);
    return (cx * 5 + cy) * 5 + cz;
}

__global__ void scatter_all(const float* __restrict__ kv_xyz,
                            const unsigned char* __restrict__ kv_pad,
                            const float* __restrict__ q_xyz) {
    int i = blockIdx.x * 256 + threadIdx.x;
    if (i < NM_) {
        if (kv_pad[i]) return;
        int b = i >> 13;
        float x = kv_xyz[i * 3], y = kv_xyz[i * 3 + 1], z = kv_xyz[i * 3 + 2];
        int cid = b * 125 + cell_of(x, y, z);
        int pos = atomicAdd(&g_cnt[cid], 1);
        if (pos < CAP_) {
            g_pts[cid * CAP_ + pos] = make_float4(x, y, z, x * x + y * y + z * z);
            g_pidx[cid * CAP_ + pos] = i & 8191;
        }
    } else {
        int qi = i - NM_;
        if (qi >= NQ_) return;
        int b = qi >> 12;
        float x = q_xyz[qi * 3], y = q_xyz[qi * 3 + 1], z = q_xyz[qi * 3 + 2];
        int cid = b * 125 + cell_of(x, y, z);
        int pos = atomicAdd(&g_qcnt[cid], 1);
        if (pos < QCAP_) g_qids[cid * QCAP_ + pos] = qi;
    }
}

// ================= cell-grouped kNN: register-resident top-8 (R11 win) ==========
#define KNN_SMEM (SCAP_ * 20)

__global__ __launch_bounds__(512, 3)
void knn_cell_kernel(const float* __restrict__ q_xyz, int* __restrict__ nidx) {
    const float INF = __int_as_float(0x7f800000);
    int cid = blockIdx.x;
    int nq = min(g_qcnt[cid], QCAP_);
    if (nq == 0) return;
    int b = cid / 125;
    int cc = cid % 125;
    int cx = cc / 25, cy = (cc / 5) % 5, cz = cc % 5;

    extern __shared__ char sm[];
    float4* spts = (float4*)sm;
    int*    sidx = (int*)(sm + SCAP_ * 16);
    __shared__ int s_cells[27], s_offs[28];
    __shared__ int s_nc;

    int tid = threadIdx.x, warp = tid >> 5, lane = tid & 31;

    if (tid == 0) {
        int nc = 0, tot = 0;
        for (int dx = -1; dx <= 1; dx++) {
            int x = cx + dx; if (x < 0 || x > 4) continue;
            for (int dy = -1; dy <= 1; dy++) {
                int y = cy + dy; if (y < 0 || y > 4) continue;
                for (int dz = -1; dz <= 1; dz++) {
                    int z = cz + dz; if (z < 0 || z > 4) continue;
                    int nid = b * 125 + (x * 5 + y) * 5 + z;
                    int c = min(g_cnt[nid], CAP_);
                    if (tot + c > SCAP_) c = SCAP_ - tot;
                    s_cells[nc] = nid;
                    s_offs[nc] = tot;
                    tot += c;
                    nc++;
                }
            }
        }
        s_nc = nc;
        s_offs[nc] = tot;
    }
    __syncthreads();
    int nc = s_nc, tot = s_offs[nc];

    for (int j = 0; j < nc; j++) {
        int nid = s_cells[j], off = s_offs[j], n = s_offs[j + 1] - off;
        for (int t = tid; t < n; t += 512) {
            spts[off + t] = g_pts[nid * CAP_ + t];
            sidx[off + t] = g_pidx[nid * CAP_ + t];
        }
    }
    __syncthreads();

    for (int qj = warp; qj < nq; qj += 16) {
        int qi = g_qids[cid * QCAP_ + qj];
        float qx = q_xyz[qi * 3], qy = q_xyz[qi * 3 + 1], qz = q_xyz[qi * 3 + 2];
        float qn = qx * qx + qy * qy + qz * qz;

        float d8[8]; int i8[8];
#pragma unroll
        for (int i = 0; i < 8; i++) { d8[i] = INF; i8[i] = -1; }

        for (int t = lane; t < tot; t += 32) {
            float4 p = spts[t];
            float d2 = qn + p.w - 2.f * (qx * p.x + qy * p.y + qz * p.z);
            if (d2 <= 0.04f && d2 < d8[7]) {
                float dv = d2; int iv = sidx[t];
#pragma unroll
                for (int k = 0; k < 8; k++) {
                    if (dv < d8[k]) {
                        float td = d8[k]; d8[k] = dv; dv = td;
                        int   ti = i8[k]; i8[k] = iv; iv = ti;
                    }
                }
            }
        }

        for (int r = 0; r < 8; r++) {
            unsigned db = __float_as_uint(fmaxf(d8[0], 0.f));
            unsigned long long key = ((unsigned long long)db << 32)
                                   | ((unsigned)(i8[0] & 0x1FFF) << 5) | (unsigned)lane;
#pragma unroll
            for (int o = 16; o; o >>= 1) {
                unsigned long long other = __shfl_xor_sync(0xffffffffu, key, o);
                key = (other < key) ? other : key;
            }
            bool valid = ((unsigned)(key >> 32)) < 0x7f800000u;
            if (valid && lane == (int)(key & 31u)) {
#pragma unroll
                for (int k = 0; k < 7; k++) { d8[k] = d8[k + 1]; i8[k] = i8[k + 1]; }
                d8[7] = INF; i8[7] = -1;
            }
            if (lane == 0) nidx[qi * 8 + r] = valid ? (int)((key >> 5) & 0x1FFF) : -1;
        }
    }
}

// ================= gather attention =============================================
__device__ __forceinline__ void ld8bf(const __nv_bfloat16* p, float* f) {
    uint4 u = *(const uint4*)p;
    const __nv_bfloat162* h = (const __nv_bfloat162*)&u;
#pragma unroll
    for (int i = 0; i < 4; i++) {
        float2 t = __bfloat1622float2(h[i]);
        f[2 * i] = t.x; f[2 * i + 1] = t.y;
    }
}

__global__ void attn_kernel(const __nv_bfloat16* __restrict__ QKV,
                            const __nv_bfloat16* __restrict__ KV,
                            const int* __restrict__ nidx,
                            __nv_bfloat16* __restrict__ O) {
    const float INF = __int_as_float(0x7f800000);
    int warp = threadIdx.x >> 5, lane = threadIdx.x & 31;
    int q = blockIdx.x * 8 + warp;
    int b = q >> 12;
    const int off8 = lane * 8;
    const __nv_bfloat16* qkv = QKV + (size_t)q * 768;

    float qr[8];
    ld8bf(qkv + off8, qr);

    int rid[8]; int nt = 1;
#pragma unroll
    for (int j = 0; j < 8; j++) {
        rid[j] = nidx[q * 8 + j];
        if (rid[j] >= 0) nt++;
    }
    float sc[9];
#pragma unroll
    for (int j = 0; j < 9; j++) {
        if (j == 0 || j < nt) {
            const __nv_bfloat16* kr = (j == 0)
                ? qkv + 256 + off8
                : KV + ((size_t)b * M_ + rid[j - 1]) * 512 + off8;
            float kf[8];
            ld8bf(kr, kf);
            float s = qr[0] * kf[0] + qr[1] * kf[1] + qr[2] * kf[2] + qr[3] * kf[3]
                    + qr[4] * kf[4] + qr[5] * kf[5] + qr[6] * kf[6] + qr[7] * kf[7];
            s += __shfl_xor_sync(0xffffffffu, s, 1);
            s += __shfl_xor_sync(0xffffffffu, s, 2);
            sc[j] = s * 0.17677669529663687f;
        } else sc[j] = -INF;
    }
    float m = sc[0];
#pragma unroll
    for (int j = 1; j < 9; j++) m = fmaxf(m, sc[j]);
    float w[9], ssum = 0.f;
#pragma unroll
    for (int j = 0; j < 9; j++) {
        w[j] = (j == 0 || j < nt) ? expf(sc[j] - m) : 0.f;
        ssum += w[j];
    }
    float inv = 1.f / ssum;

    float o[8] = {0, 0, 0, 0, 0, 0, 0, 0};
#pragma unroll
    for (int j = 0; j < 9; j++) {
        if (j == 0 || j < nt) {
            const __nv_bfloat16* vr = (j == 0)
                ? qkv + 512 + off8
                : KV + ((size_t)b * M_ + rid[j - 1]) * 512 + 256 + off8;
            float vf[8];
            ld8bf(vr, vf);
            float a = w[j] * inv;
#pragma unroll
            for (int d = 0; d < 8; d++) o[d] += a * vf[d];
        }
    }
    __nv_bfloat162 pk[4];
#pragma unroll
    for (int t = 0; t < 4; t++) pk[t] = __floats2bfloat162_rn(o[2 * t], o[2 * t + 1]);
    *(uint4*)&O[(size_t)q * C_ + off8] = *(uint4*)pk;
}

// ================= residual + LayerNorm (Bv in bf16) ============================
__global__ void ln_res_kernel(const float* __restrict__ A,
                              const __nv_bfloat16* __restrict__ Bv,
                              const float* __restrict__ g,
                              const float* __restrict__ be,
                              const float* __restrict__ addq,
                              float* __restrict__ out,
                              __nv_bfloat16* __restrict__ outb) {
    int warp = threadIdx.x >> 5, lane = threadIdx.x & 31;
    int row = blockIdx.x * 8 + warp;
    size_t off = (size_t)row * C_ + lane * 8;

    float v[8], bvf[8];
    float4 a0 = *(const float4*)&A[off],  a1 = *(const float4*)&A[off + 4];
    ld8bf(&Bv[off], bvf);
    v[0] = a0.x + bvf[0]; v[1] = a0.y + bvf[1]; v[2] = a0.z + bvf[2]; v[3] = a0.w + bvf[3];
    v[4] = a1.x + bvf[4]; v[5] = a1.y + bvf[5]; v[6] = a1.z + bvf[6]; v[7] = a1.w + bvf[7];

    float s = 0.f;
#pragma unroll
    for (int d = 0; d < 8; d++) s += v[d];
#pragma unroll
    for (int o = 16; o; o >>= 1) s += __shfl_xor_sync(0xffffffffu, s, o);
    float mu = s * (1.f / 256.f);
    float s2 = 0.f;
#pragma unroll
    for (int d = 0; d < 8; d++) { float t = v[d] - mu; s2 += t * t; }
#pragma unroll
    for (int o = 16; o; o >>= 1) s2 += __shfl_xor_sync(0xffffffffu, s2, o);
    float is = rsqrtf(s2 * (1.f / 256.f) + 1e-5f);

    float r[8];
#pragma unroll
    for (int d = 0; d < 8; d++) {
        r[d] = (v[d] - mu) * is * g[lane * 8 + d] + be[lane * 8 + d];
        if (addq) r[d] += addq[off + d];
    }
    if (out) {
        *(float4*)&out[off]     = make_float4(r[0], r[1], r[2], r[3]);
        *(float4*)&out[off + 4] = make_float4(r[4], r[5], r[6], r[7]);
    }
    if (outb) {
        __nv_bfloat162 pk[4];
#pragma unroll
        for (int t = 0; t < 4; t++) pk[t] = __floats2bfloat162_rn(r[2 * t], r[2 * t + 1]);
        *(uint4*)&outb[off] = *(uint4*)pk;
    }
}

// ================= launch =======================================================
extern "C" void kernel_launch(void* const* d_in, const int* in_sizes, int n_in,
                              void* d_out, int out_size) {
    (void)in_sizes; (void)n_in; (void)out_size;
    const float* q_xyz   = (const float*)d_in[0];
    const float* q_feat  = (const float*)d_in[1];
    const float* kv_xyz  = (const float*)d_in[2];
    const float* kv_feat = (const float*)d_in[3];
    const unsigned char* kv_pad = (const unsigned char*)d_in[4];
    const float* Wpos  = (const float*)d_in[5];
    const float* bpos  = (const float*)d_in[6];
    const float* Wq    = (const float*)d_in[7];
    const float* bq    = (const float*)d_in[8];
    const float* Wk    = (const float*)d_in[9];
    const float* bk    = (const float*)d_in[10];
    const float* Wv    = (const float*)d_in[11];
    const float* bv    = (const float*)d_in[12];
    const float* Wo    = (const float*)d_in[13];
    const float* bo    = (const float*)d_in[14];
    const float* ln1_g = (const float*)d_in[15];
    const float* ln1_b = (const float*)d_in[16];
    const float* W1    = (const float*)d_in[17];
    const float* b1    = (const float*)d_in[18];
    const float* W2    = (const float*)d_in[19];
    const float* b2    = (const float*)d_in[20];
    const float* ln2_g = (const float*)d_in[21];
    const float* ln2_b = (const float*)d_in[22];
    float* out = (float*)d_out;

    float *Xq, *Y, *bqkv, *bkv;
    __nv_bfloat16 *Xqb, *Xkvb, *QKVq, *KVkv, *Ob, *Tb, *Yb, *Hidb, *WTqkv, *WTkv, *WTo, *WT1, *WT2;
    int* nidx;
    cudaGetSymbolAddress((void**)&Xq,    g_Xq);
    cudaGetSymbolAddress((void**)&Xqb,   g_Xq_b);
    cudaGetSymbolAddress((void**)&Xkvb,  g_Xkv_b);
    cudaGetSymbolAddress((void**)&QKVq,  g_QKVq);
    cudaGetSymbolAddress((void**)&KVkv,  g_KVkv);
    cudaGetSymbolAddress((void**)&Ob,    g_O_b);
    cudaGetSymbolAddress((void**)&Tb,    g_T_b);
    cudaGetSymbolAddress((void**)&Y,     g_Y);
    cudaGetSymbolAddress((void**)&Yb,    g_Y_b);
    cudaGetSymbolAddress((void**)&Hidb,  g_Hid_b);
    cudaGetSymbolAddress((void**)&nidx,  g_nidx);
    cudaGetSymbolAddress((void**)&WTqkv, g_WTqkv);
    cudaGetSymbolAddress((void**)&WTkv,  g_WTkv);
    cudaGetSymbolAddress((void**)&WTo,   g_WTo);
    cudaGetSymbolAddress((void**)&WT1,   g_WT1);
    cudaGetSymbolAddress((void**)&WT2,   g_WT2);
    cudaGetSymbolAddress((void**)&bqkv,  g_bqkv);
    cudaGetSymbolAddress((void**)&bkv,   g_bkv);

    cudaFuncSetAttribute(gemm_hmma<0>, cudaFuncAttributeMaxDynamicSharedMemorySize, GEMM_SMEM);
    cudaFuncSetAttribute(gemm_hmma<1>, cudaFuncAttributeMaxDynamicSharedMemorySize, GEMM_SMEM);
    cudaFuncSetAttribute(gemm_hmma<2>, cudaFuncAttributeMaxDynamicSharedMemorySize, GEMM_SMEM);
    cudaFuncSetAttribute(knn_cell_kernel, cudaFuncAttributeMaxDynamicSharedMemorySize, KNN_SMEM);

    // 0: weight prep + cell zeroing
    prep_weights<<<(PREP_ITEMS + 255) / 256, 256>>>(Wq, Wk, Wv, Wo, W1, W2, bq, bk, bv);
    // 1: bin kv points + queries
    scatter_all<<<(NM_ + NQ_ + 255) / 256, 256>>>(kv_xyz, kv_pad, q_xyz);
    // 2: fused pos-encoding (4 rows/CTA)
    posenc_kernel<<<(NQ_ + NM_) / 4, 256>>>(q_xyz, q_feat, kv_xyz, kv_feat, Wpos, bpos);
    // 3: fused QKV projection  <-- profiled slot (verify BK=64)
    dim3 gqkv(768 / 128, NQ_ / 128);
    gemm_hmma<2><<<gqkv, 256, GEMM_SMEM>>>(Xqb, WTqkv, bqkv, QKVq, C_, 768);
    // 4: fused KV projection
    dim3 gkv(512 / 128, NM_ / 128);
    gemm_hmma<2><<<gkv, 256, GEMM_SMEM>>>(Xkvb, WTkv, bkv, KVkv, C_, 512);
    // 5: cell-grouped kNN
    knn_cell_kernel<<<NCELL_, 512, KNN_SMEM>>>(q_xyz, nidx);
    // 6: gather attention
    attn_kernel<<<NQ_ / 8, 256>>>(QKVq, KVkv, nidx, Ob);
    // 7-8: output projection (bf16 out) + LN1
    dim3 go(C_ / 128, NQ_ / 128);
    gemm_hmma<2><<<go, 256, GEMM_SMEM>>>(Ob, WTo, bo, Tb, C_, C_);
    ln_res_kernel<<<NQ_ / 8, 256>>>(Xq, Tb, ln1_g, ln1_b, nullptr, Y, Yb);
    // 9-10: FFN
    dim3 gf1(FF_ / 128, NQ_ / 128);
    gemm_hmma<1><<<gf1, 256, GEMM_SMEM>>>(Yb, WT1, b1, Hidb, C_, FF_);
    gemm_hmma<2><<<go, 256, GEMM_SMEM>>>(Hidb, WT2, b2, Tb, FF_, C_);
    // 11: LN2 + residual + q_feat -> d_out
    ln_res_kernel<<<NQ_ / 8, 256>>>(Y, Tb, ln2_g, ln2_b, q_feat, out, nullptr);
}

// round 13
// speedup vs baseline: 1.9698x; 1.0004x over previous
#include <cuda_runtime.h>
#include <cuda_bf16.h>
#include <math.h>
#include <cstdint>

#define B_   4
#define N_   4096
#define M_   8192
#define C_   256
#define K_   8
#define FF_  1024
#define NQ_  (B_ * N_)
#define NM_  (B_ * M_)
#define NCELL_ (B_ * 125)
#define CAP_ 192
#define QCAP_ 128
#define SCAP_ 2400
#define WBUF_ 448   /* per-warp in-radius buffer; Poisson(274), 10+ sigma margin */

// ================= scratch ======================================================
__device__ float          g_Xq   [NQ_ * C_];
__device__ __nv_bfloat16  g_Xq_b [NQ_ * C_];
__device__ __nv_bfloat16  g_Xkv_b[NM_ * C_];
__device__ __nv_bfloat16  g_QKVq [NQ_ * 3 * C_];
__device__ __nv_bfloat16  g_KVkv [NM_ * 2 * C_];
__device__ __nv_bfloat16  g_O_b  [NQ_ * C_];
__device__ __nv_bfloat16  g_T_b  [NQ_ * C_];
__device__ float          g_Y    [NQ_ * C_];
__device__ __nv_bfloat16  g_Y_b  [NQ_ * C_];
__device__ __nv_bfloat16  g_Hid_b[NQ_ * FF_];
__device__ int            g_nidx [NQ_ * K_];
__device__ int            g_cnt  [NCELL_];
__device__ int            g_qcnt [NCELL_];
__device__ int            g_qids [NCELL_ * QCAP_];
__device__ float4         g_pts  [NCELL_ * CAP_];
__device__ int            g_pidx [NCELL_ * CAP_];
__device__ __nv_bfloat16  g_WTqkv[3 * C_ * C_];
__device__ __nv_bfloat16  g_WTkv [2 * C_ * C_];
__device__ __nv_bfloat16  g_WTo  [C_ * C_];
__device__ __nv_bfloat16  g_WT1  [FF_ * C_];
__device__ __nv_bfloat16  g_WT2  [C_ * FF_];
__device__ float          g_bqkv [3 * C_];
__device__ float          g_bkv  [2 * C_];

__device__ __forceinline__ uint32_t smem_u32(const void* p) {
    uint32_t a;
    asm("{ .reg .u64 t; cvta.to.shared.u64 t, %1; cvt.u32.u64 %0, t; }" : "=r"(a) : "l"(p));
    return a;
}

// ================= fused weight prep + cell zeroing =============================
__global__ void prep_weights(const float* __restrict__ Wq, const float* __restrict__ Wk,
                             const float* __restrict__ Wv, const float* __restrict__ Wo,
                             const float* __restrict__ W1, const float* __restrict__ W2,
                             const float* __restrict__ bq, const float* __restrict__ bk,
                             const float* __restrict__ bv) {
    int idx = blockIdx.x * 256 + threadIdx.x;
    const int S = C_ * C_;
    const int E0 = 4 * S + 2 * C_ * FF_;
    if (idx < S) {
        int k = idx >> 8, n = idx & 255;
        g_WTqkv[(size_t)n * C_ + k] = __float2bfloat16(Wq[idx]);
    } else if (idx < 2 * S) {
        int j = idx - S; int k = j >> 8, n = j & 255;
        __nv_bfloat16 v = __float2bfloat16(Wk[j]);
        g_WTqkv[(size_t)(C_ + n) * C_ + k] = v;
        g_WTkv [(size_t)n * C_ + k] = v;
    } else if (idx < 3 * S) {
        int j = idx - 2 * S; int k = j >> 8, n = j & 255;
        __nv_bfloat16 v = __float2bfloat16(Wv[j]);
        g_WTqkv[(size_t)(2 * C_ + n) * C_ + k] = v;
        g_WTkv [(size_t)(C_ + n) * C_ + k] = v;
    } else if (idx < 4 * S) {
        int j = idx - 3 * S; int k = j >> 8, n = j & 255;
        g_WTo[(size_t)n * C_ + k] = __float2bfloat16(Wo[j]);
    } else if (idx < 4 * S + C_ * FF_) {
        int j = idx - 4 * S; int k = j >> 10, n = j & 1023;
        g_WT1[(size_t)n * C_ + k] = __float2bfloat16(W1[j]);
    } else if (idx < E0) {
        int j = idx - 4 * S - C_ * FF_; int k = j >> 8, n = j & 255;
        g_WT2[(size_t)n * FF_ + k] = __float2bfloat16(W2[j]);
    } else if (idx < E0 + 768) {
        int j = idx - E0;
        g_bqkv[j] = (j < 256) ? bq[j] : (j < 512 ? bk[j - 256] : bv[j - 512]);
    } else if (idx < E0 + 768 + 512) {
        int j = idx - E0 - 768;
        g_bkv[j] = (j < 256) ? bk[j] : bv[j - 256];
    } else if (idx < E0 + 768 + 512 + NCELL_) {
        g_cnt[idx - E0 - 768 - 512] = 0;
    } else if (idx < E0 + 768 + 512 + 2 * NCELL_) {
        g_qcnt[idx - E0 - 768 - 512 - NCELL_] = 0;
    }
}
#define PREP_ITEMS (4 * C_ * C_ + 2 * C_ * FF_ + 768 + 512 + 2 * NCELL_)

// ================= cell index helper ============================================
__device__ __forceinline__ int cell_of(float x, float y, float z) {
    int cx = min((int)(x * 5.f), 4);
    int cy = min((int)(y * 5.f), 4);
    int cz = min((int)(z * 5.f), 4);
    return (cx * 5 + cy) * 5 + cz;
}

// ================= fused pos-encoding + binning (4 rows per CTA) ================
__global__ void posenc_kernel(const float* __restrict__ q_xyz,
                              const float* __restrict__ q_feat,
                              const float* __restrict__ kv_xyz,
                              const float* __restrict__ kv_feat,
                              const unsigned char* __restrict__ kv_pad,
                              const float* __restrict__ Wpos,
                              const float* __restrict__ bpos) {
    int base = blockIdx.x * 4;
    int c    = threadIdx.x;
    float w0 = Wpos[c], w1 = Wpos[C_ + c], w2 = Wpos[2 * C_ + c], bp = bpos[c];
#pragma unroll
    for (int r = 0; r < 4; r++) {
        int row = base + r;
        const float* xyz; const float* feat;
        if (row < NQ_) { xyz = q_xyz + row * 3; feat = q_feat + (size_t)row * C_; }
        else { int rr = row - NQ_; xyz = kv_xyz + rr * 3; feat = kv_feat + (size_t)rr * C_; }
        float v = feat[c] + xyz[0] * w0 + xyz[1] * w1 + xyz[2] * w2 + bp;
        if (row < NQ_) {
            g_Xq[(size_t)row * C_ + c] = v;
            g_Xq_b[(size_t)row * C_ + c] = __float2bfloat16(v);
        } else {
            g_Xkv_b[(size_t)(row - NQ_) * C_ + c] = __float2bfloat16(v);
        }
    }
    // binning for these 4 rows (threads 0..3)
    if (c < 4) {
        int row = base + c;
        if (row < NQ_) {
            int qi = row, b = qi >> 12;
            float x = q_xyz[qi * 3], y = q_xyz[qi * 3 + 1], z = q_xyz[qi * 3 + 2];
            int cid = b * 125 + cell_of(x, y, z);
            int pos = atomicAdd(&g_qcnt[cid], 1);
            if (pos < QCAP_) g_qids[cid * QCAP_ + pos] = qi;
        } else {
            int i = row - NQ_;
            if (!kv_pad[i]) {
                int b = i >> 13;
                float x = kv_xyz[i * 3], y = kv_xyz[i * 3 + 1], z = kv_xyz[i * 3 + 2];
                int cid = b * 125 + cell_of(x, y, z);
                int pos = atomicAdd(&g_cnt[cid], 1);
                if (pos < CAP_) {
                    g_pts[cid * CAP_ + pos] = make_float4(x, y, z, x * x + y * y + z * z);
                    g_pidx[cid * CAP_ + pos] = i & 8191;
                }
            }
        }
    }
}

// ================= HMMA GEMM: 128x128 tile, 64x32 warp, BK=64, XOR swizzle ======
#define STG_BYTES (128 * 128)
#define GEMM_SMEM (3 * STG_BYTES * 2)

__device__ __forceinline__ void ldm_x4(uint32_t* r, uint32_t addr) {
    asm volatile("ldmatrix.sync.aligned.m8n8.x4.shared.b16 {%0,%1,%2,%3}, [%4];"
                 : "=r"(r[0]), "=r"(r[1]), "=r"(r[2]), "=r"(r[3]) : "r"(addr));
}
__device__ __forceinline__ void mma_bf16(float* d, const uint32_t* a, const uint32_t* b) {
    asm volatile(
        "mma.sync.aligned.m16n8k16.row.col.f32.bf16.bf16.f32 "
        "{%0,%1,%2,%3}, {%4,%5,%6,%7}, {%8,%9}, {%0,%1,%2,%3};"
        : "+f"(d[0]), "+f"(d[1]), "+f"(d[2]), "+f"(d[3])
        : "r"(a[0]), "r"(a[1]), "r"(a[2]), "r"(a[3]), "r"(b[0]), "r"(b[1]));
}
__device__ __forceinline__ void cp16(uint32_t saddr, const void* gaddr) {
    asm volatile("cp.async.cg.shared.global [%0], [%1], 16;" :: "r"(saddr), "l"(gaddr));
}

template <int MODE>
__global__ __launch_bounds__(256, 2)
void gemm_hmma(const __nv_bfloat16* __restrict__ A,
               const __nv_bfloat16* __restrict__ BT,
               const float* __restrict__ bias,
               void* __restrict__ Out, int K, int N) {
    extern __shared__ char dsm[];
    int tid  = threadIdx.x;
    int wid  = tid >> 5, lane = tid & 31;
    int row0 = blockIdx.y * 128;
    int col0 = blockIdx.x * 128;
    int wm   = (wid & 1) * 64;
    int wn   = (wid >> 1) * 32;

    uint32_t aA = smem_u32(dsm);
    uint32_t aB = aA + 3 * STG_BYTES;

    auto issue = [&](int st, int kc0) {
        uint32_t oA = aA + st * STG_BYTES, oB = aB + st * STG_BYTES;
#pragma unroll
        for (int j = 0; j < 4; j++) {
            int idx = tid + j * 256;
            int row = idx >> 3, s = idx & 7;
            uint32_t soff = row * 128 + ((s ^ (row & 7)) << 4);
            cp16(oA + soff, A  + (size_t)(row0 + row) * K + kc0 + s * 8);
            cp16(oB + soff, BT + (size_t)(col0 + row) * K + kc0 + s * 8);
        }
        asm volatile("cp.async.commit_group;" ::: "memory");
    };

    float acc[4][4][4] = {};
    int nk = K >> 6;

    issue(0, 0);
    issue(1, 64);

    for (int i = 0; i < nk; i++) {
        if (i < nk - 1) asm volatile("cp.async.wait_group 1;" ::: "memory");
        else            asm volatile("cp.async.wait_group 0;" ::: "memory");
        __syncthreads();

        if (i + 2 < nk) issue((i + 2) % 3, (i + 2) << 6);

        uint32_t bAs = aA + (i % 3) * STG_BYTES;
        uint32_t bBs = aB + (i % 3) * STG_BYTES;
#pragma unroll
        for (int ks = 0; ks < 4; ks++) {
            uint32_t afr[4][4];
#pragma unroll
            for (int mt = 0; mt < 4; mt++) {
                uint32_t row = wm + mt * 16 + (lane & 15);
                uint32_t ch  = (uint32_t)(ks * 2) + (lane >> 4);
                ldm_x4(afr[mt], bAs + row * 128 + ((ch ^ (row & 7)) << 4));
            }
            uint32_t bfr[2][4];
#pragma unroll
            for (int np = 0; np < 2; np++) {
                uint32_t row = wn + np * 16 + ((lane >> 4) << 3) + (lane & 7);
                uint32_t ch  = (uint32_t)(ks * 2) + ((lane >> 3) & 1);
                ldm_x4(bfr[np], bBs + row * 128 + ((ch ^ (row & 7)) << 4));
            }
#pragma unroll
            for (int mt = 0; mt < 4; mt++)
#pragma unroll
                for (int nt = 0; nt < 4; nt++)
                    mma_bf16(acc[mt][nt], afr[mt], &bfr[nt >> 1][(nt & 1) * 2]);
        }
    }

    int g  = lane >> 2;
    int t2 = (lane & 3) * 2;
#pragma unroll
    for (int mt = 0; mt < 4; mt++) {
#pragma unroll
        for (int nt = 0; nt < 4; nt++) {
            int row = row0 + wm + mt * 16 + g;
            int col = col0 + wn + nt * 8 + t2;
            float2 b2 = *(const float2*)&bias[col];
            float v0 = acc[mt][nt][0] + b2.x, v1 = acc[mt][nt][1] + b2.y;
            float v2 = acc[mt][nt][2] + b2.x, v3 = acc[mt][nt][3] + b2.y;
            if (MODE == 0) {
                float* op = (float*)Out;
                *(float2*)&op[(size_t)row * N + col]       = make_float2(v0, v1);
                *(float2*)&op[(size_t)(row + 8) * N + col] = make_float2(v2, v3);
            } else {
                if (MODE == 1) {
                    v0 = fmaxf(v0, 0.f); v1 = fmaxf(v1, 0.f);
                    v2 = fmaxf(v2, 0.f); v3 = fmaxf(v3, 0.f);
                }
                __nv_bfloat16* op = (__nv_bfloat16*)Out;
                *(__nv_bfloat162*)&op[(size_t)row * N + col]       = __floats2bfloat162_rn(v0, v1);
                *(__nv_bfloat162*)&op[(size_t)(row + 8) * N + col] = __floats2bfloat162_rn(v2, v3);
            }
        }
    }
}

// ================= cell-grouped kNN: two-pass (compact then select) =============
#define KNN_SMEM (SCAP_ * 20 + 16 * WBUF_ * 8)

__global__ __launch_bounds__(512, 2)
void knn_cell_kernel(const float* __restrict__ q_xyz, int* __restrict__ nidx) {
    const float INF = __int_as_float(0x7f800000);
    int cid = blockIdx.x;
    int nq = min(g_qcnt[cid], QCAP_);
    if (nq == 0) return;
    int b = cid / 125;
    int cc = cid % 125;
    int cx = cc / 25, cy = (cc / 5) % 5, cz = cc % 5;

    extern __shared__ char sm[];
    float4* spts = (float4*)sm;
    int*    sidx = (int*)(sm + SCAP_ * 16);
    __shared__ int s_cells[27], s_offs[28];
    __shared__ int s_nc;

    int tid = threadIdx.x, warp = tid >> 5, lane = tid & 31;
    float2* wbuf = (float2*)(sm + SCAP_ * 20) + warp * WBUF_;

    if (tid == 0) {
        int nc = 0, tot = 0;
        for (int dx = -1; dx <= 1; dx++) {
            int x = cx + dx; if (x < 0 || x > 4) continue;
            for (int dy = -1; dy <= 1; dy++) {
                int y = cy + dy; if (y < 0 || y > 4) continue;
                for (int dz = -1; dz <= 1; dz++) {
                    int z = cz + dz; if (z < 0 || z > 4) continue;
                    int nid = b * 125 + (x * 5 + y) * 5 + z;
                    int c = min(g_cnt[nid], CAP_);
                    if (tot + c > SCAP_) c = SCAP_ - tot;
                    s_cells[nc] = nid;
                    s_offs[nc] = tot;
                    tot += c;
                    nc++;
                }
            }
        }
        s_nc = nc;
        s_offs[nc] = tot;
    }
    __syncthreads();
    int nc = s_nc, tot = s_offs[nc];

    for (int j = 0; j < nc; j++) {
        int nid = s_cells[j], off = s_offs[j], n = s_offs[j + 1] - off;
        for (int t = tid; t < n; t += 512) {
            spts[off + t] = g_pts[nid * CAP_ + t];
            sidx[off + t] = g_pidx[nid * CAP_ + t];
        }
    }
    __syncthreads();

    int nb = (tot + 31) >> 5;
    for (int qj = warp; qj < nq; qj += 16) {
        int qi = g_qids[cid * QCAP_ + qj];
        float qx = q_xyz[qi * 3], qy = q_xyz[qi * 3 + 1], qz = q_xyz[qi * 3 + 2];
        float qn = qx * qx + qy * qy + qz * qz;

        // ---- pass 1: ballot-compact in-radius candidates into per-warp buffer --
        int cnt = 0;
        for (int bt = 0; bt < nb; bt++) {
            int t = (bt << 5) + lane;
            bool pass = false;
            float d2 = 0.f; int iv = 0;
            if (t < tot) {
                float4 p = spts[t];
                d2 = qn + p.w - 2.f * (qx * p.x + qy * p.y + qz * p.z);
                pass = (d2 <= 0.04f);
                iv = sidx[t];
            }
            unsigned mask = __ballot_sync(0xffffffffu, pass);
            if (pass) {
                int pos = cnt + __popc(mask & ((1u << lane) - 1u));
                if (pos < WBUF_) wbuf[pos] = make_float2(d2, __int_as_float(iv));
            }
            cnt += __popc(mask);
        }
        if (cnt > WBUF_) cnt = WBUF_;
        __syncwarp();

        // ---- pass 2: per-lane sorted top-8 over compacted survivors ------------
        float d8[8]; int i8[8];
#pragma unroll
        for (int i = 0; i < 8; i++) { d8[i] = INF; i8[i] = -1; }
        for (int t = lane; t < cnt; t += 32) {
            float2 e = wbuf[t];
            float dv = e.x;
            if (dv < d8[7]) {
                int iv = __float_as_int(e.y);
#pragma unroll
                for (int k = 0; k < 8; k++) {
                    if (dv < d8[k]) {
                        float td = d8[k]; d8[k] = dv; dv = td;
                        int   ti = i8[k]; i8[k] = iv; iv = ti;
                    }
                }
            }
        }

        // ---- merge: consume d8[0], winner shifts (static indices) --------------
        for (int r = 0; r < 8; r++) {
            unsigned db = __float_as_uint(fmaxf(d8[0], 0.f));
            unsigned long long key = ((unsigned long long)db << 32)
                                   | ((unsigned)(i8[0] & 0x1FFF) << 5) | (unsigned)lane;
#pragma unroll
            for (int o = 16; o; o >>= 1) {
                unsigned long long other = __shfl_xor_sync(0xffffffffu, key, o);
                key = (other < key) ? other : key;
            }
            bool valid = ((unsigned)(key >> 32)) < 0x7f800000u;
            if (valid && lane == (int)(key & 31u)) {
#pragma unroll
                for (int k = 0; k < 7; k++) { d8[k] = d8[k + 1]; i8[k] = i8[k + 1]; }
                d8[7] = INF; i8[7] = -1;
            }
            if (lane == 0) nidx[qi * 8 + r] = valid ? (int)((key >> 5) & 0x1FFF) : -1;
        }
        __syncwarp();
    }
}

// ================= gather attention =============================================
__device__ __forceinline__ void ld8bf(const __nv_bfloat16* p, float* f) {
    uint4 u = *(const uint4*)p;
    const __nv_bfloat162* h = (const __nv_bfloat162*)&u;
#pragma unroll
    for (int i = 0; i < 4; i++) {
        float2 t = __bfloat1622float2(h[i]);
        f[2 * i] = t.x; f[2 * i + 1] = t.y;
    }
}

__global__ void attn_kernel(const __nv_bfloat16* __restrict__ QKV,
                            const __nv_bfloat16* __restrict__ KV,
                            const int* __restrict__ nidx,
                            __nv_bfloat16* __restrict__ O) {
    const float INF = __int_as_float(0x7f800000);
    int warp = threadIdx.x >> 5, lane = threadIdx.x & 31;
    int q = blockIdx.x * 8 + warp;
    int b = q >> 12;
    const int off8 = lane * 8;
    const __nv_bfloat16* qkv = QKV + (size_t)q * 768;

    float qr[8];
    ld8bf(qkv + off8, qr);

    int rid[8]; int nt = 1;
#pragma unroll
    for (int j = 0; j < 8; j++) {
        rid[j] = nidx[q * 8 + j];
        if (rid[j] >= 0) nt++;
    }
    float sc[9];
#pragma unroll
    for (int j = 0; j < 9; j++) {
        if (j == 0 || j < nt) {
            const __nv_bfloat16* kr = (j == 0)
                ? qkv + 256 + off8
                : KV + ((size_t)b * M_ + rid[j - 1]) * 512 + off8;
            float kf[8];
            ld8bf(kr, kf);
            float s = qr[0] * kf[0] + qr[1] * kf[1] + qr[2] * kf[2] + qr[3] * kf[3]
                    + qr[4] * kf[4] + qr[5] * kf[5] + qr[6] * kf[6] + qr[7] * kf[7];
            s += __shfl_xor_sync(0xffffffffu, s, 1);
            s += __shfl_xor_sync(0xffffffffu, s, 2);
            sc[j] = s * 0.17677669529663687f;
        } else sc[j] = -INF;
    }
    float m = sc[0];
#pragma unroll
    for (int j = 1; j < 9; j++) m = fmaxf(m, sc[j]);
    float w[9], ssum = 0.f;
#pragma unroll
    for (int j = 0; j < 9; j++) {
        w[j] = (j == 0 || j < nt) ? expf(sc[j] - m) : 0.f;
        ssum += w[j];
    }
    float inv = 1.f / ssum;

    float o[8] = {0, 0, 0, 0, 0, 0, 0, 0};
#pragma unroll
    for (int j = 0; j < 9; j++) {
        if (j == 0 || j < nt) {
            const __nv_bfloat16* vr = (j == 0)
                ? qkv + 512 + off8
                : KV + ((size_t)b * M_ + rid[j - 1]) * 512 + 256 + off8;
            float vf[8];
            ld8bf(vr, vf);
            float a = w[j] * inv;
#pragma unroll
            for (int d = 0; d < 8; d++) o[d] += a * vf[d];
        }
    }
    __nv_bfloat162 pk[4];
#pragma unroll
    for (int t = 0; t < 4; t++) pk[t] = __floats2bfloat162_rn(o[2 * t], o[2 * t + 1]);
    *(uint4*)&O[(size_t)q * C_ + off8] = *(uint4*)pk;
}

// ================= residual + LayerNorm (Bv in bf16) ============================
__global__ void ln_res_kernel(const float* __restrict__ A,
                              const __nv_bfloat16* __restrict__ Bv,
                              const float* __restrict__ g,
                              const float* __restrict__ be,
                              const float* __restrict__ addq,
                              float* __restrict__ out,
                              __nv_bfloat16* __restrict__ outb) {
    int warp = threadIdx.x >> 5, lane = threadIdx.x & 31;
    int row = blockIdx.x * 8 + warp;
    size_t off = (size_t)row * C_ + lane * 8;

    float v[8], bvf[8];
    float4 a0 = *(const float4*)&A[off],  a1 = *(const float4*)&A[off + 4];
    ld8bf(&Bv[off], bvf);
    v[0] = a0.x + bvf[0]; v[1] = a0.y + bvf[1]; v[2] = a0.z + bvf[2]; v[3] = a0.w + bvf[3];
    v[4] = a1.x + bvf[4]; v[5] = a1.y + bvf[5]; v[6] = a1.z + bvf[6]; v[7] = a1.w + bvf[7];

    float s = 0.f;
#pragma unroll
    for (int d = 0; d < 8; d++) s += v[d];
#pragma unroll
    for (int o = 16; o; o >>= 1) s += __shfl_xor_sync(0xffffffffu, s, o);
    float mu = s * (1.f / 256.f);
    float s2 = 0.f;
#pragma unroll
    for (int d = 0; d < 8; d++) { float t = v[d] - mu; s2 += t * t; }
#pragma unroll
    for (int o = 16; o; o >>= 1) s2 += __shfl_xor_sync(0xffffffffu, s2, o);
    float is = rsqrtf(s2 * (1.f / 256.f) + 1e-5f);

    float r[8];
#pragma unroll
    for (int d = 0; d < 8; d++) {
        r[d] = (v[d] - mu) * is * g[lane * 8 + d] + be[lane * 8 + d];
        if (addq) r[d] += addq[off + d];
    }
    if (out) {
        *(float4*)&out[off]     = make_float4(r[0], r[1], r[2], r[3]);
        *(float4*)&out[off + 4] = make_float4(r[4], r[5], r[6], r[7]);
    }
    if (outb) {
        __nv_bfloat162 pk[4];
#pragma unroll
        for (int t = 0; t < 4; t++) pk[t] = __floats2bfloat162_rn(r[2 * t], r[2 * t + 1]);
        *(uint4*)&outb[off] = *(uint4*)pk;
    }
}

// ================= launch =======================================================
extern "C" void kernel_launch(void* const* d_in, const int* in_sizes, int n_in,
                              void* d_out, int out_size) {
    (void)in_sizes; (void)n_in; (void)out_size;
    const float* q_xyz   = (const float*)d_in[0];
    const float* q_feat  = (const float*)d_in[1];
    const float* kv_xyz  = (const float*)d_in[2];
    const float* kv_feat = (const float*)d_in[3];
    const unsigned char* kv_pad = (const unsigned char*)d_in[4];
    const float* Wpos  = (const float*)d_in[5];
    const float* bpos  = (const float*)d_in[6];
    const float* Wq    = (const float*)d_in[7];
    const float* bq    = (const float*)d_in[8];
    const float* Wk    = (const float*)d_in[9];
    const float* bk    = (const float*)d_in[10];
    const float* Wv    = (const float*)d_in[11];
    const float* bv    = (const float*)d_in[12];
    const float* Wo    = (const float*)d_in[13];
    const float* bo    = (const float*)d_in[14];
    const float* ln1_g = (const float*)d_in[15];
    const float* ln1_b = (const float*)d_in[16];
    const float* W1    = (const float*)d_in[17];
    const float* b1    = (const float*)d_in[18];
    const float* W2    = (const float*)d_in[19];
    const float* b2    = (const float*)d_in[20];
    const float* ln2_g = (const float*)d_in[21];
    const float* ln2_b = (const float*)d_in[22];
    float* out = (float*)d_out;

    float *Xq, *Y, *bqkv, *bkv;
    __nv_bfloat16 *Xqb, *Xkvb, *QKVq, *KVkv, *Ob, *Tb, *Yb, *Hidb, *WTqkv, *WTkv, *WTo, *WT1, *WT2;
    int* nidx;
    cudaGetSymbolAddress((void**)&Xq,    g_Xq);
    cudaGetSymbolAddress((void**)&Xqb,   g_Xq_b);
    cudaGetSymbolAddress((void**)&Xkvb,  g_Xkv_b);
    cudaGetSymbolAddress((void**)&QKVq,  g_QKVq);
    cudaGetSymbolAddress((void**)&KVkv,  g_KVkv);
    cudaGetSymbolAddress((void**)&Ob,    g_O_b);
    cudaGetSymbolAddress((void**)&Tb,    g_T_b);
    cudaGetSymbolAddress((void**)&Y,     g_Y);
    cudaGetSymbolAddress((void**)&Yb,    g_Y_b);
    cudaGetSymbolAddress((void**)&Hidb,  g_Hid_b);
    cudaGetSymbolAddress((void**)&nidx,  g_nidx);
    cudaGetSymbolAddress((void**)&WTqkv, g_WTqkv);
    cudaGetSymbolAddress((void**)&WTkv,  g_WTkv);
    cudaGetSymbolAddress((void**)&WTo,   g_WTo);
    cudaGetSymbolAddress((void**)&WT1,   g_WT1);
    cudaGetSymbolAddress((void**)&WT2,   g_WT2);
    cudaGetSymbolAddress((void**)&bqkv,  g_bqkv);
    cudaGetSymbolAddress((void**)&bkv,   g_bkv);

    cudaFuncSetAttribute(gemm_hmma<0>, cudaFuncAttributeMaxDynamicSharedMemorySize, GEMM_SMEM);
    cudaFuncSetAttribute(gemm_hmma<1>, cudaFuncAttributeMaxDynamicSharedMemorySize, GEMM_SMEM);
    cudaFuncSetAttribute(gemm_hmma<2>, cudaFuncAttributeMaxDynamicSharedMemorySize, GEMM_SMEM);
    cudaFuncSetAttribute(knn_cell_kernel, cudaFuncAttributeMaxDynamicSharedMemorySize, KNN_SMEM);

    // 0: weight prep + cell zeroing
    prep_weights<<<(PREP_ITEMS + 255) / 256, 256>>>(Wq, Wk, Wv, Wo, W1, W2, bq, bk, bv);
    // 1: fused pos-encoding + binning
    posenc_kernel<<<(NQ_ + NM_) / 4, 256>>>(q_xyz, q_feat, kv_xyz, kv_feat, kv_pad, Wpos, bpos);
    // 2: fused QKV projection
    dim3 gqkv(768 / 128, NQ_ / 128);
    gemm_hmma<2><<<gqkv, 256, GEMM_SMEM>>>(Xqb, WTqkv, bqkv, QKVq, C_, 768);
    // 3: cell-grouped kNN (two-pass)  <-- profiled slot
    knn_cell_kernel<<<NCELL_, 512, KNN_SMEM>>>(q_xyz, nidx);
    // 4: fused KV projection
    dim3 gkv(512 / 128, NM_ / 128);
    gemm_hmma<2><<<gkv, 256, GEMM_SMEM>>>(Xkvb, WTkv, bkv, KVkv, C_, 512);
    // 5: gather attention
    attn_kernel<<<NQ_ / 8, 256>>>(QKVq, KVkv, nidx, Ob);
    // 6-7: output projection (bf16 out) + LN1
    dim3 go(C_ / 128, NQ_ / 128);
    gemm_hmma<2><<<go, 256, GEMM_SMEM>>>(Ob, WTo, bo, Tb, C_, C_);
    ln_res_kernel<<<NQ_ / 8, 256>>>(Xq, Tb, ln1_g, ln1_b, nullptr, Y, Yb);
    // 8-9: FFN
    dim3 gf1(FF_ / 128, NQ_ / 128);
    gemm_hmma<1><<<gf1, 256, GEMM_SMEM>>>(Yb, WT1, b1, Hidb, C_, FF_);
    gemm_hmma<2><<<go, 256, GEMM_SMEM>>>(Hidb, WT2, b2, Tb, FF_, C_);
    // 10: LN2 + residual + q_feat -> d_out
    ln_res_kernel<<<NQ_ / 8, 256>>>(Y, Tb, ln2_g, ln2_b, q_feat, out, nullptr);
}

// round 15
// speedup vs baseline: 2.0468x; 1.0391x over previous
#include <cuda_runtime.h>
#include <cuda_bf16.h>
#include <math.h>
#include <cstdint>

#define B_   4
#define N_   4096
#define M_   8192
#define C_   256
#define K_   8
#define FF_  1024
#define NQ_  (B_ * N_)
#define NM_  (B_ * M_)
#define NCELL_ (B_ * 125)
#define CAP_ 192
#define QCAP_ 128
#define SCAP_ 2400

// ================= scratch ======================================================
__device__ float          g_Xq   [NQ_ * C_];
__device__ __nv_bfloat16  g_Xq_b [NQ_ * C_];
__device__ __nv_bfloat16  g_Xkv_b[NM_ * C_];
__device__ __nv_bfloat16  g_QKVq [NQ_ * 3 * C_];
__device__ __nv_bfloat16  g_KVkv [NM_ * 2 * C_];
__device__ __nv_bfloat16  g_O_b  [NQ_ * C_];
__device__ __nv_bfloat16  g_T_b  [NQ_ * C_];
__device__ float          g_Y    [NQ_ * C_];
__device__ __nv_bfloat16  g_Y_b  [NQ_ * C_];
__device__ __nv_bfloat16  g_Hid_b[NQ_ * FF_];
__device__ int            g_nidx [NQ_ * K_];
__device__ int            g_cnt  [NCELL_];
__device__ int            g_qcnt [NCELL_];
__device__ int            g_qids [NCELL_ * QCAP_];
__device__ float4         g_pts  [NCELL_ * CAP_];
__device__ int            g_pidx [NCELL_ * CAP_];
__device__ __nv_bfloat16  g_WTqkv[3 * C_ * C_];
__device__ __nv_bfloat16  g_WTkv [2 * C_ * C_];
__device__ __nv_bfloat16  g_WTo  [C_ * C_];
__device__ __nv_bfloat16  g_WT1  [FF_ * C_];
__device__ __nv_bfloat16  g_WT2  [C_ * FF_];
__device__ float          g_bqkv [3 * C_];
__device__ float          g_bkv  [2 * C_];

__device__ __forceinline__ uint32_t smem_u32(const void* p) {
    uint32_t a;
    asm("{ .reg .u64 t; cvta.to.shared.u64 t, %1; cvt.u32.u64 %0, t; }" : "=r"(a) : "l"(p));
    return a;
}

// ================= fused weight prep + cell zeroing =============================
__global__ void prep_weights(const float* __restrict__ Wq, const float* __restrict__ Wk,
                             const float* __restrict__ Wv, const float* __restrict__ Wo,
                             const float* __restrict__ W1, const float* __restrict__ W2,
                             const float* __restrict__ bq, const float* __restrict__ bk,
                             const float* __restrict__ bv) {
    int idx = blockIdx.x * 256 + threadIdx.x;
    const int S = C_ * C_;
    const int E0 = 4 * S + 2 * C_ * FF_;
    if (idx < S) {
        int k = idx >> 8, n = idx & 255;
        g_WTqkv[(size_t)n * C_ + k] = __float2bfloat16(Wq[idx]);
    } else if (idx < 2 * S) {
        int j = idx - S; int k = j >> 8, n = j & 255;
        __nv_bfloat16 v = __float2bfloat16(Wk[j]);
        g_WTqkv[(size_t)(C_ + n) * C_ + k] = v;
        g_WTkv [(size_t)n * C_ + k] = v;
    } else if (idx < 3 * S) {
        int j = idx - 2 * S; int k = j >> 8, n = j & 255;
        __nv_bfloat16 v = __float2bfloat16(Wv[j]);
        g_WTqkv[(size_t)(2 * C_ + n) * C_ + k] = v;
        g_WTkv [(size_t)(C_ + n) * C_ + k] = v;
    } else if (idx < 4 * S) {
        int j = idx - 3 * S; int k = j >> 8, n = j & 255;
        g_WTo[(size_t)n * C_ + k] = __float2bfloat16(Wo[j]);
    } else if (idx < 4 * S + C_ * FF_) {
        int j = idx - 4 * S; int k = j >> 10, n = j & 1023;
        g_WT1[(size_t)n * C_ + k] = __float2bfloat16(W1[j]);
    } else if (idx < E0) {
        int j = idx - 4 * S - C_ * FF_; int k = j >> 8, n = j & 255;
        g_WT2[(size_t)n * FF_ + k] = __float2bfloat16(W2[j]);
    } else if (idx < E0 + 768) {
        int j = idx - E0;
        g_bqkv[j] = (j < 256) ? bq[j] : (j < 512 ? bk[j - 256] : bv[j - 512]);
    } else if (idx < E0 + 768 + 512) {
        int j = idx - E0 - 768;
        g_bkv[j] = (j < 256) ? bk[j] : bv[j - 256];
    } else if (idx < E0 + 768 + 512 + NCELL_) {
        g_cnt[idx - E0 - 768 - 512] = 0;
    } else if (idx < E0 + 768 + 512 + 2 * NCELL_) {
        g_qcnt[idx - E0 - 768 - 512 - NCELL_] = 0;
    }
}
#define PREP_ITEMS (4 * C_ * C_ + 2 * C_ * FF_ + 768 + 512 + 2 * NCELL_)

// ================= cell index helper ============================================
__device__ __forceinline__ int cell_of(float x, float y, float z) {
    int cx = min((int)(x * 5.f), 4);
    int cy = min((int)(y * 5.f), 4);
    int cz = min((int)(z * 5.f), 4);
    return (cx * 5 + cy) * 5 + cz;
}

// ================= fused pos-encoding + binning (4 rows per CTA) ================
__global__ void posenc_kernel(const float* __restrict__ q_xyz,
                              const float* __restrict__ q_feat,
                              const float* __restrict__ kv_xyz,
                              const float* __restrict__ kv_feat,
                              const unsigned char* __restrict__ kv_pad,
                              const float* __restrict__ Wpos,
                              const float* __restrict__ bpos) {
    int base = blockIdx.x * 4;
    int c    = threadIdx.x;
    float w0 = Wpos[c], w1 = Wpos[C_ + c], w2 = Wpos[2 * C_ + c], bp = bpos[c];
#pragma unroll
    for (int r = 0; r < 4; r++) {
        int row = base + r;
        const float* xyz; const float* feat;
        if (row < NQ_) { xyz = q_xyz + row * 3; feat = q_feat + (size_t)row * C_; }
        else { int rr = row - NQ_; xyz = kv_xyz + rr * 3; feat = kv_feat + (size_t)rr * C_; }
        float v = feat[c] + xyz[0] * w0 + xyz[1] * w1 + xyz[2] * w2 + bp;
        if (row < NQ_) {
            g_Xq[(size_t)row * C_ + c] = v;
            g_Xq_b[(size_t)row * C_ + c] = __float2bfloat16(v);
        } else {
            g_Xkv_b[(size_t)(row - NQ_) * C_ + c] = __float2bfloat16(v);
        }
    }
    if (c < 4) {
        int row = base + c;
        if (row < NQ_) {
            int qi = row, b = qi >> 12;
            float x = q_xyz[qi * 3], y = q_xyz[qi * 3 + 1], z = q_xyz[qi * 3 + 2];
            int cid = b * 125 + cell_of(x, y, z);
            int pos = atomicAdd(&g_qcnt[cid], 1);
            if (pos < QCAP_) g_qids[cid * QCAP_ + pos] = qi;
        } else {
            int i = row - NQ_;
            if (!kv_pad[i]) {
                int b = i >> 13;
                float x = kv_xyz[i * 3], y = kv_xyz[i * 3 + 1], z = kv_xyz[i * 3 + 2];
                int cid = b * 125 + cell_of(x, y, z);
                int pos = atomicAdd(&g_cnt[cid], 1);
                if (pos < CAP_) {
                    g_pts[cid * CAP_ + pos] = make_float4(x, y, z, x * x + y * y + z * z);
                    g_pidx[cid * CAP_ + pos] = i & 8191;
                }
            }
        }
    }
}

// ================= HMMA GEMM: 128x128 tile, 64x32 warp, BK=64, XOR swizzle ======
#define STG_BYTES (128 * 128)
#define GEMM_SMEM (3 * STG_BYTES * 2)

__device__ __forceinline__ void ldm_x4(uint32_t* r, uint32_t addr) {
    asm volatile("ldmatrix.sync.aligned.m8n8.x4.shared.b16 {%0,%1,%2,%3}, [%4];"
                 : "=r"(r[0]), "=r"(r[1]), "=r"(r[2]), "=r"(r[3]) : "r"(addr));
}
__device__ __forceinline__ void mma_bf16(float* d, const uint32_t* a, const uint32_t* b) {
    asm volatile(
        "mma.sync.aligned.m16n8k16.row.col.f32.bf16.bf16.f32 "
        "{%0,%1,%2,%3}, {%4,%5,%6,%7}, {%8,%9}, {%0,%1,%2,%3};"
        : "+f"(d[0]), "+f"(d[1]), "+f"(d[2]), "+f"(d[3])
        : "r"(a[0]), "r"(a[1]), "r"(a[2]), "r"(a[3]), "r"(b[0]), "r"(b[1]));
}
__device__ __forceinline__ void cp16(uint32_t saddr, const void* gaddr) {
    asm volatile("cp.async.cg.shared.global [%0], [%1], 16;" :: "r"(saddr), "l"(gaddr));
}

template <int MODE>
__global__ __launch_bounds__(256, 2)
void gemm_hmma(const __nv_bfloat16* __restrict__ A,
               const __nv_bfloat16* __restrict__ BT,
               const float* __restrict__ bias,
               void* __restrict__ Out, int K, int N) {
    extern __shared__ char dsm[];
    int tid  = threadIdx.x;
    int wid  = tid >> 5, lane = tid & 31;
    int row0 = blockIdx.y * 128;
    int col0 = blockIdx.x * 128;
    int wm   = (wid & 1) * 64;
    int wn   = (wid >> 1) * 32;

    uint32_t aA = smem_u32(dsm);
    uint32_t aB = aA + 3 * STG_BYTES;

    auto issue = [&](int st, int kc0) {
        uint32_t oA = aA + st * STG_BYTES, oB = aB + st * STG_BYTES;
#pragma unroll
        for (int j = 0; j < 4; j++) {
            int idx = tid + j * 256;
            int row = idx >> 3, s = idx & 7;
            uint32_t soff = row * 128 + ((s ^ (row & 7)) << 4);
            cp16(oA + soff, A  + (size_t)(row0 + row) * K + kc0 + s * 8);
            cp16(oB + soff, BT + (size_t)(col0 + row) * K + kc0 + s * 8);
        }
        asm volatile("cp.async.commit_group;" ::: "memory");
    };

    float acc[4][4][4] = {};
    int nk = K >> 6;

    issue(0, 0);
    issue(1, 64);

    for (int i = 0; i < nk; i++) {
        if (i < nk - 1) asm volatile("cp.async.wait_group 1;" ::: "memory");
        else            asm volatile("cp.async.wait_group 0;" ::: "memory");
        __syncthreads();

        if (i + 2 < nk) issue((i + 2) % 3, (i + 2) << 6);

        uint32_t bAs = aA + (i % 3) * STG_BYTES;
        uint32_t bBs = aB + (i % 3) * STG_BYTES;
#pragma unroll
        for (int ks = 0; ks < 4; ks++) {
            uint32_t afr[4][4];
#pragma unroll
            for (int mt = 0; mt < 4; mt++) {
                uint32_t row = wm + mt * 16 + (lane & 15);
                uint32_t ch  = (uint32_t)(ks * 2) + (lane >> 4);
                ldm_x4(afr[mt], bAs + row * 128 + ((ch ^ (row & 7)) << 4));
            }
            uint32_t bfr[2][4];
#pragma unroll
            for (int np = 0; np < 2; np++) {
                uint32_t row = wn + np * 16 + ((lane >> 4) << 3) + (lane & 7);
                uint32_t ch  = (uint32_t)(ks * 2) + ((lane >> 3) & 1);
                ldm_x4(bfr[np], bBs + row * 128 + ((ch ^ (row & 7)) << 4));
            }
#pragma unroll
            for (int mt = 0; mt < 4; mt++)
#pragma unroll
                for (int nt = 0; nt < 4; nt++)
                    mma_bf16(acc[mt][nt], afr[mt], &bfr[nt >> 1][(nt & 1) * 2]);
        }
    }

    int g  = lane >> 2;
    int t2 = (lane & 3) * 2;
#pragma unroll
    for (int mt = 0; mt < 4; mt++) {
#pragma unroll
        for (int nt = 0; nt < 4; nt++) {
            int row = row0 + wm + mt * 16 + g;
            int col = col0 + wn + nt * 8 + t2;
            float2 b2 = *(const float2*)&bias[col];
            float v0 = acc[mt][nt][0] + b2.x, v1 = acc[mt][nt][1] + b2.y;
            float v2 = acc[mt][nt][2] + b2.x, v3 = acc[mt][nt][3] + b2.y;
            if (MODE == 0) {
                float* op = (float*)Out;
                *(float2*)&op[(size_t)row * N + col]       = make_float2(v0, v1);
                *(float2*)&op[(size_t)(row + 8) * N + col] = make_float2(v2, v3);
            } else {
                if (MODE == 1) {
                    v0 = fmaxf(v0, 0.f); v1 = fmaxf(v1, 0.f);
                    v2 = fmaxf(v2, 0.f); v3 = fmaxf(v3, 0.f);
                }
                __nv_bfloat16* op = (__nv_bfloat16*)Out;
                *(__nv_bfloat162*)&op[(size_t)row * N + col]       = __floats2bfloat162_rn(v0, v1);
                *(__nv_bfloat162*)&op[(size_t)(row + 8) * N + col] = __floats2bfloat162_rn(v2, v3);
            }
        }
    }
}

// ================= cell-grouped kNN: adaptive-threshold select ===================
#define KNN_SMEM (SCAP_ * 20)

__global__ __launch_bounds__(512, 3)
void knn_cell_kernel(const float* __restrict__ q_xyz, int* __restrict__ nidx) {
    const float INF = __int_as_float(0x7f800000);
    int cid = blockIdx.x;
    int nq = min(g_qcnt[cid], QCAP_);
    if (nq == 0) return;
    int b = cid / 125;
    int cc = cid % 125;
    int cx = cc / 25, cy = (cc / 5) % 5, cz = cc % 5;

    extern __shared__ char sm[];
    float4* spts = (float4*)sm;
    int*    sidx = (int*)(sm + SCAP_ * 16);
    __shared__ int s_cells[32], s_off[32], s_cnt[32];
    __shared__ int s_tot;

    int tid = threadIdx.x, warp = tid >> 5, lane = tid & 31;

    // parallel prologue: 27 neighbor cells via one warp + shfl scan
    if (tid < 32) {
        int lx = tid / 9, ly = (tid / 3) % 3, lz = tid % 3;
        int x = cx + lx - 1, y = cy + ly - 1, z = cz + lz - 1;
        bool ok = (tid < 27) && x >= 0 && x <= 4 && y >= 0 && y <= 4 && z >= 0 && z <= 4;
        int nid = ok ? b * 125 + (x * 5 + y) * 5 + z : 0;
        int c = ok ? min(g_cnt[nid], CAP_) : 0;
        int inc = c;
#pragma unroll
        for (int o = 1; o < 32; o <<= 1) {
            int u = __shfl_up_sync(0xffffffffu, inc, o);
            if (tid >= o) inc += u;
        }
        int excl = inc - c;
        if (excl > SCAP_) excl = SCAP_;
        if (excl + c > SCAP_) c = SCAP_ - excl;
        s_cells[tid] = nid; s_off[tid] = excl; s_cnt[tid] = c;
        if (tid == 31) s_tot = min(inc, SCAP_);
    }
    __syncthreads();
    int tot = s_tot;

    for (int j = 0; j < 27; j++) {
        int n = s_cnt[j];
        if (n == 0) continue;
        int nid = s_cells[j], off = s_off[j];
        for (int t = tid; t < n; t += 512) {
            spts[off + t] = g_pts[nid * CAP_ + t];
            sidx[off + t] = g_pidx[nid * CAP_ + t];
        }
    }
    __syncthreads();

    int nb = (tot + 31) >> 5;
    for (int qj = warp; qj < nq; qj += 16) {
        int qi = g_qids[cid * QCAP_ + qj];
        float qx = q_xyz[qi * 3], qy = q_xyz[qi * 3 + 1], qz = q_xyz[qi * 3 + 2];
        float qn = qx * qx + qy * qy + qz * qz;

        // adaptive threshold: target ~32 survivors (boundary-corrected)
        const float r8 = 0.0977f;
        float fx = fminf(qx + r8, 1.f) - fmaxf(qx - r8, 0.f);
        float fy = fminf(qy + r8, 1.f) - fmaxf(qy - r8, 0.f);
        float fz = fminf(qz + r8, 1.f) - fmaxf(qz - r8, 0.f);
        float f  = fx * fy * fz * (1.f / (8.f * r8 * r8 * r8));
        float ta = fminf(0.04f, 0.00955f * __powf(f, -0.6666667f));

        float d8[8]; int i8[8];
#pragma unroll
        for (int i = 0; i < 8; i++) { d8[i] = INF; i8[i] = -1; }

        int scnt = 0;
        for (int bt = 0; bt < nb; bt++) {
            int t = (bt << 5) + lane;
            float d2 = INF; int iv = 0;
            bool pass = false;
            if (t < tot) {
                float4 p = spts[t];
                d2 = qn + p.w - 2.f * (qx * p.x + qy * p.y + qz * p.z);
                pass = (d2 <= ta);
                iv = sidx[t];
            }
            unsigned m = __ballot_sync(0xffffffffu, pass);
            scnt += __popc(m);
            if (pass && d2 < d8[7]) {
                float dv = d2;
#pragma unroll
                for (int k = 0; k < 8; k++) {
                    if (dv < d8[k]) {
                        float td = d8[k]; d8[k] = dv; dv = td;
                        int   ti = i8[k]; i8[k] = iv; iv = ti;
                    }
                }
            }
        }

        // fallback (probabilistically ~never): fewer than 8 under ta and ta < R^2
        if (scnt < 8 && ta < 0.04f) {
            for (int t = lane; t < tot; t += 32) {
                float4 p = spts[t];
                float d2 = qn + p.w - 2.f * (qx * p.x + qy * p.y + qz * p.z);
                if (d2 > ta && d2 <= 0.04f && d2 < d8[7]) {
                    float dv = d2; int iv = sidx[t];
#pragma unroll
                    for (int k = 0; k < 8; k++) {
                        if (dv < d8[k]) {
                            float td = d8[k]; d8[k] = dv; dv = td;
                            int   ti = i8[k]; i8[k] = iv; iv = ti;
                        }
                    }
                }
            }
        }

        // merge: consume d8[0], winner shifts (static indices)
        for (int r = 0; r < 8; r++) {
            unsigned db = __float_as_uint(fmaxf(d8[0], 0.f));
            unsigned long long key = ((unsigned long long)db << 32)
                                   | ((unsigned)(i8[0] & 0x1FFF) << 5) | (unsigned)lane;
#pragma unroll
            for (int o = 16; o; o >>= 1) {
                unsigned long long other = __shfl_xor_sync(0xffffffffu, key, o);
                key = (other < key) ? other : key;
            }
            bool valid = ((unsigned)(key >> 32)) < 0x7f800000u;
            if (valid && lane == (int)(key & 31u)) {
#pragma unroll
                for (int k = 0; k < 7; k++) { d8[k] = d8[k + 1]; i8[k] = i8[k + 1]; }
                d8[7] = INF; i8[7] = -1;
            }
            if (lane == 0) nidx[qi * 8 + r] = valid ? (int)((key >> 5) & 0x1FFF) : -1;
        }
    }
}

// ================= gather attention =============================================
__device__ __forceinline__ void ld8bf(const __nv_bfloat16* p, float* f) {
    uint4 u = *(const uint4*)p;
    const __nv_bfloat162* h = (const __nv_bfloat162*)&u;
#pragma unroll
    for (int i = 0; i < 4; i++) {
        float2 t = __bfloat1622float2(h[i]);
        f[2 * i] = t.x; f[2 * i + 1] = t.y;
    }
}

__global__ void attn_kernel(const __nv_bfloat16* __restrict__ QKV,
                            const __nv_bfloat16* __restrict__ KV,
                            const int* __restrict__ nidx,
                            __nv_bfloat16* __restrict__ O) {
    const float INF = __int_as_float(0x7f800000);
    int warp = threadIdx.x >> 5, lane = threadIdx.x & 31;
    int q = blockIdx.x * 8 + warp;
    int b = q >> 12;
    const int off8 = lane * 8;
    const __nv_bfloat16* qkv = QKV + (size_t)q * 768;

    float qr[8];
    ld8bf(qkv + off8, qr);

    int rid[8]; int nt = 1;
#pragma unroll
    for (int j = 0; j < 8; j++) {
        rid[j] = nidx[q * 8 + j];
        if (rid[j] >= 0) nt++;
    }
    float sc[9];
#pragma unroll
    for (int j = 0; j < 9; j++) {
        if (j == 0 || j < nt) {
            const __nv_bfloat16* kr = (j == 0)
                ? qkv + 256 + off8
                : KV + ((size_t)b * M_ + rid[j - 1]) * 512 + off8;
            float kf[8];
            ld8bf(kr, kf);
            float s = qr[0] * kf[0] + qr[1] * kf[1] + qr[2] * kf[2] + qr[3] * kf[3]
                    + qr[4] * kf[4] + qr[5] * kf[5] + qr[6] * kf[6] + qr[7] * kf[7];
            s += __shfl_xor_sync(0xffffffffu, s, 1);
            s += __shfl_xor_sync(0xffffffffu, s, 2);
            sc[j] = s * 0.17677669529663687f;
        } else sc[j] = -INF;
    }
    float m = sc[0];
#pragma unroll
    for (int j = 1; j < 9; j++) m = fmaxf(m, sc[j]);
    float w[9], ssum = 0.f;
#pragma unroll
    for (int j = 0; j < 9; j++) {
        w[j] = (j == 0 || j < nt) ? expf(sc[j] - m) : 0.f;
        ssum += w[j];
    }
    float inv = 1.f / ssum;

    float o[8] = {0, 0, 0, 0, 0, 0, 0, 0};
#pragma unroll
    for (int j = 0; j < 9; j++) {
        if (j == 0 || j < nt) {
            const __nv_bfloat16* vr = (j == 0)
                ? qkv + 512 + off8
                : KV + ((size_t)b * M_ + rid[j - 1]) * 512 + 256 + off8;
            float vf[8];
            ld8bf(vr, vf);
            float a = w[j] * inv;
#pragma unroll
            for (int d = 0; d < 8; d++) o[d] += a * vf[d];
        }
    }
    __nv_bfloat162 pk[4];
#pragma unroll
    for (int t = 0; t < 4; t++) pk[t] = __floats2bfloat162_rn(o[2 * t], o[2 * t + 1]);
    *(uint4*)&O[(size_t)q * C_ + off8] = *(uint4*)pk;
}

// ================= residual + LayerNorm (Bv in bf16) ============================
__global__ void ln_res_kernel(const float* __restrict__ A,
                              const __nv_bfloat16* __restrict__ Bv,
                              const float* __restrict__ g,
                              const float* __restrict__ be,
                              const float* __restrict__ addq,
                              float* __restrict__ out,
                              __nv_bfloat16* __restrict__ outb) {
    int warp = threadIdx.x >> 5, lane = threadIdx.x & 31;
    int row = blockIdx.x * 8 + warp;
    size_t off = (size_t)row * C_ + lane * 8;

    float v[8], bvf[8];
    float4 a0 = *(const float4*)&A[off],  a1 = *(const float4*)&A[off + 4];
    ld8bf(&Bv[off], bvf);
    v[0] = a0.x + bvf[0]; v[1] = a0.y + bvf[1]; v[2] = a0.z + bvf[2]; v[3] = a0.w + bvf[3];
    v[4] = a1.x + bvf[4]; v[5] = a1.y + bvf[5]; v[6] = a1.z + bvf[6]; v[7] = a1.w + bvf[7];

    float s = 0.f;
#pragma unroll
    for (int d = 0; d < 8; d++) s += v[d];
#pragma unroll
    for (int o = 16; o; o >>= 1) s += __shfl_xor_sync(0xffffffffu, s, o);
    float mu = s * (1.f / 256.f);
    float s2 = 0.f;
#pragma unroll
    for (int d = 0; d < 8; d++) { float t = v[d] - mu; s2 += t * t; }
#pragma unroll
    for (int o = 16; o; o >>= 1) s2 += __shfl_xor_sync(0xffffffffu, s2, o);
    float is = rsqrtf(s2 * (1.f / 256.f) + 1e-5f);

    float r[8];
#pragma unroll
    for (int d = 0; d < 8; d++) {
        r[d] = (v[d] - mu) * is * g[lane * 8 + d] + be[lane * 8 + d];
        if (addq) r[d] += addq[off + d];
    }
    if (out) {
        *(float4*)&out[off]     = make_float4(r[0], r[1], r[2], r[3]);
        *(float4*)&out[off + 4] = make_float4(r[4], r[5], r[6], r[7]);
    }
    if (outb) {
        __nv_bfloat162 pk[4];
#pragma unroll
        for (int t = 0; t < 4; t++) pk[t] = __floats2bfloat162_rn(r[2 * t], r[2 * t + 1]);
        *(uint4*)&outb[off] = *(uint4*)pk;
    }
}

// ================= launch =======================================================
extern "C" void kernel_launch(void* const* d_in, const int* in_sizes, int n_in,
                              void* d_out, int out_size) {
    (void)in_sizes; (void)n_in; (void)out_size;
    const float* q_xyz   = (const float*)d_in[0];
    const float* q_feat  = (const float*)d_in[1];
    const float* kv_xyz  = (const float*)d_in[2];
    const float* kv_feat = (const float*)d_in[3];
    const unsigned char* kv_pad = (const unsigned char*)d_in[4];
    const float* Wpos  = (const float*)d_in[5];
    const float* bpos  = (const float*)d_in[6];
    const float* Wq    = (const float*)d_in[7];
    const float* bq    = (const float*)d_in[8];
    const float* Wk    = (const float*)d_in[9];
    const float* bk    = (const float*)d_in[10];
    const float* Wv    = (const float*)d_in[11];
    const float* bv    = (const float*)d_in[12];
    const float* Wo    = (const float*)d_in[13];
    const float* bo    = (const float*)d_in[14];
    const float* ln1_g = (const float*)d_in[15];
    const float* ln1_b = (const float*)d_in[16];
    const float* W1    = (const float*)d_in[17];
    const float* b1    = (const float*)d_in[18];
    const float* W2    = (const float*)d_in[19];
    const float* b2    = (const float*)d_in[20];
    const float* ln2_g = (const float*)d_in[21];
    const float* ln2_b = (const float*)d_in[22];
    float* out = (float*)d_out;

    float *Xq, *Y, *bqkv, *bkv;
    __nv_bfloat16 *Xqb, *Xkvb, *QKVq, *KVkv, *Ob, *Tb, *Yb, *Hidb, *WTqkv, *WTkv, *WTo, *WT1, *WT2;
    int* nidx;
    cudaGetSymbolAddress((void**)&Xq,    g_Xq);
    cudaGetSymbolAddress((void**)&Xqb,   g_Xq_b);
    cudaGetSymbolAddress((void**)&Xkvb,  g_Xkv_b);
    cudaGetSymbolAddress((void**)&QKVq,  g_QKVq);
    cudaGetSymbolAddress((void**)&KVkv,  g_KVkv);
    cudaGetSymbolAddress((void**)&Ob,    g_O_b);
    cudaGetSymbolAddress((void**)&Tb,    g_T_b);
    cudaGetSymbolAddress((void**)&Y,     g_Y);
    cudaGetSymbolAddress((void**)&Yb,    g_Y_b);
    cudaGetSymbolAddress((void**)&Hidb,  g_Hid_b);
    cudaGetSymbolAddress((void**)&nidx,  g_nidx);
    cudaGetSymbolAddress((void**)&WTqkv, g_WTqkv);
    cudaGetSymbolAddress((void**)&WTkv,  g_WTkv);
    cudaGetSymbolAddress((void**)&WTo,   g_WTo);
    cudaGetSymbolAddress((void**)&WT1,   g_WT1);
    cudaGetSymbolAddress((void**)&WT2,   g_WT2);
    cudaGetSymbolAddress((void**)&bqkv,  g_bqkv);
    cudaGetSymbolAddress((void**)&bkv,   g_bkv);

    cudaFuncSetAttribute(gemm_hmma<0>, cudaFuncAttributeMaxDynamicSharedMemorySize, GEMM_SMEM);
    cudaFuncSetAttribute(gemm_hmma<1>, cudaFuncAttributeMaxDynamicSharedMemorySize, GEMM_SMEM);
    cudaFuncSetAttribute(gemm_hmma<2>, cudaFuncAttributeMaxDynamicSharedMemorySize, GEMM_SMEM);
    cudaFuncSetAttribute(knn_cell_kernel, cudaFuncAttributeMaxDynamicSharedMemorySize, KNN_SMEM);

    // 0: weight prep + cell zeroing
    prep_weights<<<(PREP_ITEMS + 255) / 256, 256>>>(Wq, Wk, Wv, Wo, W1, W2, bq, bk, bv);
    // 1: fused pos-encoding + binning
    posenc_kernel<<<(NQ_ + NM_) / 4, 256>>>(q_xyz, q_feat, kv_xyz, kv_feat, kv_pad, Wpos, bpos);
    // 2: fused QKV projection
    dim3 gqkv(768 / 128, NQ_ / 128);
    gemm_hmma<2><<<gqkv, 256, GEMM_SMEM>>>(Xqb, WTqkv, bqkv, QKVq, C_, 768);
    // 3: cell-grouped kNN (adaptive threshold)  <-- profiled slot
    knn_cell_kernel<<<NCELL_, 512, KNN_SMEM>>>(q_xyz, nidx);
    // 4: fused KV projection
    dim3 gkv(512 / 128, NM_ / 128);
    gemm_hmma<2><<<gkv, 256, GEMM_SMEM>>>(Xkvb, WTkv, bkv, KVkv, C_, 512);
    // 5: gather attention
    attn_kernel<<<NQ_ / 8, 256>>>(QKVq, KVkv, nidx, Ob);
    // 6-7: output projection (bf16 out) + LN1
    dim3 go(C_ / 128, NQ_ / 128);
    gemm_hmma<2><<<go, 256, GEMM_SMEM>>>(Ob, WTo, bo, Tb, C_, C_);
    ln_res_kernel<<<NQ_ / 8, 256>>>(Xq, Tb, ln1_g, ln1_b, nullptr, Y, Yb);
    // 8-9: FFN
    dim3 gf1(FF_ / 128, NQ_ / 128);
    gemm_hmma<1><<<gf1, 256, GEMM_SMEM>>>(Yb, WT1, b1, Hidb, C_, FF_);
    gemm_hmma<2><<<go, 256, GEMM_SMEM>>>(Hidb, WT2, b2, Tb, FF_, C_);
    // 10: LN2 + residual + q_feat -> d_out
    ln_res_kernel<<<NQ_ / 8, 256>>>(Y, Tb, ln2_g, ln2_b, q_feat, out, nullptr);
}

// round 16
// speedup vs baseline: 2.1048x; 1.0283x over previous
#include <cuda_runtime.h>
#include <cuda_bf16.h>
#include <math.h>
#include <cstdint>

#define B_   4
#define N_   4096
#define M_   8192
#define C_   256
#define K_   8
#define FF_  1024
#define NQ_  (B_ * N_)
#define NM_  (B_ * M_)
#define NCELL_ (B_ * 125)
#define CAP_ 192
#define QCAP_ 128
#define SCAP_ 2400

// ================= scratch ======================================================
__device__ float          g_Xq   [NQ_ * C_];
__device__ __nv_bfloat16  g_Xq_b [NQ_ * C_];
__device__ __nv_bfloat16  g_Xkv_b[NM_ * C_];
__device__ __nv_bfloat16  g_QKVq [NQ_ * 3 * C_];
__device__ __nv_bfloat16  g_KVkv [NM_ * 2 * C_];
__device__ __nv_bfloat16  g_O_b  [NQ_ * C_];
__device__ __nv_bfloat16  g_T_b  [NQ_ * C_];
__device__ float          g_Y    [NQ_ * C_];
__device__ __nv_bfloat16  g_Y_b  [NQ_ * C_];
__device__ __nv_bfloat16  g_Hid_b[NQ_ * FF_];
__device__ int            g_nidx [NQ_ * K_];
__device__ int            g_cnt  [NCELL_];
__device__ int            g_qcnt [NCELL_];
__device__ int            g_qids [NCELL_ * QCAP_];
__device__ float4         g_pts  [NCELL_ * CAP_];
__device__ int            g_pidx [NCELL_ * CAP_];
__device__ __nv_bfloat16  g_WTqkv[3 * C_ * C_];
__device__ __nv_bfloat16  g_WTkv [2 * C_ * C_];
__device__ __nv_bfloat16  g_WTo  [C_ * C_];
__device__ __nv_bfloat16  g_WT1  [FF_ * C_];
__device__ __nv_bfloat16  g_WT2  [C_ * FF_];
__device__ float          g_bqkv [3 * C_];
__device__ float          g_bkv  [2 * C_];

__device__ __forceinline__ uint32_t smem_u32(const void* p) {
    uint32_t a;
    asm("{ .reg .u64 t; cvta.to.shared.u64 t, %1; cvt.u32.u64 %0, t; }" : "=r"(a) : "l"(p));
    return a;
}

// ================= fused weight prep + cell zeroing =============================
__global__ void prep_weights(const float* __restrict__ Wq, const float* __restrict__ Wk,
                             const float* __restrict__ Wv, const float* __restrict__ Wo,
                             const float* __restrict__ W1, const float* __restrict__ W2,
                             const float* __restrict__ bq, const float* __restrict__ bk,
                             const float* __restrict__ bv) {
    int idx = blockIdx.x * 256 + threadIdx.x;
    const int S = C_ * C_;
    const int E0 = 4 * S + 2 * C_ * FF_;
    if (idx < S) {
        int k = idx >> 8, n = idx & 255;
        g_WTqkv[(size_t)n * C_ + k] = __float2bfloat16(Wq[idx]);
    } else if (idx < 2 * S) {
        int j = idx - S; int k = j >> 8, n = j & 255;
        __nv_bfloat16 v = __float2bfloat16(Wk[j]);
        g_WTqkv[(size_t)(C_ + n) * C_ + k] = v;
        g_WTkv [(size_t)n * C_ + k] = v;
    } else if (idx < 3 * S) {
        int j = idx - 2 * S; int k = j >> 8, n = j & 255;
        __nv_bfloat16 v = __float2bfloat16(Wv[j]);
        g_WTqkv[(size_t)(2 * C_ + n) * C_ + k] = v;
        g_WTkv [(size_t)(C_ + n) * C_ + k] = v;
    } else if (idx < 4 * S) {
        int j = idx - 3 * S; int k = j >> 8, n = j & 255;
        g_WTo[(size_t)n * C_ + k] = __float2bfloat16(Wo[j]);
    } else if (idx < 4 * S + C_ * FF_) {
        int j = idx - 4 * S; int k = j >> 10, n = j & 1023;
        g_WT1[(size_t)n * C_ + k] = __float2bfloat16(W1[j]);
    } else if (idx < E0) {
        int j = idx - 4 * S - C_ * FF_; int k = j >> 8, n = j & 255;
        g_WT2[(size_t)n * FF_ + k] = __float2bfloat16(W2[j]);
    } else if (idx < E0 + 768) {
        int j = idx - E0;
        g_bqkv[j] = (j < 256) ? bq[j] : (j < 512 ? bk[j - 256] : bv[j - 512]);
    } else if (idx < E0 + 768 + 512) {
        int j = idx - E0 - 768;
        g_bkv[j] = (j < 256) ? bk[j] : bv[j - 256];
    } else if (idx < E0 + 768 + 512 + NCELL_) {
        g_cnt[idx - E0 - 768 - 512] = 0;
    } else if (idx < E0 + 768 + 512 + 2 * NCELL_) {
        g_qcnt[idx - E0 - 768 - 512 - NCELL_] = 0;
    }
}
#define PREP_ITEMS (4 * C_ * C_ + 2 * C_ * FF_ + 768 + 512 + 2 * NCELL_)

// ================= cell index helper ============================================
__device__ __forceinline__ int cell_of(float x, float y, float z) {
    int cx = min((int)(x * 5.f), 4);
    int cy = min((int)(y * 5.f), 4);
    int cz = min((int)(z * 5.f), 4);
    return (cx * 5 + cy) * 5 + cz;
}

// ================= fused pos-encoding + binning (4 rows per CTA) ================
__global__ void posenc_kernel(const float* __restrict__ q_xyz,
                              const float* __restrict__ q_feat,
                              const float* __restrict__ kv_xyz,
                              const float* __restrict__ kv_feat,
                              const unsigned char* __restrict__ kv_pad,
                              const float* __restrict__ Wpos,
                              const float* __restrict__ bpos) {
    int base = blockIdx.x * 4;
    int c    = threadIdx.x;
    float w0 = Wpos[c], w1 = Wpos[C_ + c], w2 = Wpos[2 * C_ + c], bp = bpos[c];
#pragma unroll
    for (int r = 0; r < 4; r++) {
        int row = base + r;
        const float* xyz; const float* feat;
        if (row < NQ_) { xyz = q_xyz + row * 3; feat = q_feat + (size_t)row * C_; }
        else { int rr = row - NQ_; xyz = kv_xyz + rr * 3; feat = kv_feat + (size_t)rr * C_; }
        float v = feat[c] + xyz[0] * w0 + xyz[1] * w1 + xyz[2] * w2 + bp;
        if (row < NQ_) {
            g_Xq[(size_t)row * C_ + c] = v;
            g_Xq_b[(size_t)row * C_ + c] = __float2bfloat16(v);
        } else {
            g_Xkv_b[(size_t)(row - NQ_) * C_ + c] = __float2bfloat16(v);
        }
    }
    if (c < 4) {
        int row = base + c;
        if (row < NQ_) {
            int qi = row, b = qi >> 12;
            float x = q_xyz[qi * 3], y = q_xyz[qi * 3 + 1], z = q_xyz[qi * 3 + 2];
            int cid = b * 125 + cell_of(x, y, z);
            int pos = atomicAdd(&g_qcnt[cid], 1);
            if (pos < QCAP_) g_qids[cid * QCAP_ + pos] = qi;
        } else {
            int i = row - NQ_;
            if (!kv_pad[i]) {
                int b = i >> 13;
                float x = kv_xyz[i * 3], y = kv_xyz[i * 3 + 1], z = kv_xyz[i * 3 + 2];
                int cid = b * 125 + cell_of(x, y, z);
                int pos = atomicAdd(&g_cnt[cid], 1);
                if (pos < CAP_) {
                    g_pts[cid * CAP_ + pos] = make_float4(x, y, z, x * x + y * y + z * z);
                    g_pidx[cid * CAP_ + pos] = i & 8191;
                }
            }
        }
    }
}

// ================= HMMA GEMM: 128x128 tile, 64x32 warp, BK=64, XOR swizzle ======
#define STG_BYTES (128 * 128)
#define GEMM_SMEM (3 * STG_BYTES * 2)

__device__ __forceinline__ void ldm_x4(uint32_t* r, uint32_t addr) {
    asm volatile("ldmatrix.sync.aligned.m8n8.x4.shared.b16 {%0,%1,%2,%3}, [%4];"
                 : "=r"(r[0]), "=r"(r[1]), "=r"(r[2]), "=r"(r[3]) : "r"(addr));
}
__device__ __forceinline__ void mma_bf16(float* d, const uint32_t* a, const uint32_t* b) {
    asm volatile(
        "mma.sync.aligned.m16n8k16.row.col.f32.bf16.bf16.f32 "
        "{%0,%1,%2,%3}, {%4,%5,%6,%7}, {%8,%9}, {%0,%1,%2,%3};"
        : "+f"(d[0]), "+f"(d[1]), "+f"(d[2]), "+f"(d[3])
        : "r"(a[0]), "r"(a[1]), "r"(a[2]), "r"(a[3]), "r"(b[0]), "r"(b[1]));
}
__device__ __forceinline__ void cp16(uint32_t saddr, const void* gaddr) {
    asm volatile("cp.async.cg.shared.global [%0], [%1], 16;" :: "r"(saddr), "l"(gaddr));
}

template <int MODE>
__global__ __launch_bounds__(256, 2)
void gemm_hmma(const __nv_bfloat16* __restrict__ A,
               const __nv_bfloat16* __restrict__ BT,
               const float* __restrict__ bias,
               void* __restrict__ Out, int K, int N) {
    extern __shared__ char dsm[];
    int tid  = threadIdx.x;
    int wid  = tid >> 5, lane = tid & 31;
    int row0 = blockIdx.y * 128;
    int col0 = blockIdx.x * 128;
    int wm   = (wid & 1) * 64;
    int wn   = (wid >> 1) * 32;

    uint32_t aA = smem_u32(dsm);
    uint32_t aB = aA + 3 * STG_BYTES;

    auto issue = [&](int st, int kc0) {
        uint32_t oA = aA + st * STG_BYTES, oB = aB + st * STG_BYTES;
#pragma unroll
        for (int j = 0; j < 4; j++) {
            int idx = tid + j * 256;
            int row = idx >> 3, s = idx & 7;
            uint32_t soff = row * 128 + ((s ^ (row & 7)) << 4);
            cp16(oA + soff, A  + (size_t)(row0 + row) * K + kc0 + s * 8);
            cp16(oB + soff, BT + (size_t)(col0 + row) * K + kc0 + s * 8);
        }
        asm volatile("cp.async.commit_group;" ::: "memory");
    };

    float acc[4][4][4] = {};
    int nk = K >> 6;

    issue(0, 0);
    issue(1, 64);

    for (int i = 0; i < nk; i++) {
        if (i < nk - 1) asm volatile("cp.async.wait_group 1;" ::: "memory");
        else            asm volatile("cp.async.wait_group 0;" ::: "memory");
        __syncthreads();

        if (i + 2 < nk) issue((i + 2) % 3, (i + 2) << 6);

        uint32_t bAs = aA + (i % 3) * STG_BYTES;
        uint32_t bBs = aB + (i % 3) * STG_BYTES;
#pragma unroll
        for (int ks = 0; ks < 4; ks++) {
            uint32_t afr[4][4];
#pragma unroll
            for (int mt = 0; mt < 4; mt++) {
                uint32_t row = wm + mt * 16 + (lane & 15);
                uint32_t ch  = (uint32_t)(ks * 2) + (lane >> 4);
                ldm_x4(afr[mt], bAs + row * 128 + ((ch ^ (row & 7)) << 4));
            }
            uint32_t bfr[2][4];
#pragma unroll
            for (int np = 0; np < 2; np++) {
                uint32_t row = wn + np * 16 + ((lane >> 4) << 3) + (lane & 7);
                uint32_t ch  = (uint32_t)(ks * 2) + ((lane >> 3) & 1);
                ldm_x4(bfr[np], bBs + row * 128 + ((ch ^ (row & 7)) << 4));
            }
#pragma unroll
            for (int mt = 0; mt < 4; mt++)
#pragma unroll
                for (int nt = 0; nt < 4; nt++)
                    mma_bf16(acc[mt][nt], afr[mt], &bfr[nt >> 1][(nt & 1) * 2]);
        }
    }

    int g  = lane >> 2;
    int t2 = (lane & 3) * 2;
#pragma unroll
    for (int mt = 0; mt < 4; mt++) {
#pragma unroll
        for (int nt = 0; nt < 4; nt++) {
            int row = row0 + wm + mt * 16 + g;
            int col = col0 + wn + nt * 8 + t2;
            float2 b2 = *(const float2*)&bias[col];
            float v0 = acc[mt][nt][0] + b2.x, v1 = acc[mt][nt][1] + b2.y;
            float v2 = acc[mt][nt][2] + b2.x, v3 = acc[mt][nt][3] + b2.y;
            if (MODE == 0) {
                float* op = (float*)Out;
                *(float2*)&op[(size_t)row * N + col]       = make_float2(v0, v1);
                *(float2*)&op[(size_t)(row + 8) * N + col] = make_float2(v2, v3);
            } else {
                if (MODE == 1) {
                    v0 = fmaxf(v0, 0.f); v1 = fmaxf(v1, 0.f);
                    v2 = fmaxf(v2, 0.f); v3 = fmaxf(v3, 0.f);
                }
                __nv_bfloat16* op = (__nv_bfloat16*)Out;
                *(__nv_bfloat162*)&op[(size_t)row * N + col]       = __floats2bfloat162_rn(v0, v1);
                *(__nv_bfloat162*)&op[(size_t)(row + 8) * N + col] = __floats2bfloat162_rn(v2, v3);
            }
        }
    }
}

// ================= cell-grouped kNN: adaptive threshold + cell pruning ==========
#define KNN_SMEM (SCAP_ * 20)

__global__ __launch_bounds__(512, 3)
void knn_cell_kernel(const float* __restrict__ q_xyz, int* __restrict__ nidx) {
    const float INF = __int_as_float(0x7f800000);
    int cid = blockIdx.x;
    int nq = min(g_qcnt[cid], QCAP_);
    if (nq == 0) return;
    int b = cid / 125;
    int cc = cid % 125;
    int cx = cc / 25, cy = (cc / 5) % 5, cz = cc % 5;

    extern __shared__ char sm[];
    float4* spts = (float4*)sm;
    int*    sidx = (int*)(sm + SCAP_ * 16);
    __shared__ int s_cells[32], s_off[32], s_cnt[32];
    __shared__ int s_tot;

    int tid = threadIdx.x, warp = tid >> 5, lane = tid & 31;

    // parallel prologue: 27 neighbor cells via one warp + shfl scan
    if (tid < 32) {
        int lx = tid / 9, ly = (tid / 3) % 3, lz = tid % 3;
        int x = cx + lx - 1, y = cy + ly - 1, z = cz + lz - 1;
        bool ok = (tid < 27) && x >= 0 && x <= 4 && y >= 0 && y <= 4 && z >= 0 && z <= 4;
        int nid = ok ? b * 125 + (x * 5 + y) * 5 + z : 0;
        int c = ok ? min(g_cnt[nid], CAP_) : 0;
        int inc = c;
#pragma unroll
        for (int o = 1; o < 32; o <<= 1) {
            int u = __shfl_up_sync(0xffffffffu, inc, o);
            if (tid >= o) inc += u;
        }
        int excl = inc - c;
        if (excl > SCAP_) excl = SCAP_;
        if (excl + c > SCAP_) c = SCAP_ - excl;
        s_cells[tid] = nid; s_off[tid] = excl; s_cnt[tid] = c;
        if (tid == 31) s_tot = min(inc, SCAP_);
    }
    __syncthreads();
    int tot = s_tot;

    for (int j = 0; j < 27; j++) {
        int n = s_cnt[j];
        if (n == 0) continue;
        int nid = s_cells[j], off = s_off[j];
        for (int t = tid; t < n; t += 512) {
            spts[off + t] = g_pts[nid * CAP_ + t];
            sidx[off + t] = g_pidx[nid * CAP_ + t];
        }
    }
    __syncthreads();

    for (int qj = warp; qj < nq; qj += 16) {
        int qi = g_qids[cid * QCAP_ + qj];
        float qx = q_xyz[qi * 3], qy = q_xyz[qi * 3 + 1], qz = q_xyz[qi * 3 + 2];
        float qn = qx * qx + qy * qy + qz * qz;

        // adaptive threshold: target ~32 survivors (boundary-corrected)
        const float r8 = 0.0977f;
        float fx = fminf(qx + r8, 1.f) - fmaxf(qx - r8, 0.f);
        float fy = fminf(qy + r8, 1.f) - fmaxf(qy - r8, 0.f);
        float fz = fminf(qz + r8, 1.f) - fmaxf(qz - r8, 0.f);
        float f  = fx * fy * fz * (1.f / (8.f * r8 * r8 * r8));
        float ta = fminf(0.04f, 0.00955f * __powf(f, -0.6666667f));

        // warp-parallel cell pruning: lane j tests cell j's AABB against ta
        unsigned cmask;
        {
            int j = lane;
            bool keep = false;
            if (j < 27 && s_cnt[j] > 0) {
                float lo, hi;
                lo = (float)(cx + j / 9 - 1) * 0.2f;       hi = lo + 0.2f;
                float ddx = fmaxf(fmaxf(lo - qx, qx - hi), 0.f);
                lo = (float)(cy + (j / 3) % 3 - 1) * 0.2f; hi = lo + 0.2f;
                float ddy = fmaxf(fmaxf(lo - qy, qy - hi), 0.f);
                lo = (float)(cz + j % 3 - 1) * 0.2f;       hi = lo + 0.2f;
                float ddz = fmaxf(fmaxf(lo - qz, qz - hi), 0.f);
                keep = (ddx * ddx + ddy * ddy + ddz * ddz) <= ta;
            }
            cmask = __ballot_sync(0xffffffffu, keep);
        }

        float d8[8]; int i8[8];
#pragma unroll
        for (int i = 0; i < 8; i++) { d8[i] = INF; i8[i] = -1; }

        int scnt = 0;
        unsigned mrem = cmask;
        while (mrem) {
            int j = __ffs(mrem) - 1; mrem &= mrem - 1;
            int off = s_off[j], n = s_cnt[j];
            for (int t0 = 0; t0 < n; t0 += 32) {
                int t = t0 + lane;
                float d2 = INF; int iv = 0;
                bool pass = false;
                if (t < n) {
                    float4 p = spts[off + t];
                    d2 = qn + p.w - 2.f * (qx * p.x + qy * p.y + qz * p.z);
                    pass = (d2 <= ta);
                    iv = sidx[off + t];
                }
                unsigned m = __ballot_sync(0xffffffffu, pass);
                scnt += __popc(m);
                if (pass && d2 < d8[7]) {
                    float dv = d2;
#pragma unroll
                    for (int k = 0; k < 8; k++) {
                        if (dv < d8[k]) {
                            float td = d8[k]; d8[k] = dv; dv = td;
                            int   ti = i8[k]; i8[k] = iv; iv = ti;
                        }
                    }
                }
            }
        }

        // fallback (probabilistically ~never): fewer than 8 under ta and ta < R^2
        if (scnt < 8 && ta < 0.04f) {
            for (int t = lane; t < tot; t += 32) {
                float4 p = spts[t];
                float d2 = qn + p.w - 2.f * (qx * p.x + qy * p.y + qz * p.z);
                if (d2 > ta && d2 <= 0.04f && d2 < d8[7]) {
                    float dv = d2; int iv = sidx[t];
#pragma unroll
                    for (int k = 0; k < 8; k++) {
                        if (dv < d8[k]) {
                            float td = d8[k]; d8[k] = dv; dv = td;
                            int   ti = i8[k]; i8[k] = iv; iv = ti;
                        }
                    }
                }
            }
        }

        // merge: consume d8[0], winner shifts (static indices)
        for (int r = 0; r < 8; r++) {
            unsigned db = __float_as_uint(fmaxf(d8[0], 0.f));
            unsigned long long key = ((unsigned long long)db << 32)
                                   | ((unsigned)(i8[0] & 0x1FFF) << 5) | (unsigned)lane;
#pragma unroll
            for (int o = 16; o; o >>= 1) {
                unsigned long long other = __shfl_xor_sync(0xffffffffu, key, o);
                key = (other < key) ? other : key;
            }
            bool valid = ((unsigned)(key >> 32)) < 0x7f800000u;
            if (valid && lane == (int)(key & 31u)) {
#pragma unroll
                for (int k = 0; k < 7; k++) { d8[k] = d8[k + 1]; i8[k] = i8[k + 1]; }
                d8[7] = INF; i8[7] = -1;
            }
            if (lane == 0) nidx[qi * 8 + r] = valid ? (int)((key >> 5) & 0x1FFF) : -1;
        }
    }
}

// ================= gather attention =============================================
__device__ __forceinline__ void ld8bf(const __nv_bfloat16* p, float* f) {
    uint4 u = *(const uint4*)p;
    const __nv_bfloat162* h = (const __nv_bfloat162*)&u;
#pragma unroll
    for (int i = 0; i < 4; i++) {
        float2 t = __bfloat1622float2(h[i]);
        f[2 * i] = t.x; f[2 * i + 1] = t.y;
    }
}

__global__ void attn_kernel(const __nv_bfloat16* __restrict__ QKV,
                            const __nv_bfloat16* __restrict__ KV,
                            const int* __restrict__ nidx,
                            __nv_bfloat16* __restrict__ O) {
    const float INF = __int_as_float(0x7f800000);
    int warp = threadIdx.x >> 5, lane = threadIdx.x & 31;
    int q = blockIdx.x * 8 + warp;
    int b = q >> 12;
    const int off8 = lane * 8;
    const __nv_bfloat16* qkv = QKV + (size_t)q * 768;

    float qr[8];
    ld8bf(qkv + off8, qr);

    int rid[8]; int nt = 1;
#pragma unroll
    for (int j = 0; j < 8; j++) {
        rid[j] = nidx[q * 8 + j];
        if (rid[j] >= 0) nt++;
    }
    float sc[9];
#pragma unroll
    for (int j = 0; j < 9; j++) {
        if (j == 0 || j < nt) {
            const __nv_bfloat16* kr = (j == 0)
                ? qkv + 256 + off8
                : KV + ((size_t)b * M_ + rid[j - 1]) * 512 + off8;
            float kf[8];
            ld8bf(kr, kf);
            float s = qr[0] * kf[0] + qr[1] * kf[1] + qr[2] * kf[2] + qr[3] * kf[3]
                    + qr[4] * kf[4] + qr[5] * kf[5] + qr[6] * kf[6] + qr[7] * kf[7];
            s += __shfl_xor_sync(0xffffffffu, s, 1);
            s += __shfl_xor_sync(0xffffffffu, s, 2);
            sc[j] = s * 0.17677669529663687f;
        } else sc[j] = -INF;
    }
    float m = sc[0];
#pragma unroll
    for (int j = 1; j < 9; j++) m = fmaxf(m, sc[j]);
    float w[9], ssum = 0.f;
#pragma unroll
    for (int j = 0; j < 9; j++) {
        w[j] = (j == 0 || j < nt) ? expf(sc[j] - m) : 0.f;
        ssum += w[j];
    }
    float inv = 1.f / ssum;

    float o[8] = {0, 0, 0, 0, 0, 0, 0, 0};
#pragma unroll
    for (int j = 0; j < 9; j++) {
        if (j == 0 || j < nt) {
            const __nv_bfloat16* vr = (j == 0)
                ? qkv + 512 + off8
                : KV + ((size_t)b * M_ + rid[j - 1]) * 512 + 256 + off8;
            float vf[8];
            ld8bf(vr, vf);
            float a = w[j] * inv;
#pragma unroll
            for (int d = 0; d < 8; d++) o[d] += a * vf[d];
        }
    }
    __nv_bfloat162 pk[4];
#pragma unroll
    for (int t = 0; t < 4; t++) pk[t] = __floats2bfloat162_rn(o[2 * t], o[2 * t + 1]);
    *(uint4*)&O[(size_t)q * C_ + off8] = *(uint4*)pk;
}

// ================= residual + LayerNorm (Bv in bf16) ============================
__global__ void ln_res_kernel(const float* __restrict__ A,
                              const __nv_bfloat16* __restrict__ Bv,
                              const float* __restrict__ g,
                              const float* __restrict__ be,
                              const float* __restrict__ addq,
                              float* __restrict__ out,
                              __nv_bfloat16* __restrict__ outb) {
    int warp = threadIdx.x >> 5, lane = threadIdx.x & 31;
    int row = blockIdx.x * 8 + warp;
    size_t off = (size_t)row * C_ + lane * 8;

    float v[8], bvf[8];
    float4 a0 = *(const float4*)&A[off],  a1 = *(const float4*)&A[off + 4];
    ld8bf(&Bv[off], bvf);
    v[0] = a0.x + bvf[0]; v[1] = a0.y + bvf[1]; v[2] = a0.z + bvf[2]; v[3] = a0.w + bvf[3];
    v[4] = a1.x + bvf[4]; v[5] = a1.y + bvf[5]; v[6] = a1.z + bvf[6]; v[7] = a1.w + bvf[7];

    float s = 0.f;
#pragma unroll
    for (int d = 0; d < 8; d++) s += v[d];
#pragma unroll
    for (int o = 16; o; o >>= 1) s += __shfl_xor_sync(0xffffffffu, s, o);
    float mu = s * (1.f / 256.f);
    float s2 = 0.f;
#pragma unroll
    for (int d = 0; d < 8; d++) { float t = v[d] - mu; s2 += t * t; }
#pragma unroll
    for (int o = 16; o; o >>= 1) s2 += __shfl_xor_sync(0xffffffffu, s2, o);
    float is = rsqrtf(s2 * (1.f / 256.f) + 1e-5f);

    float r[8];
#pragma unroll
    for (int d = 0; d < 8; d++) {
        r[d] = (v[d] - mu) * is * g[lane * 8 + d] + be[lane * 8 + d];
        if (addq) r[d] += addq[off + d];
    }
    if (out) {
        *(float4*)&out[off]     = make_float4(r[0], r[1], r[2], r[3]);
        *(float4*)&out[off + 4] = make_float4(r[4], r[5], r[6], r[7]);
    }
    if (outb) {
        __nv_bfloat162 pk[4];
#pragma unroll
        for (int t = 0; t < 4; t++) pk[t] = __floats2bfloat162_rn(r[2 * t], r[2 * t + 1]);
        *(uint4*)&outb[off] = *(uint4*)pk;
    }
}

// ================= launch =======================================================
extern "C" void kernel_launch(void* const* d_in, const int* in_sizes, int n_in,
                              void* d_out, int out_size) {
    (void)in_sizes; (void)n_in; (void)out_size;
    const float* q_xyz   = (const float*)d_in[0];
    const float* q_feat  = (const float*)d_in[1];
    const float* kv_xyz  = (const float*)d_in[2];
    const float* kv_feat = (const float*)d_in[3];
    const unsigned char* kv_pad = (const unsigned char*)d_in[4];
    const float* Wpos  = (const float*)d_in[5];
    const float* bpos  = (const float*)d_in[6];
    const float* Wq    = (const float*)d_in[7];
    const float* bq    = (const float*)d_in[8];
    const float* Wk    = (const float*)d_in[9];
    const float* bk    = (const float*)d_in[10];
    const float* Wv    = (const float*)d_in[11];
    const float* bv    = (const float*)d_in[12];
    const float* Wo    = (const float*)d_in[13];
    const float* bo    = (const float*)d_in[14];
    const float* ln1_g = (const float*)d_in[15];
    const float* ln1_b = (const float*)d_in[16];
    const float* W1    = (const float*)d_in[17];
    const float* b1    = (const float*)d_in[18];
    const float* W2    = (const float*)d_in[19];
    const float* b2    = (const float*)d_in[20];
    const float* ln2_g = (const float*)d_in[21];
    const float* ln2_b = (const float*)d_in[22];
    float* out = (float*)d_out;

    float *Xq, *Y, *bqkv, *bkv;
    __nv_bfloat16 *Xqb, *Xkvb, *QKVq, *KVkv, *Ob, *Tb, *Yb, *Hidb, *WTqkv, *WTkv, *WTo, *WT1, *WT2;
    int* nidx;
    cudaGetSymbolAddress((void**)&Xq,    g_Xq);
    cudaGetSymbolAddress((void**)&Xqb,   g_Xq_b);
    cudaGetSymbolAddress((void**)&Xkvb,  g_Xkv_b);
    cudaGetSymbolAddress((void**)&QKVq,  g_QKVq);
    cudaGetSymbolAddress((void**)&KVkv,  g_KVkv);
    cudaGetSymbolAddress((void**)&Ob,    g_O_b);
    cudaGetSymbolAddress((void**)&Tb,    g_T_b);
    cudaGetSymbolAddress((void**)&Y,     g_Y);
    cudaGetSymbolAddress((void**)&Yb,    g_Y_b);
    cudaGetSymbolAddress((void**)&Hidb,  g_Hid_b);
    cudaGetSymbolAddress((void**)&nidx,  g_nidx);
    cudaGetSymbolAddress((void**)&WTqkv, g_WTqkv);
    cudaGetSymbolAddress((void**)&WTkv,  g_WTkv);
    cudaGetSymbolAddress((void**)&WTo,   g_WTo);
    cudaGetSymbolAddress((void**)&WT1,   g_WT1);
    cudaGetSymbolAddress((void**)&WT2,   g_WT2);
    cudaGetSymbolAddress((void**)&bqkv,  g_bqkv);
    cudaGetSymbolAddress((void**)&bkv,   g_bkv);

    cudaFuncSetAttribute(gemm_hmma<0>, cudaFuncAttributeMaxDynamicSharedMemorySize, GEMM_SMEM);
    cudaFuncSetAttribute(gemm_hmma<1>, cudaFuncAttributeMaxDynamicSharedMemorySize, GEMM_SMEM);
    cudaFuncSetAttribute(gemm_hmma<2>, cudaFuncAttributeMaxDynamicSharedMemorySize, GEMM_SMEM);
    cudaFuncSetAttribute(knn_cell_kernel, cudaFuncAttributeMaxDynamicSharedMemorySize, KNN_SMEM);

    // 0: weight prep + cell zeroing
    prep_weights<<<(PREP_ITEMS + 255) / 256, 256>>>(Wq, Wk, Wv, Wo, W1, W2, bq, bk, bv);
    // 1: fused pos-encoding + binning
    posenc_kernel<<<(NQ_ + NM_) / 4, 256>>>(q_xyz, q_feat, kv_xyz, kv_feat, kv_pad, Wpos, bpos);
    // 2: fused QKV projection
    dim3 gqkv(768 / 128, NQ_ / 128);
    gemm_hmma<2><<<gqkv, 256, GEMM_SMEM>>>(Xqb, WTqkv, bqkv, QKVq, C_, 768);
    // 3: cell-grouped kNN (adaptive threshold + cell pruning)  <-- profiled slot
    knn_cell_kernel<<<NCELL_, 512, KNN_SMEM>>>(q_xyz, nidx);
    // 4: fused KV projection
    dim3 gkv(512 / 128, NM_ / 128);
    gemm_hmma<2><<<gkv, 256, GEMM_SMEM>>>(Xkvb, WTkv, bkv, KVkv, C_, 512);
    // 5: gather attention
    attn_kernel<<<NQ_ / 8, 256>>>(QKVq, KVkv, nidx, Ob);
    // 6-7: output projection (bf16 out) + LN1
    dim3 go(C_ / 128, NQ_ / 128);
    gemm_hmma<2><<<go, 256, GEMM_SMEM>>>(Ob, WTo, bo, Tb, C_, C_);
    ln_res_kernel<<<NQ_ / 8, 256>>>(Xq, Tb, ln1_g, ln1_b, nullptr, Y, Yb);
    // 8-9: FFN
    dim3 gf1(FF_ / 128, NQ_ / 128);
    gemm_hmma<1><<<gf1, 256, GEMM_SMEM>>>(Yb, WT1, b1, Hidb, C_, FF_);
    gemm_hmma<2><<<go, 256, GEMM_SMEM>>>(Hidb, WT2, b2, Tb, FF_, C_);
    // 10: LN2 + residual + q_feat -> d_out
    ln_res_kernel<<<NQ_ / 8, 256>>>(Y, Tb, ln2_g, ln2_b, q_feat, out, nullptr);
}